// round 10
// baseline (speedup 1.0000x reference)
#include <cuda_runtime.h>
#include <cuda_bf16.h>
#include <cstdint>

// ---------------- problem constants ----------------
#define BATCH 4
#define NQ    16384
#define EDIM  256
#define KCB   8192
#define KP    768            // packed K' = 3 * 256 for VQ GEMM

// ---------------- scratch (static device memory; no allocation) ----------------
__device__ float g_h1[4 * 128 * 128 * 128];
__device__ float g_h2[4 * 128 * 64 * 64];
__device__ float g_h3[4 * 128 * 64 * 64];
__device__ float g_z[NQ * EDIM];
__device__ float g_quant[NQ * EDIM];
__device__ __nv_bfloat16 g_qh[4 * 128 * 64 * 64];
__device__ __nv_bfloat16 g_ql[4 * 128 * 64 * 64];
__device__ __nv_bfloat16 g_d1h[4 * 128 * 64 * 64];
__device__ __nv_bfloat16 g_d1l[4 * 128 * 64 * 64];
__device__ float g_d2[4 * 128 * 128 * 128];
__device__ float g_znorm[NQ];
__device__ float g_cnorm[KCB];
__device__ int   g_idx[NQ];
__device__ float g_commit;
// VQ packed split buffers
__device__ __nv_bfloat16 g_apk[(size_t)NQ * KP];
__device__ __nv_bfloat16 g_bpk[(size_t)KCB * KP];
__device__ float g_bv8[8 * NQ];
__device__ int   g_bi8[8 * NQ];
// pre-split decoder weights
__device__ __nv_bfloat16 g_wd1h[128 * 1152], g_wd1l[128 * 1152];
__device__ __nv_bfloat16 g_wt2h[4 * 128 * 512], g_wt2l[4 * 128 * 512];

__device__ __forceinline__ uint32_t s2u(const void* p)
{
    uint32_t a;
    asm("{ .reg .u64 t; cvta.to.shared.u64 t, %1; cvt.u32.u64 %0, t; }" : "=r"(a) : "l"(p));
    return a;
}

#define CP16(dst, src) \
    asm volatile("cp.async.cg.shared.global [%0], [%1], 16;" :: "r"(dst), "l"(src) : "memory")
#define CP_COMMIT() asm volatile("cp.async.commit_group;" ::: "memory")
#define CP_WAIT1()  asm volatile("cp.async.wait_group 1;" ::: "memory")
#define CP_WAIT0()  asm volatile("cp.async.wait_group 0;" ::: "memory")

__device__ __forceinline__ void mma_bf16(float* c, const uint32_t* a, const uint32_t* b)
{
    asm volatile(
        "mma.sync.aligned.m16n8k16.row.col.f32.bf16.bf16.f32 "
        "{%0,%1,%2,%3}, {%4,%5,%6,%7}, {%8,%9}, {%0,%1,%2,%3};"
        : "+f"(c[0]), "+f"(c[1]), "+f"(c[2]), "+f"(c[3])
        : "r"(a[0]), "r"(a[1]), "r"(a[2]), "r"(a[3]), "r"(b[0]), "r"(b[1]));
}

__device__ __forceinline__ void ffma2(uint64_t& acc, uint64_t wp, uint64_t xx)
{
    asm("fma.rn.f32x2 %0, %1, %2, %0;" : "+l"(acc) : "l"(wp), "l"(xx));
}

// =====================================================================
// Dedicated enc1 kernel (R9 — passing; h1 bitwise identical)
// =====================================================================
__global__ __launch_bounds__(256)
void conv_enc1(const float* __restrict__ x, const float* __restrict__ w,
               const float* __restrict__ bias, float* __restrict__ out)
{
    __shared__ __align__(16) float ws[48][128];
    __shared__ __align__(16) float xs[48][128];

    const int tid = threadIdx.x;
    const int oh = blockIdx.x;
    const int b = blockIdx.y;

#pragma unroll
    for (int i = 0; i < 24; i++) {
        int idx = tid + i * 256;
        int r = idx >> 7, oc = idx & 127;
        ws[r][oc] = w[oc * 48 + r];
    }
#pragma unroll
    for (int i = 0; i < 24; i++) {
        int idx = tid + i * 256;
        int r = idx >> 7, p = idx & 127;
        int ic = r >> 4, kh = (r >> 2) & 3, kw = r & 3;
        int ih = oh * 2 + kh - 1;
        int iw = p * 2 + kw - 1;
        float v = 0.f;
        if ((unsigned)ih < 256u && (unsigned)iw < 256u)
            v = x[((size_t)(b * 3 + ic) * 256 + ih) * 256 + iw];
        xs[r][p] = v;
    }
    __syncthreads();

    const int tx = tid & 15;
    const int ty = tid >> 4;
    const uint32_t wsb = s2u(ws) + ty * 32;

    uint64_t acc2[4][8];
#pragma unroll
    for (int pq = 0; pq < 4; pq++)
#pragma unroll
        for (int i = 0; i < 8; i++) acc2[pq][i] = 0ull;

#pragma unroll 4
    for (int k = 0; k < 48; k++) {
        uint64_t wp0, wp1, wp2, wp3;
        asm("ld.shared.v2.u64 {%0,%1}, [%2];"
            : "=l"(wp0), "=l"(wp1) : "r"(wsb + (uint32_t)(k * 512)));
        asm("ld.shared.v2.u64 {%0,%1}, [%2];"
            : "=l"(wp2), "=l"(wp3) : "r"(wsb + (uint32_t)(k * 512 + 16)));
        float4 xv0 = *reinterpret_cast<const float4*>(&xs[k][tx * 8]);
        float4 xv1 = *reinterpret_cast<const float4*>(&xs[k][tx * 8 + 4]);
        uint64_t xx[8];
        asm("mov.b64 %0, {%1,%1};" : "=l"(xx[0]) : "f"(xv0.x));
        asm("mov.b64 %0, {%1,%1};" : "=l"(xx[1]) : "f"(xv0.y));
        asm("mov.b64 %0, {%1,%1};" : "=l"(xx[2]) : "f"(xv0.z));
        asm("mov.b64 %0, {%1,%1};" : "=l"(xx[3]) : "f"(xv0.w));
        asm("mov.b64 %0, {%1,%1};" : "=l"(xx[4]) : "f"(xv1.x));
        asm("mov.b64 %0, {%1,%1};" : "=l"(xx[5]) : "f"(xv1.y));
        asm("mov.b64 %0, {%1,%1};" : "=l"(xx[6]) : "f"(xv1.z));
        asm("mov.b64 %0, {%1,%1};" : "=l"(xx[7]) : "f"(xv1.w));
#pragma unroll
        for (int i = 0; i < 8; i++) {
            ffma2(acc2[0][i], wp0, xx[i]);
            ffma2(acc2[1][i], wp1, xx[i]);
            ffma2(acc2[2][i], wp2, xx[i]);
            ffma2(acc2[3][i], wp3, xx[i]);
        }
    }

#pragma unroll
    for (int pq = 0; pq < 4; pq++)
#pragma unroll
        for (int half = 0; half < 2; half++) {
            int oc = ty * 8 + 2 * pq + half;
            float bv = bias[oc];
            float* op = out + ((size_t)(b * 128 + oc) * 128 + oh) * 128 + tx * 8;
#pragma unroll
            for (int i = 0; i < 8; i++) {
                uint32_t bits = half ? (uint32_t)(acc2[pq][i] >> 32)
                                     : (uint32_t)(acc2[pq][i] & 0xffffffffull);
                float v = __uint_as_float(bits) + bv;
                op[i] = fmaxf(v, 0.f);
            }
        }
}

// =====================================================================
// FFMA2 implicit-GEMM conv, 128 oc x 128 px tile, 8x8 micro-tile.
// 1.0 B LDS per MAC (vs 1.5 in the 64-px version) -> smem roofline
// rises from ~85 to ~128 MAC/cyc/SM. Per-output chain: single fp32
// accumulator, ascending k, identical staged values => z bitwise stable.
// OUTL: 0 = NCHW f32, 1 = [n][Cout] f32, 2 = bf16 split planes NCHW.
// =====================================================================
template<int KK, int S, int P, bool RELU, int INL, int OUTL>
__global__ __launch_bounds__(256)
void conv_gemm8(const float* __restrict__ in, const float* __restrict__ w,
                const float* __restrict__ bias, float* __restrict__ out,
                __nv_bfloat16* __restrict__ outh, __nv_bfloat16* __restrict__ outl,
                int Cin, int Cout, int Hin, int Win, int Hout, int Wout,
                int woutShift)
{
    const int R = Cin * KK * KK;
    const int b = blockIdx.z;
    const int oc0 = blockIdx.y * 128;
    const int pxbase = blockIdx.x * 128;

    __shared__ __align__(16) float ws[16][128];
    __shared__ __align__(16) float xs[16][136];

    const int tid = threadIdx.x;
    const int tx = tid & 15;     // px group (8 px each)
    const int ty = tid >> 4;     // oc group (8 oc each)

    const uint32_t wsb = s2u(ws) + ty * 32;

    uint64_t acc2[4][8];         // [oc pair][px]; lo word = even oc
#pragma unroll
    for (int pq = 0; pq < 4; pq++)
#pragma unroll
        for (int i = 0; i < 8; i++) acc2[pq][i] = 0ull;

    for (int r0 = 0; r0 < R; r0 += 16) {
        __syncthreads();
        {
            int row = tid >> 1;
            int half = tid & 1;
            int oc = oc0 + row;
#pragma unroll
            for (int i = 0; i < 8; i++) {
                int r = r0 + half * 8 + i;
                ws[half * 8 + i][row] = (r < R) ? w[oc * R + r] : 0.f;
            }
        }
#pragma unroll
        for (int i2 = 0; i2 < 8; i2++) {
            int li = tid + i2 * 256;
            int r, p;
            if (INL == 1) { r = li & 15; p = li >> 4; }
            else          { r = li >> 7; p = li & 127; }
            int rr = r0 + r;
            float v = 0.f;
            if (rr < R) {
                if (INL == 1) {
                    int n = b * (Hout * Wout) + pxbase + p;
                    v = in[(size_t)n * Cin + rr];
                } else {
                    int ic = rr / (KK * KK);
                    int kr = rr - ic * KK * KK;
                    int kh = kr / KK, kw = kr - kh * KK;
                    int px = pxbase + p;
                    int oh = px >> woutShift;
                    int ow = px & (Wout - 1);
                    int ih = oh * S + kh - P;
                    int iw = ow * S + kw - P;
                    if ((unsigned)ih < (unsigned)Hin && (unsigned)iw < (unsigned)Win)
                        v = in[((size_t)(b * Cin + ic) * Hin + ih) * Win + iw];
                }
            }
            xs[r][p] = v;
        }
        __syncthreads();
#pragma unroll
        for (int k = 0; k < 16; k++) {
            uint64_t wp0, wp1, wp2, wp3;
            asm("ld.shared.v2.u64 {%0,%1}, [%2];"
                : "=l"(wp0), "=l"(wp1) : "r"(wsb + (uint32_t)(k * 512)));
            asm("ld.shared.v2.u64 {%0,%1}, [%2];"
                : "=l"(wp2), "=l"(wp3) : "r"(wsb + (uint32_t)(k * 512 + 16)));
            float4 xv0 = *reinterpret_cast<const float4*>(&xs[k][tx * 8]);
            float4 xv1 = *reinterpret_cast<const float4*>(&xs[k][tx * 8 + 4]);
            uint64_t xx[8];
            asm("mov.b64 %0, {%1,%1};" : "=l"(xx[0]) : "f"(xv0.x));
            asm("mov.b64 %0, {%1,%1};" : "=l"(xx[1]) : "f"(xv0.y));
            asm("mov.b64 %0, {%1,%1};" : "=l"(xx[2]) : "f"(xv0.z));
            asm("mov.b64 %0, {%1,%1};" : "=l"(xx[3]) : "f"(xv0.w));
            asm("mov.b64 %0, {%1,%1};" : "=l"(xx[4]) : "f"(xv1.x));
            asm("mov.b64 %0, {%1,%1};" : "=l"(xx[5]) : "f"(xv1.y));
            asm("mov.b64 %0, {%1,%1};" : "=l"(xx[6]) : "f"(xv1.z));
            asm("mov.b64 %0, {%1,%1};" : "=l"(xx[7]) : "f"(xv1.w));
#pragma unroll
            for (int i = 0; i < 8; i++) {
                ffma2(acc2[0][i], wp0, xx[i]);
                ffma2(acc2[1][i], wp1, xx[i]);
                ffma2(acc2[2][i], wp2, xx[i]);
                ffma2(acc2[3][i], wp3, xx[i]);
            }
        }
    }

#pragma unroll
    for (int pq = 0; pq < 4; pq++)
#pragma unroll
        for (int half = 0; half < 2; half++) {
            int j = 2 * pq + half;
            int oc = oc0 + ty * 8 + j;
            float bv = bias[oc];
#pragma unroll
            for (int i = 0; i < 8; i++) {
                uint32_t bits = half ? (uint32_t)(acc2[pq][i] >> 32)
                                     : (uint32_t)(acc2[pq][i] & 0xffffffffull);
                float v = __uint_as_float(bits) + bv;
                if (RELU) v = fmaxf(v, 0.f);
                if (OUTL == 1) {
                    size_t n = (size_t)(b * (Hout * Wout) + pxbase + tx * 8 + i);
                    out[n * Cout + oc] = v;
                } else {
                    size_t addr = (size_t)(b * Cout + oc) * (Hout * Wout) + pxbase + tx * 8 + i;
                    if (OUTL == 0) {
                        out[addr] = v;
                    } else {
                        __nv_bfloat16 h = __float2bfloat16(v);
                        outh[addr] = h;
                        outl[addr] = __float2bfloat16(v - __bfloat162float(h));
                    }
                }
            }
        }
}

// =====================================================================
// Tensor-core implicit-GEMM conv, bf16 3-term split — DECODER ONLY.
// (unchanged from R5/R6 — passing)
// =====================================================================
#define CLDA 40
#define ABUF 5120

template<int MODE, int KK, int S, int P, bool RELU, int OUTMODE>
__global__ __launch_bounds__(256)
void conv_mma(const __nv_bfloat16* __restrict__ xh, const __nv_bfloat16* __restrict__ xl,
              const __nv_bfloat16* __restrict__ wh_g, const __nv_bfloat16* __restrict__ wl_g,
              const float* __restrict__ bias,
              float* __restrict__ outf, __nv_bfloat16* __restrict__ outh,
              __nv_bfloat16* __restrict__ outl,
              int Cin, int Hin, int Win, int R)
{
    extern __shared__ __align__(16) char sm[];
    __nv_bfloat16* sA_h = (__nv_bfloat16*)(sm);
    __nv_bfloat16* sA_l = (__nv_bfloat16*)(sm + 20480);
    __nv_bfloat16* sB_h = (__nv_bfloat16*)(sm + 40960);
    __nv_bfloat16* sB_l = (__nv_bfloat16*)(sm + 61440);
    float* biasS = (float*)(sm + 81920);

    const int tid = threadIdx.x;
    const int lane = tid & 31, wid = tid >> 5;
    const int wm = wid & 3, wn = wid >> 2;
    const int lr = lane >> 2, lc = lane & 3;
    const int b = blockIdx.z;

    int pxbase = 0, j0 = 0, ohp = 0, owp = 0;
    const __nv_bfloat16* wh = wh_g;
    const __nv_bfloat16* wl = wl_g;
    if (MODE == 1) {
        j0 = blockIdx.x * 2;
        int cls = blockIdx.y;
        ohp = cls >> 1; owp = cls & 1;
        wh = wh_g + cls * (128 * 512);
        wl = wl_g + cls * (128 * 512);
    } else {
        pxbase = blockIdx.x * 128;
    }

    if (tid < 128) biasS[tid] = bias[tid];

    const int NC = R >> 5;

    const int boc = tid >> 1;
    const uint32_t sbBh = s2u(sB_h), sbBl = s2u(sB_l);
    const uint32_t bOff = (uint32_t)(boc * 80 + (tid & 1) * 32);
    const size_t bSrc = (size_t)boc * R + (tid & 1) * 16;

    const int kloc = tid & 31, pblk = tid >> 5;

    float acc[2][8][4];
#pragma unroll
    for (int mf = 0; mf < 2; mf++)
#pragma unroll
        for (int nf = 0; nf < 8; nf++)
#pragma unroll
            for (int e = 0; e < 4; e++) acc[mf][nf][e] = 0.f;

    __nv_bfloat16 pvh[16], pvl[16];

    auto cpB = [&](int r0, int bf) {
        uint32_t d = (uint32_t)bf * 10240;
        const __nv_bfloat16* sh = wh + bSrc + r0;
        const __nv_bfloat16* sl = wl + bSrc + r0;
        CP16(sbBh + d + bOff, sh);  CP16(sbBh + d + bOff + 16, sh + 8);
        CP16(sbBl + d + bOff, sl);  CP16(sbBl + d + bOff + 16, sl + 8);
    };

    auto ldgA = [&](int r0) {
        int r = r0 + kloc;
        if (MODE == 0) {
            int ic = r / (KK * KK);
            int rem = r - ic * KK * KK;
            int kh = rem / KK, kw = rem - kh * KK;
            int px = pxbase + pblk * 16;
            int oh = px >> 6, ow0 = px & 63;
            int ih = oh * S + kh - P;
            const size_t rowb = ((size_t)(b * Cin + ic) * Hin + ih) * Win;
            bool okh = (unsigned)ih < (unsigned)Hin;
#pragma unroll
            for (int i = 0; i < 16; i++) {
                int iw = (ow0 + i) * S + kw - P;
                bool ok = okh && (unsigned)iw < (unsigned)Win;
                pvh[i] = ok ? xh[rowb + iw] : __float2bfloat16(0.f);
                pvl[i] = ok ? xl[rowb + iw] : __float2bfloat16(0.f);
            }
        } else {
            int ic = r >> 2, th = (r >> 1) & 1, tw = r & 1;
            int j = j0 + (pblk >> 2);
            int i0 = (pblk & 3) * 16;
            int ih = j + (1 - ohp) - th;
            int iwb = i0 + (1 - owp) - tw;
            const size_t rowb = ((size_t)(b * Cin + ic) * 64 + ih) * 64;
            bool okh = (unsigned)ih < 64u;
#pragma unroll
            for (int i = 0; i < 16; i++) {
                int iw = iwb + i;
                bool ok = okh && (unsigned)iw < 64u;
                pvh[i] = ok ? xh[rowb + iw] : __float2bfloat16(0.f);
                pvl[i] = ok ? xl[rowb + iw] : __float2bfloat16(0.f);
            }
        }
    };

    auto stsA = [&](int bf) {
        int base = bf * ABUF + kloc;
#pragma unroll
        for (int i = 0; i < 16; i++) {
            int p = pblk * 16 + i;
            sA_h[base + p * CLDA] = pvh[i];
            sA_l[base + p * CLDA] = pvl[i];
        }
    };

    auto domma = [&](int bf) {
        const int off = bf * ABUF;
#pragma unroll
        for (int ks = 0; ks < 2; ks++) {
            const int k0 = ks * 16 + lc * 2;
            uint32_t ah[2][4], al[2][4];
#pragma unroll
            for (int mf = 0; mf < 2; mf++) {
                int r1 = wm * 32 + mf * 16 + lr;
                ah[mf][0] = *(const uint32_t*)&sA_h[off + r1 * CLDA + k0];
                ah[mf][1] = *(const uint32_t*)&sA_h[off + (r1 + 8) * CLDA + k0];
                ah[mf][2] = *(const uint32_t*)&sA_h[off + r1 * CLDA + k0 + 8];
                ah[mf][3] = *(const uint32_t*)&sA_h[off + (r1 + 8) * CLDA + k0 + 8];
                al[mf][0] = *(const uint32_t*)&sA_l[off + r1 * CLDA + k0];
                al[mf][1] = *(const uint32_t*)&sA_l[off + (r1 + 8) * CLDA + k0];
                al[mf][2] = *(const uint32_t*)&sA_l[off + r1 * CLDA + k0 + 8];
                al[mf][3] = *(const uint32_t*)&sA_l[off + (r1 + 8) * CLDA + k0 + 8];
            }
#pragma unroll
            for (int nf = 0; nf < 8; nf++) {
                int cr = wn * 64 + nf * 8 + lr;
                uint32_t bh[2], bl[2];
                bh[0] = *(const uint32_t*)&sB_h[off + cr * CLDA + k0];
                bh[1] = *(const uint32_t*)&sB_h[off + cr * CLDA + k0 + 8];
                bl[0] = *(const uint32_t*)&sB_l[off + cr * CLDA + k0];
                bl[1] = *(const uint32_t*)&sB_l[off + cr * CLDA + k0 + 8];
#pragma unroll
                for (int mf = 0; mf < 2; mf++) {
                    mma_bf16(acc[mf][nf], ah[mf], bh);
                    mma_bf16(acc[mf][nf], al[mf], bh);
                    mma_bf16(acc[mf][nf], ah[mf], bl);
                }
            }
        }
    };

    cpB(0, 0); CP_COMMIT();
    ldgA(0); stsA(0);
    for (int kc = 0; kc < NC; kc++) {
        const int bf = kc & 1;
        const bool nxt = (kc + 1 < NC);
        if (nxt) {
            cpB((kc + 1) * 32, bf ^ 1); CP_COMMIT();
            ldgA((kc + 1) * 32);
            CP_WAIT1();
        } else {
            CP_WAIT0();
        }
        __syncthreads();
        domma(bf);
        if (nxt) stsA(bf ^ 1);
        __syncthreads();
    }

#pragma unroll
    for (int mf = 0; mf < 2; mf++)
#pragma unroll
        for (int nf = 0; nf < 8; nf++)
#pragma unroll
            for (int e = 0; e < 4; e++) {
                int row = wm * 32 + mf * 16 + lr + (e >> 1) * 8;
                int oc = wn * 64 + nf * 8 + lc * 2 + (e & 1);
                float v = acc[mf][nf][e] + biasS[oc];
                if (RELU) v = fmaxf(v, 0.f);
                size_t addr;
                if (MODE == 0) {
                    int px = pxbase + row;
                    addr = ((size_t)(b * 128 + oc) * 64 + (px >> 6)) * 64 + (px & 63);
                } else {
                    int oh = (1 - ohp) + 2 * (j0 + (row >> 6));
                    int ow = (1 - owp) + 2 * (row & 63);
                    addr = ((size_t)(b * 128 + oc) * 128 + oh) * 128 + ow;
                }
                if (OUTMODE == 0) {
                    outf[addr] = v;
                } else {
                    __nv_bfloat16 h = __float2bfloat16(v);
                    outh[addr] = h;
                    outl[addr] = __float2bfloat16(v - __bfloat162float(h));
                }
            }
}

// =====================================================================
// weight split kernels (decoder only)
// =====================================================================
__global__ void wsplit(const float* __restrict__ w, __nv_bfloat16* __restrict__ wh,
                       __nv_bfloat16* __restrict__ wl, int n)
{
    int i = blockIdx.x * 256 + threadIdx.x;
    if (i >= n) return;
    float x = w[i];
    __nv_bfloat16 h = __float2bfloat16(x);
    wh[i] = h;
    wl[i] = __float2bfloat16(x - __bfloat162float(h));
}

__global__ void pack_wt2(const float* __restrict__ w, __nv_bfloat16* __restrict__ wh,
                         __nv_bfloat16* __restrict__ wl)
{
    int i = blockIdx.x * 256 + threadIdx.x;      // over 4*128*512
    int cls = i >> 16;
    int oc = (i >> 9) & 127;
    int r = i & 511;
    int ohp = cls >> 1, owp = cls & 1;
    int ic = r >> 2, th = (r >> 1) & 1, tw = r & 1;
    float x = w[((ic * 128 + oc) * 4 + ohp + 2 * th) * 4 + owp + 2 * tw];
    __nv_bfloat16 h = __float2bfloat16(x);
    wh[i] = h;
    wl[i] = __float2bfloat16(x - __bfloat162float(h));
}

// =====================================================================
// row squared-norm (exact R1 arithmetic)
// =====================================================================
__global__ void rownorm_kernel(const float* __restrict__ v, float* __restrict__ outn, int rows)
{
    int warp = threadIdx.x >> 5, lane = threadIdx.x & 31;
    int n = blockIdx.x * 8 + warp;
    if (n >= rows) return;
    const float* p = v + (size_t)n * 256;
    float s = 0.f;
#pragma unroll
    for (int k = 0; k < 8; k++) { float x = p[lane + 32 * k]; s = fmaf(x, x, s); }
#pragma unroll
    for (int off = 16; off; off >>= 1) s += __shfl_down_sync(0xffffffffu, s, off);
    if (lane == 0) outn[n] = s;
}

__global__ void zero_commit_kernel(float* c) { *c = 0.f; }

// =====================================================================
// VQ pack kernels (exact R3)
// =====================================================================
__global__ void pack_z_bf16(const float* __restrict__ z, __nv_bfloat16* __restrict__ A)
{
    int i = blockIdx.x * 256 + threadIdx.x;
    int q = i >> 8, k = i & 255;
    float x = z[i];
    __nv_bfloat16 h = __float2bfloat16(x);
    __nv_bfloat16 l = __float2bfloat16(x - __bfloat162float(h));
    size_t base = (size_t)q * KP;
    A[base + k] = h;
    A[base + 256 + k] = l;
    A[base + 512 + k] = h;
}

__global__ void pack_c_bf16(const float* __restrict__ c, __nv_bfloat16* __restrict__ B)
{
    int i = blockIdx.x * 256 + threadIdx.x;
    int q = i >> 8, k = i & 255;
    float x = c[i];
    __nv_bfloat16 h = __float2bfloat16(x);
    __nv_bfloat16 l = __float2bfloat16(x - __bfloat162float(h));
    size_t base = (size_t)q * KP;
    B[base + k] = h;
    B[base + 256 + k] = h;
    B[base + 512 + k] = l;
}

// =====================================================================
// VQ GEMM + fused argmin (exact R3/R6 — fastest passing version)
// =====================================================================
#define LDA 40
#define BUFB (128 * LDA * 2)

__global__ __launch_bounds__(256)
void vq_mma(const __nv_bfloat16* __restrict__ Apk, const __nv_bfloat16* __restrict__ Bpk,
            const float* __restrict__ znorm, const float* __restrict__ cnorm,
            float* __restrict__ bv8, int* __restrict__ bi8)
{
    __shared__ __align__(16) __nv_bfloat16 sA[2][128 * LDA];
    __shared__ __align__(16) __nv_bfloat16 sB[2][128 * LDA];
    __shared__ float znS[128], cnS[128];
    __shared__ float redV[2][128];
    __shared__ int   redI[2][128];

    const int tid = threadIdx.x;
    const int lane = tid & 31, wid = tid >> 5;
    const int wm = wid & 3, wn = wid >> 2;
    const int lr = lane >> 2, lc = lane & 3;
    const int qbase = blockIdx.x * 128;
    const int gbase = blockIdx.y * 1024;

    if (tid < 128) znS[tid] = znorm[qbase + tid];
    __syncthreads();
    float znr[4];
#pragma unroll
    for (int s = 0; s < 4; s++)
        znr[s] = znS[wm * 32 + (s >> 1) * 16 + lr + (s & 1) * 8];

    float bestv[4] = {3.4e38f, 3.4e38f, 3.4e38f, 3.4e38f};
    int   besti[4] = {0, 0, 0, 0};

    float acc[2][8][4];
#pragma unroll
    for (int mf = 0; mf < 2; mf++)
#pragma unroll
        for (int nf = 0; nf < 8; nf++)
#pragma unroll
            for (int e = 0; e < 4; e++) acc[mf][nf][e] = 0.f;

    const int srow = tid >> 1;
    const __nv_bfloat16* asrc = Apk + (size_t)(qbase + srow) * KP + (tid & 1) * 16;
    const uint32_t saA = s2u(sA) + srow * (LDA * 2) + (tid & 1) * 32;
    const uint32_t saB = s2u(sB) + srow * (LDA * 2) + (tid & 1) * 32;

    for (int nt = 0; nt < 8; nt++) {
        const __nv_bfloat16* bsrc =
            Bpk + (size_t)(gbase + nt * 128 + srow) * KP + (tid & 1) * 16;
        if (tid < 128) cnS[tid] = cnorm[gbase + nt * 128 + tid];

        CP16(saA, asrc);      CP16(saA + 16, asrc + 8);
        CP16(saB, bsrc);      CP16(saB + 16, bsrc + 8);
        CP_COMMIT();

        for (int kc = 0; kc < 24; kc++) {
            if (kc + 1 < 24) {
                const uint32_t nb = (uint32_t)((kc + 1) & 1) * BUFB;
                const __nv_bfloat16* a2 = asrc + (kc + 1) * 32;
                const __nv_bfloat16* b2 = bsrc + (kc + 1) * 32;
                CP16(saA + nb, a2);      CP16(saA + nb + 16, a2 + 8);
                CP16(saB + nb, b2);      CP16(saB + nb + 16, b2 + 8);
                CP_COMMIT();
                CP_WAIT1();
            } else {
                CP_WAIT0();
            }
            __syncthreads();

            const int buf = kc & 1;
#pragma unroll
            for (int ks = 0; ks < 2; ks++) {
                const int k0 = ks * 16 + lc * 2;
                uint32_t a[2][4], b[8][2];
#pragma unroll
                for (int mf = 0; mf < 2; mf++) {
                    int r = wm * 32 + mf * 16 + lr;
                    a[mf][0] = *(const uint32_t*)&sA[buf][r * LDA + k0];
                    a[mf][1] = *(const uint32_t*)&sA[buf][(r + 8) * LDA + k0];
                    a[mf][2] = *(const uint32_t*)&sA[buf][r * LDA + k0 + 8];
                    a[mf][3] = *(const uint32_t*)&sA[buf][(r + 8) * LDA + k0 + 8];
                }
#pragma unroll
                for (int nf = 0; nf < 8; nf++) {
                    int cr = wn * 64 + nf * 8 + lr;
                    b[nf][0] = *(const uint32_t*)&sB[buf][cr * LDA + k0];
                    b[nf][1] = *(const uint32_t*)&sB[buf][cr * LDA + k0 + 8];
                }
#pragma unroll
                for (int mf = 0; mf < 2; mf++)
#pragma unroll
                    for (int nf = 0; nf < 8; nf++)
                        mma_bf16(acc[mf][nf], a[mf], b[nf]);
            }
            __syncthreads();
        }

#pragma unroll
        for (int mf = 0; mf < 2; mf++)
#pragma unroll
            for (int nf = 0; nf < 8; nf++)
#pragma unroll
                for (int e = 0; e < 4; e++) {
                    int h = e >> 1;
                    int col = wn * 64 + nf * 8 + lc * 2 + (e & 1);
                    int slot = mf * 2 + h;
                    float t = znr[slot] + cnS[col];
                    float s = fmaf(-2.f, acc[mf][nf][e], t);
                    int code = gbase + nt * 128 + col;
                    if (s < bestv[slot]) { bestv[slot] = s; besti[slot] = code; }
                    acc[mf][nf][e] = 0.f;
                }
        __syncthreads();
    }

#pragma unroll
    for (int s = 0; s < 4; s++) {
        float v = bestv[s]; int ix = besti[s];
#pragma unroll
        for (int off = 1; off <= 2; off <<= 1) {
            float ov = __shfl_xor_sync(0xffffffffu, v, off);
            int   oi = __shfl_xor_sync(0xffffffffu, ix, off);
            if (ov < v || (ov == v && oi < ix)) { v = ov; ix = oi; }
        }
        if (lc == 0) {
            int row = wm * 32 + (s >> 1) * 16 + lr + (s & 1) * 8;
            redV[wn][row] = v; redI[wn][row] = ix;
        }
    }
    __syncthreads();
    if (tid < 128) {
        float v = redV[0][tid]; int ix = redI[0][tid];
        float v1 = redV[1][tid]; int i1 = redI[1][tid];
        if (v1 < v || (v1 == v && i1 < ix)) { v = v1; ix = i1; }
        bv8[blockIdx.y * NQ + qbase + tid] = v;
        bi8[blockIdx.y * NQ + qbase + tid] = ix;
    }
}

__global__ void vq_combine8(const float* __restrict__ bv8, const int* __restrict__ bi8,
                            int* __restrict__ idx)
{
    int q = blockIdx.x * 256 + threadIdx.x;
    if (q >= NQ) return;
    float v = bv8[q]; int ix = bi8[q];
#pragma unroll
    for (int g = 1; g < 8; g++) {
        float v2 = bv8[g * NQ + q];
        int   i2 = bi8[g * NQ + q];
        if (v2 < v || (v2 == v && i2 < ix)) { v = v2; ix = i2; }
    }
    idx[q] = ix;
}

// =====================================================================
// gather quant = codebook[idx], commit loss
// =====================================================================
__global__ __launch_bounds__(256)
void gather_commit(const float* __restrict__ cb, const float* __restrict__ z,
                   const int* __restrict__ idx, float* __restrict__ quant,
                   float* __restrict__ commit)
{
    int n = blockIdx.x;
    int t = threadIdx.x;
    int id = idx[n];
    float q = cb[(size_t)id * 256 + t];
    float zv = z[(size_t)n * 256 + t];
    quant[(size_t)n * 256 + t] = q;
    float d = q - zv; d *= d;
#pragma unroll
    for (int off = 16; off; off >>= 1) d += __shfl_down_sync(0xffffffffu, d, off);
    __shared__ float wsum[8];
    int warp = t >> 5, lane = t & 31;
    if (lane == 0) wsum[warp] = d;
    __syncthreads();
    if (t == 0) {
        float s = 0.f;
#pragma unroll
        for (int w = 0; w < 8; w++) s += wsum[w];
        atomicAdd(commit, s);
    }
}

// =====================================================================
// Final transposed conv (128 -> 3 channels) straight into d_out
// =====================================================================
__global__ __launch_bounds__(256)
void convt_out3(const float* __restrict__ in, const float* __restrict__ w,
                const float* __restrict__ bias, float* __restrict__ out)
{
    __shared__ float ws[128 * 3 * 16];
    for (int i = threadIdx.x; i < 6144; i += 256) ws[i] = w[i];
    __syncthreads();

    int b = blockIdx.y, oh = blockIdx.x, ow = threadIdx.x;
    int ih0 = (oh + 1) >> 1, kh0 = (oh + 1) & 1;
    int iw0 = (ow + 1) >> 1, kw0 = (ow + 1) & 1;

    float acc0 = 0.f, acc1 = 0.f, acc2 = 0.f;
    for (int ic = 0; ic < 128; ic++) {
        const float* inp = in + ((size_t)(b * 128 + ic)) * 128 * 128;
        const float* wp = ws + ic * 48;
#pragma unroll
        for (int th = 0; th < 2; th++) {
            int ih = ih0 - th;
            if ((unsigned)ih < 128u) {
                int kh = kh0 + 2 * th;
#pragma unroll
                for (int tw = 0; tw < 2; tw++) {
                    int iw = iw0 - tw;
                    if ((unsigned)iw < 128u) {
                        int kw = kw0 + 2 * tw;
                        float v = inp[ih * 128 + iw];
                        int wk = kh * 4 + kw;
                        acc0 = fmaf(v, wp[wk], acc0);
                        acc1 = fmaf(v, wp[16 + wk], acc1);
                        acc2 = fmaf(v, wp[32 + wk], acc2);
                    }
                }
            }
        }
    }
    size_t ob = ((size_t)(b * 3) * 256 + oh) * 256 + ow;
    out[ob]          = acc0 + bias[0];
    out[ob + 65536]  = acc1 + bias[1];
    out[ob + 131072] = acc2 + bias[2];
}

__global__ void pack_kernel(float* __restrict__ out, const float* __restrict__ commit,
                            const int* __restrict__ idx)
{
    int i = blockIdx.x * 256 + threadIdx.x;
    if (i == 0) out[786432] = (*commit) * (1.f / 4194304.f);
    if (i < NQ) out[786433 + i] = (float)idx[i];
}

// =====================================================================
// host launcher
// =====================================================================
#define CMMA_SMEM 82432

extern "C" void kernel_launch(void* const* d_in, const int* in_sizes, int n_in,
                              void* d_out, int out_size)
{
    const float* x        = (const float*)d_in[0];
    const float* enc_w1   = (const float*)d_in[1];
    const float* enc_b1   = (const float*)d_in[2];
    const float* enc_w2   = (const float*)d_in[3];
    const float* enc_b2   = (const float*)d_in[4];
    const float* enc_w3   = (const float*)d_in[5];
    const float* enc_b3   = (const float*)d_in[6];
    const float* qconv_w  = (const float*)d_in[7];
    const float* qconv_b  = (const float*)d_in[8];
    const float* codebook = (const float*)d_in[9];
    const float* pqconv_w = (const float*)d_in[10];
    const float* pqconv_b = (const float*)d_in[11];
    const float* dec_w1   = (const float*)d_in[12];
    const float* dec_b1   = (const float*)d_in[13];
    const float* dect_w2  = (const float*)d_in[14];
    const float* dect_b2  = (const float*)d_in[15];
    const float* dect_w3  = (const float*)d_in[16];
    const float* dect_b3  = (const float*)d_in[17];
    float* out = (float*)d_out;

    float *h1, *h2, *h3, *z, *quant, *d2, *znorm, *cnorm, *commit, *bv8;
    __nv_bfloat16 *qh, *ql, *d1h, *d1l, *apk, *bpk;
    __nv_bfloat16 *wd1h, *wd1l, *wt2h, *wt2l;
    int *idx, *bi8;
    cudaGetSymbolAddress((void**)&h1, g_h1);
    cudaGetSymbolAddress((void**)&h2, g_h2);
    cudaGetSymbolAddress((void**)&h3, g_h3);
    cudaGetSymbolAddress((void**)&z, g_z);
    cudaGetSymbolAddress((void**)&quant, g_quant);
    cudaGetSymbolAddress((void**)&qh, g_qh);
    cudaGetSymbolAddress((void**)&ql, g_ql);
    cudaGetSymbolAddress((void**)&d1h, g_d1h);
    cudaGetSymbolAddress((void**)&d1l, g_d1l);
    cudaGetSymbolAddress((void**)&d2, g_d2);
    cudaGetSymbolAddress((void**)&znorm, g_znorm);
    cudaGetSymbolAddress((void**)&cnorm, g_cnorm);
    cudaGetSymbolAddress((void**)&idx, g_idx);
    cudaGetSymbolAddress((void**)&commit, g_commit);
    cudaGetSymbolAddress((void**)&apk, g_apk);
    cudaGetSymbolAddress((void**)&bpk, g_bpk);
    cudaGetSymbolAddress((void**)&bv8, g_bv8);
    cudaGetSymbolAddress((void**)&bi8, g_bi8);
    cudaGetSymbolAddress((void**)&wd1h, g_wd1h); cudaGetSymbolAddress((void**)&wd1l, g_wd1l);
    cudaGetSymbolAddress((void**)&wt2h, g_wt2h); cudaGetSymbolAddress((void**)&wt2l, g_wt2l);

    cudaFuncSetAttribute(conv_mma<0,3,1,1,true ,1>, cudaFuncAttributeMaxDynamicSharedMemorySize, CMMA_SMEM);
    cudaFuncSetAttribute(conv_mma<1,4,2,1,true ,0>, cudaFuncAttributeMaxDynamicSharedMemorySize, CMMA_SMEM);

    // weight prep (decoder splits + VQ codebook)
    wsplit<<<576, 256>>>(dec_w1, wd1h, wd1l, 128 * 1152);
    pack_wt2<<<1024, 256>>>(dect_w2, wt2h, wt2l);
    pack_c_bf16<<<KCB, 256>>>(codebook, bpk);
    rownorm_kernel<<<1024, 256>>>(codebook, cnorm, KCB);
    zero_commit_kernel<<<1, 1>>>(commit);

    // encoder — enc1 dedicated; enc2/enc3/qconv on the 8x8 FFMA2 tile
    conv_enc1<<<dim3(128,4),256>>>(x, enc_w1, enc_b1, h1);
    conv_gemm8<4,2,1,true ,0,0><<<dim3(32,1,4),256>>>(h1, enc_w2, enc_b2, h2, nullptr, nullptr,
                                                      128,128, 128,128,  64, 64, 6);
    conv_gemm8<3,1,1,false,0,0><<<dim3(32,1,4),256>>>(h2, enc_w3, enc_b3, h3, nullptr, nullptr,
                                                      128,128,  64, 64,  64, 64, 6);
    conv_gemm8<1,1,0,false,0,1><<<dim3(32,2,4),256>>>(h3, qconv_w, qconv_b, z, nullptr, nullptr,
                                                      128,256,  64, 64,  64, 64, 6);

    // quantize — exact R3/R6 path
    pack_z_bf16<<<NQ, 256>>>(z, apk);
    rownorm_kernel<<<2048, 256>>>(z, znorm, NQ);
    vq_mma<<<dim3(128, 8), 256>>>(apk, bpk, znorm, cnorm, bv8, bi8);
    vq_combine8<<<64, 256>>>(bv8, bi8, idx);
    gather_commit<<<NQ, 256>>>(codebook, z, idx, quant, commit);

    // decoder — tensor-core bf16-split
    conv_gemm8<1,1,0,false,1,2><<<dim3(32,1,4),256>>>(quant, pqconv_w, pqconv_b, nullptr, qh, ql,
                                                      256, 128, 64,64, 64,64, 6);
    conv_mma<0,3,1,1,true ,1><<<dim3(32,1,4),256,CMMA_SMEM>>>(qh, ql, wd1h, wd1l, dec_b1,
                                                     nullptr, d1h, d1l, 128, 64, 64, 1152);
    conv_mma<1,4,2,1,true ,0><<<dim3(32,4,4),256,CMMA_SMEM>>>(d1h, d1l, wt2h, wt2l, dect_b2,
                                                     d2, nullptr, nullptr, 128, 64, 64, 512);
    convt_out3<<<dim3(256,4),256>>>(d2, dect_w3, dect_b3, out);

    pack_kernel<<<64, 256>>>(out, commit, idx);

    (void)in_sizes; (void)n_in; (void)out_size;
}

// round 12
// speedup vs baseline: 1.1173x; 1.1173x over previous
#include <cuda_runtime.h>
#include <cuda_bf16.h>
#include <cstdint>

// ---------------- problem constants ----------------
#define BATCH 4
#define NQ    16384
#define EDIM  256
#define KCB   8192
#define KP    768            // packed K' = 3 * 256 for VQ GEMM

// ---------------- scratch (static device memory; no allocation) ----------------
__device__ float g_h1[4 * 128 * 128 * 128];
__device__ float g_h2[4 * 128 * 64 * 64];
__device__ float g_h3[4 * 128 * 64 * 64];
__device__ float g_z[NQ * EDIM];
__device__ float g_quant[NQ * EDIM];
__device__ __nv_bfloat16 g_qh[4 * 128 * 64 * 64];
__device__ __nv_bfloat16 g_ql[4 * 128 * 64 * 64];
__device__ __nv_bfloat16 g_d1h[4 * 128 * 64 * 64];
__device__ __nv_bfloat16 g_d1l[4 * 128 * 64 * 64];
__device__ float g_d2[4 * 128 * 128 * 128];
__device__ float g_znorm[NQ];
__device__ float g_cnorm[KCB];
__device__ int   g_idx[NQ];
__device__ float g_commit;
// VQ packed split buffers
__device__ __nv_bfloat16 g_apk[(size_t)NQ * KP];
__device__ __nv_bfloat16 g_bpk[(size_t)KCB * KP];
__device__ float g_bv8[8 * NQ];
__device__ int   g_bi8[8 * NQ];
// pre-split decoder weights
__device__ __nv_bfloat16 g_wd1h[128 * 1152], g_wd1l[128 * 1152];
__device__ __nv_bfloat16 g_wt2h[4 * 128 * 512], g_wt2l[4 * 128 * 512];
// chunk-major transposed fp32 weights for async FFMA convs
__device__ float g_w2t[128 * 2048];
__device__ float g_w3t[128 * 1152];
__device__ float g_wqt[256 * 128];
__device__ float g_wpt[128 * 256];

__device__ __forceinline__ uint32_t s2u(const void* p)
{
    uint32_t a;
    asm("{ .reg .u64 t; cvta.to.shared.u64 t, %1; cvt.u32.u64 %0, t; }" : "=r"(a) : "l"(p));
    return a;
}

#define CP16(dst, src) \
    asm volatile("cp.async.cg.shared.global [%0], [%1], 16;" :: "r"(dst), "l"(src) : "memory")
#define CP4Z(dst, src, sz) \
    asm volatile("cp.async.ca.shared.global [%0], [%1], 4, %2;" :: "r"(dst), "l"(src), "r"(sz) : "memory")
#define CP_COMMIT() asm volatile("cp.async.commit_group;" ::: "memory")
#define CP_WAIT1()  asm volatile("cp.async.wait_group 1;" ::: "memory")
#define CP_WAIT0()  asm volatile("cp.async.wait_group 0;" ::: "memory")

__device__ __forceinline__ void mma_bf16(float* c, const uint32_t* a, const uint32_t* b)
{
    asm volatile(
        "mma.sync.aligned.m16n8k16.row.col.f32.bf16.bf16.f32 "
        "{%0,%1,%2,%3}, {%4,%5,%6,%7}, {%8,%9}, {%0,%1,%2,%3};"
        : "+f"(c[0]), "+f"(c[1]), "+f"(c[2]), "+f"(c[3])
        : "r"(a[0]), "r"(a[1]), "r"(a[2]), "r"(a[3]), "r"(b[0]), "r"(b[1]));
}

__device__ __forceinline__ void ffma2(uint64_t& acc, uint64_t wp, uint64_t xx)
{
    asm("fma.rn.f32x2 %0, %1, %2, %0;" : "+l"(acc) : "l"(wp), "l"(xx));
}

// =====================================================================
// Weight transpose into chunk-major [ocTile][chunk][r(16)][ocl(128)].
// Same values, enables contiguous cp.async weight staging.
// =====================================================================
__global__ void wtrans(const float* __restrict__ w, float* __restrict__ wt, int R, int Cout)
{
    int i = blockIdx.x * 256 + threadIdx.x;
    if (i >= Cout * R) return;
    int ocl = i & 127;
    int rest = i >> 7;
    int r = rest & 15;
    int chunkAll = rest >> 4;        // ot*NC + c
    int NC = R >> 4;
    int ot = chunkAll / NC;
    int c = chunkAll - ot * NC;
    wt[i] = w[(size_t)(ot * 128 + ocl) * R + c * 16 + r];
}

// =====================================================================
// Dedicated enc1 kernel (R9 — passing; h1 bitwise identical)
// =====================================================================
__global__ __launch_bounds__(256)
void conv_enc1(const float* __restrict__ x, const float* __restrict__ w,
               const float* __restrict__ bias, float* __restrict__ out)
{
    __shared__ __align__(16) float ws[48][128];
    __shared__ __align__(16) float xs[48][128];

    const int tid = threadIdx.x;
    const int oh = blockIdx.x;
    const int b = blockIdx.y;

#pragma unroll
    for (int i = 0; i < 24; i++) {
        int idx = tid + i * 256;
        int r = idx >> 7, oc = idx & 127;
        ws[r][oc] = w[oc * 48 + r];
    }
#pragma unroll
    for (int i = 0; i < 24; i++) {
        int idx = tid + i * 256;
        int r = idx >> 7, p = idx & 127;
        int ic = r >> 4, kh = (r >> 2) & 3, kw = r & 3;
        int ih = oh * 2 + kh - 1;
        int iw = p * 2 + kw - 1;
        float v = 0.f;
        if ((unsigned)ih < 256u && (unsigned)iw < 256u)
            v = x[((size_t)(b * 3 + ic) * 256 + ih) * 256 + iw];
        xs[r][p] = v;
    }
    __syncthreads();

    const int tx = tid & 15;
    const int ty = tid >> 4;
    const uint32_t wsb = s2u(ws) + ty * 32;

    uint64_t acc2[4][8];
#pragma unroll
    for (int pq = 0; pq < 4; pq++)
#pragma unroll
        for (int i = 0; i < 8; i++) acc2[pq][i] = 0ull;

#pragma unroll 4
    for (int k = 0; k < 48; k++) {
        uint64_t wp0, wp1, wp2, wp3;
        asm("ld.shared.v2.u64 {%0,%1}, [%2];"
            : "=l"(wp0), "=l"(wp1) : "r"(wsb + (uint32_t)(k * 512)));
        asm("ld.shared.v2.u64 {%0,%1}, [%2];"
            : "=l"(wp2), "=l"(wp3) : "r"(wsb + (uint32_t)(k * 512 + 16)));
        float4 xv0 = *reinterpret_cast<const float4*>(&xs[k][tx * 8]);
        float4 xv1 = *reinterpret_cast<const float4*>(&xs[k][tx * 8 + 4]);
        uint64_t xx[8];
        asm("mov.b64 %0, {%1,%1};" : "=l"(xx[0]) : "f"(xv0.x));
        asm("mov.b64 %0, {%1,%1};" : "=l"(xx[1]) : "f"(xv0.y));
        asm("mov.b64 %0, {%1,%1};" : "=l"(xx[2]) : "f"(xv0.z));
        asm("mov.b64 %0, {%1,%1};" : "=l"(xx[3]) : "f"(xv0.w));
        asm("mov.b64 %0, {%1,%1};" : "=l"(xx[4]) : "f"(xv1.x));
        asm("mov.b64 %0, {%1,%1};" : "=l"(xx[5]) : "f"(xv1.y));
        asm("mov.b64 %0, {%1,%1};" : "=l"(xx[6]) : "f"(xv1.z));
        asm("mov.b64 %0, {%1,%1};" : "=l"(xx[7]) : "f"(xv1.w));
#pragma unroll
        for (int i = 0; i < 8; i++) {
            ffma2(acc2[0][i], wp0, xx[i]);
            ffma2(acc2[1][i], wp1, xx[i]);
            ffma2(acc2[2][i], wp2, xx[i]);
            ffma2(acc2[3][i], wp3, xx[i]);
        }
    }

#pragma unroll
    for (int pq = 0; pq < 4; pq++)
#pragma unroll
        for (int half = 0; half < 2; half++) {
            int oc = ty * 8 + 2 * pq + half;
            float bv = bias[oc];
            float* op = out + ((size_t)(b * 128 + oc) * 128 + oh) * 128 + tx * 8;
#pragma unroll
            for (int i = 0; i < 8; i++) {
                uint32_t bits = half ? (uint32_t)(acc2[pq][i] >> 32)
                                     : (uint32_t)(acc2[pq][i] & 0xffffffffull);
                float v = __uint_as_float(bits) + bv;
                op[i] = fmaxf(v, 0.f);
            }
        }
}

// =====================================================================
// FFMA2 implicit-GEMM conv with cp.async DOUBLE-BUFFERED staging.
// 128 oc x 64 px tile, 8x4 micro-tile (R6 geometry). Weights come from
// the chunk-major transposed copy (contiguous 16B cp.async); x gathers
// use 4B cp.async with zfill for OOB (identical staged values).
// Per-output chain: single fp32 acc, ascending k => z bitwise stable.
// OUTL: 0 = NCHW f32, 1 = [n][Cout] f32, 2 = bf16 split planes NCHW.
// =====================================================================
template<int KK, int S, int P, bool RELU, int INL, int OUTL>
__global__ __launch_bounds__(256)
void conv_async(const float* __restrict__ in, const float* __restrict__ wt,
                const float* __restrict__ bias, float* __restrict__ out,
                __nv_bfloat16* __restrict__ outh, __nv_bfloat16* __restrict__ outl,
                int Cin, int Cout, int Hin, int Win, int Hout, int Wout,
                int woutShift)
{
    const int R = Cin * KK * KK;
    const int NC = R >> 4;
    const int b = blockIdx.z;
    const int ot = blockIdx.y;
    const int oc0 = ot * 128;
    const int pxbase = blockIdx.x * 64;

    __shared__ __align__(16) float ws[2][16][128];
    __shared__ __align__(16) float xs[2][16][68];

    const int tid = threadIdx.x;
    const int tx = tid & 15;
    const int ty = tid >> 4;

    const uint32_t wsb0 = s2u(ws);
    const uint32_t xsb0 = s2u(xs);
    const uint32_t wdst = wsb0 + (uint32_t)tid * 32;
    const float* wsrc_base = wt + (size_t)ot * ((size_t)NC * 2048) + tid * 8;

    uint64_t acc2[4][4];
#pragma unroll
    for (int p = 0; p < 4; p++)
#pragma unroll
        for (int i = 0; i < 4; i++) acc2[p][i] = 0ull;

    auto stage = [&](int c, int bf) {
        const float* wsrc = wsrc_base + (size_t)c * 2048;
        uint32_t wd = wdst + (uint32_t)bf * 8192;
        CP16(wd, wsrc);
        CP16(wd + 16, wsrc + 4);
#pragma unroll
        for (int i2 = 0; i2 < 4; i2++) {
            int li = tid + i2 * 256;
            int r, p;
            if (INL == 1) { r = li & 15; p = li >> 4; }
            else          { r = li >> 6; p = li & 63; }
            int rr = c * 16 + r;
            const float* src = in;
            int sz = 0;
            if (INL == 1) {
                int n = b * (Hout * Wout) + pxbase + p;
                src = in + (size_t)n * Cin + rr;
                sz = 4;
            } else {
                int ic = rr / (KK * KK);
                int kr = rr - ic * KK * KK;
                int kh = kr / KK, kw = kr - kh * KK;
                int px = pxbase + p;
                int oh = px >> woutShift;
                int ow = px & (Wout - 1);
                int ih = oh * S + kh - P;
                int iw = ow * S + kw - P;
                if ((unsigned)ih < (unsigned)Hin && (unsigned)iw < (unsigned)Win) {
                    src = in + ((size_t)(b * Cin + ic) * Hin + ih) * Win + iw;
                    sz = 4;
                }
            }
            uint32_t xd = xsb0 + (uint32_t)bf * 4352 + (uint32_t)((r * 68 + p) * 4);
            CP4Z(xd, src, sz);
        }
    };

    stage(0, 0); CP_COMMIT();

    for (int c = 0; c < NC; c++) {
        const int bf = c & 1;
        if (c + 1 < NC) {
            stage(c + 1, bf ^ 1); CP_COMMIT();
            CP_WAIT1();
        } else {
            CP_WAIT0();
        }
        __syncthreads();

        const uint32_t wsb = wsb0 + (uint32_t)bf * 8192 + ty * 32;
        const float (*xsb)[68] = xs[bf];
#pragma unroll
        for (int k = 0; k < 16; k++) {
            float4 xv = *reinterpret_cast<const float4*>(&xsb[k][tx * 4]);
            uint64_t wp0, wp1, wp2, wp3;
            asm("ld.shared.v2.u64 {%0,%1}, [%2];"
                : "=l"(wp0), "=l"(wp1) : "r"(wsb + (uint32_t)(k * 512)));
            asm("ld.shared.v2.u64 {%0,%1}, [%2];"
                : "=l"(wp2), "=l"(wp3) : "r"(wsb + (uint32_t)(k * 512 + 16)));
            uint64_t xx0, xx1, xx2, xx3;
            asm("mov.b64 %0, {%1,%1};" : "=l"(xx0) : "f"(xv.x));
            asm("mov.b64 %0, {%1,%1};" : "=l"(xx1) : "f"(xv.y));
            asm("mov.b64 %0, {%1,%1};" : "=l"(xx2) : "f"(xv.z));
            asm("mov.b64 %0, {%1,%1};" : "=l"(xx3) : "f"(xv.w));
            ffma2(acc2[0][0], wp0, xx0); ffma2(acc2[0][1], wp0, xx1);
            ffma2(acc2[0][2], wp0, xx2); ffma2(acc2[0][3], wp0, xx3);
            ffma2(acc2[1][0], wp1, xx0); ffma2(acc2[1][1], wp1, xx1);
            ffma2(acc2[1][2], wp1, xx2); ffma2(acc2[1][3], wp1, xx3);
            ffma2(acc2[2][0], wp2, xx0); ffma2(acc2[2][1], wp2, xx1);
            ffma2(acc2[2][2], wp2, xx2); ffma2(acc2[2][3], wp2, xx3);
            ffma2(acc2[3][0], wp3, xx0); ffma2(acc2[3][1], wp3, xx1);
            ffma2(acc2[3][2], wp3, xx2); ffma2(acc2[3][3], wp3, xx3);
        }
        __syncthreads();
    }

#pragma unroll
    for (int p = 0; p < 4; p++)
#pragma unroll
        for (int half = 0; half < 2; half++) {
            int j = 2 * p + half;
            int oc = oc0 + ty * 8 + j;
            float bv = bias[oc];
#pragma unroll
            for (int i = 0; i < 4; i++) {
                uint32_t bits = half ? (uint32_t)(acc2[p][i] >> 32)
                                     : (uint32_t)(acc2[p][i] & 0xffffffffull);
                float v = __uint_as_float(bits) + bv;
                if (RELU) v = fmaxf(v, 0.f);
                if (OUTL == 1) {
                    size_t n = (size_t)(b * (Hout * Wout) + pxbase + tx * 4 + i);
                    out[n * Cout + oc] = v;
                } else {
                    size_t addr = (size_t)(b * Cout + oc) * (Hout * Wout) + pxbase + tx * 4 + i;
                    if (OUTL == 0) {
                        out[addr] = v;
                    } else {
                        __nv_bfloat16 h = __float2bfloat16(v);
                        outh[addr] = h;
                        outl[addr] = __float2bfloat16(v - __bfloat162float(h));
                    }
                }
            }
        }
}

// =====================================================================
// Tensor-core implicit-GEMM conv, bf16 3-term split — DECODER ONLY.
// (unchanged — passing)
// =====================================================================
#define CLDA 40
#define ABUF 5120

template<int MODE, int KK, int S, int P, bool RELU, int OUTMODE>
__global__ __launch_bounds__(256)
void conv_mma(const __nv_bfloat16* __restrict__ xh, const __nv_bfloat16* __restrict__ xl,
              const __nv_bfloat16* __restrict__ wh_g, const __nv_bfloat16* __restrict__ wl_g,
              const float* __restrict__ bias,
              float* __restrict__ outf, __nv_bfloat16* __restrict__ outh,
              __nv_bfloat16* __restrict__ outl,
              int Cin, int Hin, int Win, int R)
{
    extern __shared__ __align__(16) char sm[];
    __nv_bfloat16* sA_h = (__nv_bfloat16*)(sm);
    __nv_bfloat16* sA_l = (__nv_bfloat16*)(sm + 20480);
    __nv_bfloat16* sB_h = (__nv_bfloat16*)(sm + 40960);
    __nv_bfloat16* sB_l = (__nv_bfloat16*)(sm + 61440);
    float* biasS = (float*)(sm + 81920);

    const int tid = threadIdx.x;
    const int lane = tid & 31, wid = tid >> 5;
    const int wm = wid & 3, wn = wid >> 2;
    const int lr = lane >> 2, lc = lane & 3;
    const int b = blockIdx.z;

    int pxbase = 0, j0 = 0, ohp = 0, owp = 0;
    const __nv_bfloat16* wh = wh_g;
    const __nv_bfloat16* wl = wl_g;
    if (MODE == 1) {
        j0 = blockIdx.x * 2;
        int cls = blockIdx.y;
        ohp = cls >> 1; owp = cls & 1;
        wh = wh_g + cls * (128 * 512);
        wl = wl_g + cls * (128 * 512);
    } else {
        pxbase = blockIdx.x * 128;
    }

    if (tid < 128) biasS[tid] = bias[tid];

    const int NC = R >> 5;

    const int boc = tid >> 1;
    const uint32_t sbBh = s2u(sB_h), sbBl = s2u(sB_l);
    const uint32_t bOff = (uint32_t)(boc * 80 + (tid & 1) * 32);
    const size_t bSrc = (size_t)boc * R + (tid & 1) * 16;

    const int kloc = tid & 31, pblk = tid >> 5;

    float acc[2][8][4];
#pragma unroll
    for (int mf = 0; mf < 2; mf++)
#pragma unroll
        for (int nf = 0; nf < 8; nf++)
#pragma unroll
            for (int e = 0; e < 4; e++) acc[mf][nf][e] = 0.f;

    __nv_bfloat16 pvh[16], pvl[16];

    auto cpB = [&](int r0, int bf) {
        uint32_t d = (uint32_t)bf * 10240;
        const __nv_bfloat16* sh = wh + bSrc + r0;
        const __nv_bfloat16* sl = wl + bSrc + r0;
        CP16(sbBh + d + bOff, sh);  CP16(sbBh + d + bOff + 16, sh + 8);
        CP16(sbBl + d + bOff, sl);  CP16(sbBl + d + bOff + 16, sl + 8);
    };

    auto ldgA = [&](int r0) {
        int r = r0 + kloc;
        if (MODE == 0) {
            int ic = r / (KK * KK);
            int rem = r - ic * KK * KK;
            int kh = rem / KK, kw = rem - kh * KK;
            int px = pxbase + pblk * 16;
            int oh = px >> 6, ow0 = px & 63;
            int ih = oh * S + kh - P;
            const size_t rowb = ((size_t)(b * Cin + ic) * Hin + ih) * Win;
            bool okh = (unsigned)ih < (unsigned)Hin;
#pragma unroll
            for (int i = 0; i < 16; i++) {
                int iw = (ow0 + i) * S + kw - P;
                bool ok = okh && (unsigned)iw < (unsigned)Win;
                pvh[i] = ok ? xh[rowb + iw] : __float2bfloat16(0.f);
                pvl[i] = ok ? xl[rowb + iw] : __float2bfloat16(0.f);
            }
        } else {
            int ic = r >> 2, th = (r >> 1) & 1, tw = r & 1;
            int j = j0 + (pblk >> 2);
            int i0 = (pblk & 3) * 16;
            int ih = j + (1 - ohp) - th;
            int iwb = i0 + (1 - owp) - tw;
            const size_t rowb = ((size_t)(b * Cin + ic) * 64 + ih) * 64;
            bool okh = (unsigned)ih < 64u;
#pragma unroll
            for (int i = 0; i < 16; i++) {
                int iw = iwb + i;
                bool ok = okh && (unsigned)iw < 64u;
                pvh[i] = ok ? xh[rowb + iw] : __float2bfloat16(0.f);
                pvl[i] = ok ? xl[rowb + iw] : __float2bfloat16(0.f);
            }
        }
    };

    auto stsA = [&](int bf) {
        int base = bf * ABUF + kloc;
#pragma unroll
        for (int i = 0; i < 16; i++) {
            int p = pblk * 16 + i;
            sA_h[base + p * CLDA] = pvh[i];
            sA_l[base + p * CLDA] = pvl[i];
        }
    };

    auto domma = [&](int bf) {
        const int off = bf * ABUF;
#pragma unroll
        for (int ks = 0; ks < 2; ks++) {
            const int k0 = ks * 16 + lc * 2;
            uint32_t ah[2][4], al[2][4];
#pragma unroll
            for (int mf = 0; mf < 2; mf++) {
                int r1 = wm * 32 + mf * 16 + lr;
                ah[mf][0] = *(const uint32_t*)&sA_h[off + r1 * CLDA + k0];
                ah[mf][1] = *(const uint32_t*)&sA_h[off + (r1 + 8) * CLDA + k0];
                ah[mf][2] = *(const uint32_t*)&sA_h[off + r1 * CLDA + k0 + 8];
                ah[mf][3] = *(const uint32_t*)&sA_h[off + (r1 + 8) * CLDA + k0 + 8];
                al[mf][0] = *(const uint32_t*)&sA_l[off + r1 * CLDA + k0];
                al[mf][1] = *(const uint32_t*)&sA_l[off + (r1 + 8) * CLDA + k0];
                al[mf][2] = *(const uint32_t*)&sA_l[off + r1 * CLDA + k0 + 8];
                al[mf][3] = *(const uint32_t*)&sA_l[off + (r1 + 8) * CLDA + k0 + 8];
            }
#pragma unroll
            for (int nf = 0; nf < 8; nf++) {
                int cr = wn * 64 + nf * 8 + lr;
                uint32_t bh[2], bl[2];
                bh[0] = *(const uint32_t*)&sB_h[off + cr * CLDA + k0];
                bh[1] = *(const uint32_t*)&sB_h[off + cr * CLDA + k0 + 8];
                bl[0] = *(const uint32_t*)&sB_l[off + cr * CLDA + k0];
                bl[1] = *(const uint32_t*)&sB_l[off + cr * CLDA + k0 + 8];
#pragma unroll
                for (int mf = 0; mf < 2; mf++) {
                    mma_bf16(acc[mf][nf], ah[mf], bh);
                    mma_bf16(acc[mf][nf], al[mf], bh);
                    mma_bf16(acc[mf][nf], ah[mf], bl);
                }
            }
        }
    };

    cpB(0, 0); CP_COMMIT();
    ldgA(0); stsA(0);
    for (int kc = 0; kc < NC; kc++) {
        const int bf = kc & 1;
        const bool nxt = (kc + 1 < NC);
        if (nxt) {
            cpB((kc + 1) * 32, bf ^ 1); CP_COMMIT();
            ldgA((kc + 1) * 32);
            CP_WAIT1();
        } else {
            CP_WAIT0();
        }
        __syncthreads();
        domma(bf);
        if (nxt) stsA(bf ^ 1);
        __syncthreads();
    }

#pragma unroll
    for (int mf = 0; mf < 2; mf++)
#pragma unroll
        for (int nf = 0; nf < 8; nf++)
#pragma unroll
            for (int e = 0; e < 4; e++) {
                int row = wm * 32 + mf * 16 + lr + (e >> 1) * 8;
                int oc = wn * 64 + nf * 8 + lc * 2 + (e & 1);
                float v = acc[mf][nf][e] + biasS[oc];
                if (RELU) v = fmaxf(v, 0.f);
                size_t addr;
                if (MODE == 0) {
                    int px = pxbase + row;
                    addr = ((size_t)(b * 128 + oc) * 64 + (px >> 6)) * 64 + (px & 63);
                } else {
                    int oh = (1 - ohp) + 2 * (j0 + (row >> 6));
                    int ow = (1 - owp) + 2 * (row & 63);
                    addr = ((size_t)(b * 128 + oc) * 128 + oh) * 128 + ow;
                }
                if (OUTMODE == 0) {
                    outf[addr] = v;
                } else {
                    __nv_bfloat16 h = __float2bfloat16(v);
                    outh[addr] = h;
                    outl[addr] = __float2bfloat16(v - __bfloat162float(h));
                }
            }
}

// =====================================================================
// weight split kernels (decoder only)
// =====================================================================
__global__ void wsplit(const float* __restrict__ w, __nv_bfloat16* __restrict__ wh,
                       __nv_bfloat16* __restrict__ wl, int n)
{
    int i = blockIdx.x * 256 + threadIdx.x;
    if (i >= n) return;
    float x = w[i];
    __nv_bfloat16 h = __float2bfloat16(x);
    wh[i] = h;
    wl[i] = __float2bfloat16(x - __bfloat162float(h));
}

__global__ void pack_wt2(const float* __restrict__ w, __nv_bfloat16* __restrict__ wh,
                         __nv_bfloat16* __restrict__ wl)
{
    int i = blockIdx.x * 256 + threadIdx.x;      // over 4*128*512
    int cls = i >> 16;
    int oc = (i >> 9) & 127;
    int r = i & 511;
    int ohp = cls >> 1, owp = cls & 1;
    int ic = r >> 2, th = (r >> 1) & 1, tw = r & 1;
    float x = w[((ic * 128 + oc) * 4 + ohp + 2 * th) * 4 + owp + 2 * tw];
    __nv_bfloat16 h = __float2bfloat16(x);
    wh[i] = h;
    wl[i] = __float2bfloat16(x - __bfloat162float(h));
}

// =====================================================================
// row squared-norm (exact R1 arithmetic)
// =====================================================================
__global__ void rownorm_kernel(const float* __restrict__ v, float* __restrict__ outn, int rows)
{
    int warp = threadIdx.x >> 5, lane = threadIdx.x & 31;
    int n = blockIdx.x * 8 + warp;
    if (n >= rows) return;
    const float* p = v + (size_t)n * 256;
    float s = 0.f;
#pragma unroll
    for (int k = 0; k < 8; k++) { float x = p[lane + 32 * k]; s = fmaf(x, x, s); }
#pragma unroll
    for (int off = 16; off; off >>= 1) s += __shfl_down_sync(0xffffffffu, s, off);
    if (lane == 0) outn[n] = s;
}

__global__ void zero_commit_kernel(float* c) { *c = 0.f; }

// =====================================================================
// VQ pack kernels (exact R3)
// =====================================================================
__global__ void pack_z_bf16(const float* __restrict__ z, __nv_bfloat16* __restrict__ A)
{
    int i = blockIdx.x * 256 + threadIdx.x;
    int q = i >> 8, k = i & 255;
    float x = z[i];
    __nv_bfloat16 h = __float2bfloat16(x);
    __nv_bfloat16 l = __float2bfloat16(x - __bfloat162float(h));
    size_t base = (size_t)q * KP;
    A[base + k] = h;
    A[base + 256 + k] = l;
    A[base + 512 + k] = h;
}

__global__ void pack_c_bf16(const float* __restrict__ c, __nv_bfloat16* __restrict__ B)
{
    int i = blockIdx.x * 256 + threadIdx.x;
    int q = i >> 8, k = i & 255;
    float x = c[i];
    __nv_bfloat16 h = __float2bfloat16(x);
    __nv_bfloat16 l = __float2bfloat16(x - __bfloat162float(h));
    size_t base = (size_t)q * KP;
    B[base + k] = h;
    B[base + 256 + k] = h;
    B[base + 512 + k] = l;
}

// =====================================================================
// VQ GEMM + fused argmin (exact R3/R6 — fastest passing version)
// =====================================================================
#define LDA 40
#define BUFB (128 * LDA * 2)

__global__ __launch_bounds__(256)
void vq_mma(const __nv_bfloat16* __restrict__ Apk, const __nv_bfloat16* __restrict__ Bpk,
            const float* __restrict__ znorm, const float* __restrict__ cnorm,
            float* __restrict__ bv8, int* __restrict__ bi8)
{
    __shared__ __align__(16) __nv_bfloat16 sA[2][128 * LDA];
    __shared__ __align__(16) __nv_bfloat16 sB[2][128 * LDA];
    __shared__ float znS[128], cnS[128];
    __shared__ float redV[2][128];
    __shared__ int   redI[2][128];

    const int tid = threadIdx.x;
    const int lane = tid & 31, wid = tid >> 5;
    const int wm = wid & 3, wn = wid >> 2;
    const int lr = lane >> 2, lc = lane & 3;
    const int qbase = blockIdx.x * 128;
    const int gbase = blockIdx.y * 1024;

    if (tid < 128) znS[tid] = znorm[qbase + tid];
    __syncthreads();
    float znr[4];
#pragma unroll
    for (int s = 0; s < 4; s++)
        znr[s] = znS[wm * 32 + (s >> 1) * 16 + lr + (s & 1) * 8];

    float bestv[4] = {3.4e38f, 3.4e38f, 3.4e38f, 3.4e38f};
    int   besti[4] = {0, 0, 0, 0};

    float acc[2][8][4];
#pragma unroll
    for (int mf = 0; mf < 2; mf++)
#pragma unroll
        for (int nf = 0; nf < 8; nf++)
#pragma unroll
            for (int e = 0; e < 4; e++) acc[mf][nf][e] = 0.f;

    const int srow = tid >> 1;
    const __nv_bfloat16* asrc = Apk + (size_t)(qbase + srow) * KP + (tid & 1) * 16;
    const uint32_t saA = s2u(sA) + srow * (LDA * 2) + (tid & 1) * 32;
    const uint32_t saB = s2u(sB) + srow * (LDA * 2) + (tid & 1) * 32;

    for (int nt = 0; nt < 8; nt++) {
        const __nv_bfloat16* bsrc =
            Bpk + (size_t)(gbase + nt * 128 + srow) * KP + (tid & 1) * 16;
        if (tid < 128) cnS[tid] = cnorm[gbase + nt * 128 + tid];

        CP16(saA, asrc);      CP16(saA + 16, asrc + 8);
        CP16(saB, bsrc);      CP16(saB + 16, bsrc + 8);
        CP_COMMIT();

        for (int kc = 0; kc < 24; kc++) {
            if (kc + 1 < 24) {
                const uint32_t nb = (uint32_t)((kc + 1) & 1) * BUFB;
                const __nv_bfloat16* a2 = asrc + (kc + 1) * 32;
                const __nv_bfloat16* b2 = bsrc + (kc + 1) * 32;
                CP16(saA + nb, a2);      CP16(saA + nb + 16, a2 + 8);
                CP16(saB + nb, b2);      CP16(saB + nb + 16, b2 + 8);
                CP_COMMIT();
                CP_WAIT1();
            } else {
                CP_WAIT0();
            }
            __syncthreads();

            const int buf = kc & 1;
#pragma unroll
            for (int ks = 0; ks < 2; ks++) {
                const int k0 = ks * 16 + lc * 2;
                uint32_t a[2][4], b[8][2];
#pragma unroll
                for (int mf = 0; mf < 2; mf++) {
                    int r = wm * 32 + mf * 16 + lr;
                    a[mf][0] = *(const uint32_t*)&sA[buf][r * LDA + k0];
                    a[mf][1] = *(const uint32_t*)&sA[buf][(r + 8) * LDA + k0];
                    a[mf][2] = *(const uint32_t*)&sA[buf][r * LDA + k0 + 8];
                    a[mf][3] = *(const uint32_t*)&sA[buf][(r + 8) * LDA + k0 + 8];
                }
#pragma unroll
                for (int nf = 0; nf < 8; nf++) {
                    int cr = wn * 64 + nf * 8 + lr;
                    b[nf][0] = *(const uint32_t*)&sB[buf][cr * LDA + k0];
                    b[nf][1] = *(const uint32_t*)&sB[buf][cr * LDA + k0 + 8];
                }
#pragma unroll
                for (int mf = 0; mf < 2; mf++)
#pragma unroll
                    for (int nf = 0; nf < 8; nf++)
                        mma_bf16(acc[mf][nf], a[mf], b[nf]);
            }
            __syncthreads();
        }

#pragma unroll
        for (int mf = 0; mf < 2; mf++)
#pragma unroll
            for (int nf = 0; nf < 8; nf++)
#pragma unroll
                for (int e = 0; e < 4; e++) {
                    int h = e >> 1;
                    int col = wn * 64 + nf * 8 + lc * 2 + (e & 1);
                    int slot = mf * 2 + h;
                    float t = znr[slot] + cnS[col];
                    float s = fmaf(-2.f, acc[mf][nf][e], t);
                    int code = gbase + nt * 128 + col;
                    if (s < bestv[slot]) { bestv[slot] = s; besti[slot] = code; }
                    acc[mf][nf][e] = 0.f;
                }
        __syncthreads();
    }

#pragma unroll
    for (int s = 0; s < 4; s++) {
        float v = bestv[s]; int ix = besti[s];
#pragma unroll
        for (int off = 1; off <= 2; off <<= 1) {
            float ov = __shfl_xor_sync(0xffffffffu, v, off);
            int   oi = __shfl_xor_sync(0xffffffffu, ix, off);
            if (ov < v || (ov == v && oi < ix)) { v = ov; ix = oi; }
        }
        if (lc == 0) {
            int row = wm * 32 + (s >> 1) * 16 + lr + (s & 1) * 8;
            redV[wn][row] = v; redI[wn][row] = ix;
        }
    }
    __syncthreads();
    if (tid < 128) {
        float v = redV[0][tid]; int ix = redI[0][tid];
        float v1 = redV[1][tid]; int i1 = redI[1][tid];
        if (v1 < v || (v1 == v && i1 < ix)) { v = v1; ix = i1; }
        bv8[blockIdx.y * NQ + qbase + tid] = v;
        bi8[blockIdx.y * NQ + qbase + tid] = ix;
    }
}

__global__ void vq_combine8(const float* __restrict__ bv8, const int* __restrict__ bi8,
                            int* __restrict__ idx)
{
    int q = blockIdx.x * 256 + threadIdx.x;
    if (q >= NQ) return;
    float v = bv8[q]; int ix = bi8[q];
#pragma unroll
    for (int g = 1; g < 8; g++) {
        float v2 = bv8[g * NQ + q];
        int   i2 = bi8[g * NQ + q];
        if (v2 < v || (v2 == v && i2 < ix)) { v = v2; ix = i2; }
    }
    idx[q] = ix;
}

// =====================================================================
// gather quant = codebook[idx], commit loss
// =====================================================================
__global__ __launch_bounds__(256)
void gather_commit(const float* __restrict__ cb, const float* __restrict__ z,
                   const int* __restrict__ idx, float* __restrict__ quant,
                   float* __restrict__ commit)
{
    int n = blockIdx.x;
    int t = threadIdx.x;
    int id = idx[n];
    float q = cb[(size_t)id * 256 + t];
    float zv = z[(size_t)n * 256 + t];
    quant[(size_t)n * 256 + t] = q;
    float d = q - zv; d *= d;
#pragma unroll
    for (int off = 16; off; off >>= 1) d += __shfl_down_sync(0xffffffffu, d, off);
    __shared__ float wsum[8];
    int warp = t >> 5, lane = t & 31;
    if (lane == 0) wsum[warp] = d;
    __syncthreads();
    if (t == 0) {
        float s = 0.f;
#pragma unroll
        for (int w = 0; w < 8; w++) s += wsum[w];
        atomicAdd(commit, s);
    }
}

// =====================================================================
// Final transposed conv (128 -> 3 channels) straight into d_out
// =====================================================================
__global__ __launch_bounds__(256)
void convt_out3(const float* __restrict__ in, const float* __restrict__ w,
                const float* __restrict__ bias, float* __restrict__ out)
{
    __shared__ float ws[128 * 3 * 16];
    for (int i = threadIdx.x; i < 6144; i += 256) ws[i] = w[i];
    __syncthreads();

    int b = blockIdx.y, oh = blockIdx.x, ow = threadIdx.x;
    int ih0 = (oh + 1) >> 1, kh0 = (oh + 1) & 1;
    int iw0 = (ow + 1) >> 1, kw0 = (ow + 1) & 1;

    float acc0 = 0.f, acc1 = 0.f, acc2 = 0.f;
    for (int ic = 0; ic < 128; ic++) {
        const float* inp = in + ((size_t)(b * 128 + ic)) * 128 * 128;
        const float* wp = ws + ic * 48;
#pragma unroll
        for (int th = 0; th < 2; th++) {
            int ih = ih0 - th;
            if ((unsigned)ih < 128u) {
                int kh = kh0 + 2 * th;
#pragma unroll
                for (int tw = 0; tw < 2; tw++) {
                    int iw = iw0 - tw;
                    if ((unsigned)iw < 128u) {
                        int kw = kw0 + 2 * tw;
                        float v = inp[ih * 128 + iw];
                        int wk = kh * 4 + kw;
                        acc0 = fmaf(v, wp[wk], acc0);
                        acc1 = fmaf(v, wp[16 + wk], acc1);
                        acc2 = fmaf(v, wp[32 + wk], acc2);
                    }
                }
            }
        }
    }
    size_t ob = ((size_t)(b * 3) * 256 + oh) * 256 + ow;
    out[ob]          = acc0 + bias[0];
    out[ob + 65536]  = acc1 + bias[1];
    out[ob + 131072] = acc2 + bias[2];
}

__global__ void pack_kernel(float* __restrict__ out, const float* __restrict__ commit,
                            const int* __restrict__ idx)
{
    int i = blockIdx.x * 256 + threadIdx.x;
    if (i == 0) out[786432] = (*commit) * (1.f / 4194304.f);
    if (i < NQ) out[786433 + i] = (float)idx[i];
}

// =====================================================================
// host launcher
// =====================================================================
#define CMMA_SMEM 82432

extern "C" void kernel_launch(void* const* d_in, const int* in_sizes, int n_in,
                              void* d_out, int out_size)
{
    const float* x        = (const float*)d_in[0];
    const float* enc_w1   = (const float*)d_in[1];
    const float* enc_b1   = (const float*)d_in[2];
    const float* enc_w2   = (const float*)d_in[3];
    const float* enc_b2   = (const float*)d_in[4];
    const float* enc_w3   = (const float*)d_in[5];
    const float* enc_b3   = (const float*)d_in[6];
    const float* qconv_w  = (const float*)d_in[7];
    const float* qconv_b  = (const float*)d_in[8];
    const float* codebook = (const float*)d_in[9];
    const float* pqconv_w = (const float*)d_in[10];
    const float* pqconv_b = (const float*)d_in[11];
    const float* dec_w1   = (const float*)d_in[12];
    const float* dec_b1   = (const float*)d_in[13];
    const float* dect_w2  = (const float*)d_in[14];
    const float* dect_b2  = (const float*)d_in[15];
    const float* dect_w3  = (const float*)d_in[16];
    const float* dect_b3  = (const float*)d_in[17];
    float* out = (float*)d_out;

    float *h1, *h2, *h3, *z, *quant, *d2, *znorm, *cnorm, *commit, *bv8;
    float *w2t, *w3t, *wqt, *wpt;
    __nv_bfloat16 *qh, *ql, *d1h, *d1l, *apk, *bpk;
    __nv_bfloat16 *wd1h, *wd1l, *wt2h, *wt2l;
    int *idx, *bi8;
    cudaGetSymbolAddress((void**)&h1, g_h1);
    cudaGetSymbolAddress((void**)&h2, g_h2);
    cudaGetSymbolAddress((void**)&h3, g_h3);
    cudaGetSymbolAddress((void**)&z, g_z);
    cudaGetSymbolAddress((void**)&quant, g_quant);
    cudaGetSymbolAddress((void**)&qh, g_qh);
    cudaGetSymbolAddress((void**)&ql, g_ql);
    cudaGetSymbolAddress((void**)&d1h, g_d1h);
    cudaGetSymbolAddress((void**)&d1l, g_d1l);
    cudaGetSymbolAddress((void**)&d2, g_d2);
    cudaGetSymbolAddress((void**)&znorm, g_znorm);
    cudaGetSymbolAddress((void**)&cnorm, g_cnorm);
    cudaGetSymbolAddress((void**)&idx, g_idx);
    cudaGetSymbolAddress((void**)&commit, g_commit);
    cudaGetSymbolAddress((void**)&apk, g_apk);
    cudaGetSymbolAddress((void**)&bpk, g_bpk);
    cudaGetSymbolAddress((void**)&bv8, g_bv8);
    cudaGetSymbolAddress((void**)&bi8, g_bi8);
    cudaGetSymbolAddress((void**)&wd1h, g_wd1h); cudaGetSymbolAddress((void**)&wd1l, g_wd1l);
    cudaGetSymbolAddress((void**)&wt2h, g_wt2h); cudaGetSymbolAddress((void**)&wt2l, g_wt2l);
    cudaGetSymbolAddress((void**)&w2t, g_w2t);   cudaGetSymbolAddress((void**)&w3t, g_w3t);
    cudaGetSymbolAddress((void**)&wqt, g_wqt);   cudaGetSymbolAddress((void**)&wpt, g_wpt);

    cudaFuncSetAttribute(conv_mma<0,3,1,1,true ,1>, cudaFuncAttributeMaxDynamicSharedMemorySize, CMMA_SMEM);
    cudaFuncSetAttribute(conv_mma<1,4,2,1,true ,0>, cudaFuncAttributeMaxDynamicSharedMemorySize, CMMA_SMEM);

    // weight prep: fp32 chunk-major transposes + decoder splits + VQ codebook
    wtrans<<<1024, 256>>>(enc_w2, w2t, 2048, 128);
    wtrans<<<576, 256>>>(enc_w3, w3t, 1152, 128);
    wtrans<<<128, 256>>>(qconv_w, wqt, 128, 256);
    wtrans<<<128, 256>>>(pqconv_w, wpt, 256, 128);
    wsplit<<<576, 256>>>(dec_w1, wd1h, wd1l, 128 * 1152);
    pack_wt2<<<1024, 256>>>(dect_w2, wt2h, wt2l);
    pack_c_bf16<<<KCB, 256>>>(codebook, bpk);
    rownorm_kernel<<<1024, 256>>>(codebook, cnorm, KCB);
    zero_commit_kernel<<<1, 1>>>(commit);

    // encoder — enc1 dedicated; enc2/enc3/qconv on async-staged FFMA2
    conv_enc1<<<dim3(128,4),256>>>(x, enc_w1, enc_b1, h1);
    conv_async<4,2,1,true ,0,0><<<dim3(64,1,4),256>>>(h1, w2t, enc_b2, h2, nullptr, nullptr,
                                                      128,128, 128,128,  64, 64, 6);
    conv_async<3,1,1,false,0,0><<<dim3(64,1,4),256>>>(h2, w3t, enc_b3, h3, nullptr, nullptr,
                                                      128,128,  64, 64,  64, 64, 6);
    conv_async<1,1,0,false,0,1><<<dim3(64,2,4),256>>>(h3, wqt, qconv_b, z, nullptr, nullptr,
                                                      128,256,  64, 64,  64, 64, 6);

    // quantize — exact R3/R6 path
    pack_z_bf16<<<NQ, 256>>>(z, apk);
    rownorm_kernel<<<2048, 256>>>(z, znorm, NQ);
    vq_mma<<<dim3(128, 8), 256>>>(apk, bpk, znorm, cnorm, bv8, bi8);
    vq_combine8<<<64, 256>>>(bv8, bi8, idx);
    gather_commit<<<NQ, 256>>>(codebook, z, idx, quant, commit);

    // decoder — tensor-core bf16-split
    conv_async<1,1,0,false,1,2><<<dim3(64,1,4),256>>>(quant, wpt, pqconv_b, nullptr, qh, ql,
                                                      256, 128, 64,64, 64,64, 6);
    conv_mma<0,3,1,1,true ,1><<<dim3(32,1,4),256,CMMA_SMEM>>>(qh, ql, wd1h, wd1l, dec_b1,
                                                     nullptr, d1h, d1l, 128, 64, 64, 1152);
    conv_mma<1,4,2,1,true ,0><<<dim3(32,4,4),256,CMMA_SMEM>>>(d1h, d1l, wt2h, wt2l, dect_b2,
                                                     d2, nullptr, nullptr, 128, 64, 64, 512);
    convt_out3<<<dim3(256,4),256>>>(d2, dect_w3, dect_b3, out);

    pack_kernel<<<64, 256>>>(out, commit, idx);

    (void)in_sizes; (void)n_in; (void)out_size;
}

// round 13
// speedup vs baseline: 1.1249x; 1.0067x over previous
#include <cuda_runtime.h>
#include <cuda_bf16.h>
#include <cstdint>

// ---------------- problem constants ----------------
#define BATCH 4
#define NQ    16384
#define EDIM  256
#define KCB   8192
#define KP    768            // packed K' = 3 * 256 for VQ GEMM

// ---------------- scratch (static device memory; no allocation) ----------------
__device__ float g_h1[4 * 128 * 128 * 128];
__device__ float g_h2[4 * 128 * 64 * 64];
__device__ float g_h3[4 * 128 * 64 * 64];
__device__ float g_z[NQ * EDIM];
__device__ float g_quant[NQ * EDIM];
__device__ __nv_bfloat16 g_qh[4 * 128 * 64 * 64];
__device__ __nv_bfloat16 g_ql[4 * 128 * 64 * 64];
__device__ __nv_bfloat16 g_d1h[4 * 128 * 64 * 64];
__device__ __nv_bfloat16 g_d1l[4 * 128 * 64 * 64];
__device__ float g_d2[4 * 128 * 128 * 128];
__device__ float g_znorm[NQ];
__device__ float g_cnorm[KCB];
__device__ int   g_idx[NQ];
__device__ float g_commit;
// VQ packed split buffers
__device__ __nv_bfloat16 g_apk[(size_t)NQ * KP];
__device__ __nv_bfloat16 g_bpk[(size_t)KCB * KP];
__device__ float g_bv8[8 * NQ];
__device__ int   g_bi8[8 * NQ];
// pre-split decoder weights
__device__ __nv_bfloat16 g_wd1h[128 * 1152], g_wd1l[128 * 1152];
__device__ __nv_bfloat16 g_wt2h[4 * 128 * 512], g_wt2l[4 * 128 * 512];
// chunk-major transposed fp32 weights for async FFMA convs
__device__ float g_w2t[128 * 2048];
__device__ float g_w3t[128 * 1152];
__device__ float g_wqt[256 * 128];
__device__ float g_wpt[128 * 256];

__device__ __forceinline__ uint32_t s2u(const void* p)
{
    uint32_t a;
    asm("{ .reg .u64 t; cvta.to.shared.u64 t, %1; cvt.u32.u64 %0, t; }" : "=r"(a) : "l"(p));
    return a;
}

#define CP16(dst, src) \
    asm volatile("cp.async.cg.shared.global [%0], [%1], 16;" :: "r"(dst), "l"(src) : "memory")
#define CP4Z(dst, src, sz) \
    asm volatile("cp.async.ca.shared.global [%0], [%1], 4, %2;" :: "r"(dst), "l"(src), "r"(sz) : "memory")
#define CP_COMMIT() asm volatile("cp.async.commit_group;" ::: "memory")
#define CP_WAIT2()  asm volatile("cp.async.wait_group 2;" ::: "memory")
#define CP_WAIT1()  asm volatile("cp.async.wait_group 1;" ::: "memory")
#define CP_WAIT0()  asm volatile("cp.async.wait_group 0;" ::: "memory")

__device__ __forceinline__ void mma_bf16(float* c, const uint32_t* a, const uint32_t* b)
{
    asm volatile(
        "mma.sync.aligned.m16n8k16.row.col.f32.bf16.bf16.f32 "
        "{%0,%1,%2,%3}, {%4,%5,%6,%7}, {%8,%9}, {%0,%1,%2,%3};"
        : "+f"(c[0]), "+f"(c[1]), "+f"(c[2]), "+f"(c[3])
        : "r"(a[0]), "r"(a[1]), "r"(a[2]), "r"(a[3]), "r"(b[0]), "r"(b[1]));
}

__device__ __forceinline__ void ffma2(uint64_t& acc, uint64_t wp, uint64_t xx)
{
    asm("fma.rn.f32x2 %0, %1, %2, %0;" : "+l"(acc) : "l"(wp), "l"(xx));
}

// =====================================================================
// Weight transpose into chunk-major [ocTile][chunk][r(16)][ocl(128)].
// =====================================================================
__global__ void wtrans(const float* __restrict__ w, float* __restrict__ wt, int R, int Cout)
{
    int i = blockIdx.x * 256 + threadIdx.x;
    if (i >= Cout * R) return;
    int ocl = i & 127;
    int rest = i >> 7;
    int r = rest & 15;
    int chunkAll = rest >> 4;
    int NC = R >> 4;
    int ot = chunkAll / NC;
    int c = chunkAll - ot * NC;
    wt[i] = w[(size_t)(ot * 128 + ocl) * R + c * 16 + r];
}

// =====================================================================
// Dedicated enc1 kernel (R9 — passing; h1 bitwise identical)
// =====================================================================
__global__ __launch_bounds__(256)
void conv_enc1(const float* __restrict__ x, const float* __restrict__ w,
               const float* __restrict__ bias, float* __restrict__ out)
{
    __shared__ __align__(16) float ws[48][128];
    __shared__ __align__(16) float xs[48][128];

    const int tid = threadIdx.x;
    const int oh = blockIdx.x;
    const int b = blockIdx.y;

#pragma unroll
    for (int i = 0; i < 24; i++) {
        int idx = tid + i * 256;
        int r = idx >> 7, oc = idx & 127;
        ws[r][oc] = w[oc * 48 + r];
    }
#pragma unroll
    for (int i = 0; i < 24; i++) {
        int idx = tid + i * 256;
        int r = idx >> 7, p = idx & 127;
        int ic = r >> 4, kh = (r >> 2) & 3, kw = r & 3;
        int ih = oh * 2 + kh - 1;
        int iw = p * 2 + kw - 1;
        float v = 0.f;
        if ((unsigned)ih < 256u && (unsigned)iw < 256u)
            v = x[((size_t)(b * 3 + ic) * 256 + ih) * 256 + iw];
        xs[r][p] = v;
    }
    __syncthreads();

    const int tx = tid & 15;
    const int ty = tid >> 4;
    const uint32_t wsb = s2u(ws) + ty * 32;

    uint64_t acc2[4][8];
#pragma unroll
    for (int pq = 0; pq < 4; pq++)
#pragma unroll
        for (int i = 0; i < 8; i++) acc2[pq][i] = 0ull;

#pragma unroll 4
    for (int k = 0; k < 48; k++) {
        uint64_t wp0, wp1, wp2, wp3;
        asm("ld.shared.v2.u64 {%0,%1}, [%2];"
            : "=l"(wp0), "=l"(wp1) : "r"(wsb + (uint32_t)(k * 512)));
        asm("ld.shared.v2.u64 {%0,%1}, [%2];"
            : "=l"(wp2), "=l"(wp3) : "r"(wsb + (uint32_t)(k * 512 + 16)));
        float4 xv0 = *reinterpret_cast<const float4*>(&xs[k][tx * 8]);
        float4 xv1 = *reinterpret_cast<const float4*>(&xs[k][tx * 8 + 4]);
        uint64_t xx[8];
        asm("mov.b64 %0, {%1,%1};" : "=l"(xx[0]) : "f"(xv0.x));
        asm("mov.b64 %0, {%1,%1};" : "=l"(xx[1]) : "f"(xv0.y));
        asm("mov.b64 %0, {%1,%1};" : "=l"(xx[2]) : "f"(xv0.z));
        asm("mov.b64 %0, {%1,%1};" : "=l"(xx[3]) : "f"(xv0.w));
        asm("mov.b64 %0, {%1,%1};" : "=l"(xx[4]) : "f"(xv1.x));
        asm("mov.b64 %0, {%1,%1};" : "=l"(xx[5]) : "f"(xv1.y));
        asm("mov.b64 %0, {%1,%1};" : "=l"(xx[6]) : "f"(xv1.z));
        asm("mov.b64 %0, {%1,%1};" : "=l"(xx[7]) : "f"(xv1.w));
#pragma unroll
        for (int i = 0; i < 8; i++) {
            ffma2(acc2[0][i], wp0, xx[i]);
            ffma2(acc2[1][i], wp1, xx[i]);
            ffma2(acc2[2][i], wp2, xx[i]);
            ffma2(acc2[3][i], wp3, xx[i]);
        }
    }

#pragma unroll
    for (int pq = 0; pq < 4; pq++)
#pragma unroll
        for (int half = 0; half < 2; half++) {
            int oc = ty * 8 + 2 * pq + half;
            float bv = bias[oc];
            float* op = out + ((size_t)(b * 128 + oc) * 128 + oh) * 128 + tx * 8;
#pragma unroll
            for (int i = 0; i < 8; i++) {
                uint32_t bits = half ? (uint32_t)(acc2[pq][i] >> 32)
                                     : (uint32_t)(acc2[pq][i] & 0xffffffffull);
                float v = __uint_as_float(bits) + bv;
                op[i] = fmaxf(v, 0.f);
            }
        }
}

// =====================================================================
// FFMA2 implicit-GEMM conv with cp.async 4-STAGE pipeline (one sync per
// chunk, 2-chunk prefetch distance). Weights from chunk-major transposed
// copy; x gathers via 4B cp.async zfill. Per-output chain unchanged
// (single fp32 acc, ascending k) => z bitwise stable.
// OUTL: 0 = NCHW f32, 1 = [n][Cout] f32, 2 = bf16 split planes NCHW.
// =====================================================================
template<int KK, int S, int P, bool RELU, int INL, int OUTL>
__global__ __launch_bounds__(256)
void conv_async(const float* __restrict__ in, const float* __restrict__ wt,
                const float* __restrict__ bias, float* __restrict__ out,
                __nv_bfloat16* __restrict__ outh, __nv_bfloat16* __restrict__ outl,
                int Cin, int Cout, int Hin, int Win, int Hout, int Wout,
                int woutShift)
{
    const int R = Cin * KK * KK;
    const int NC = R >> 4;
    const int b = blockIdx.z;
    const int ot = blockIdx.y;
    const int oc0 = ot * 128;
    const int pxbase = blockIdx.x * 64;

    __shared__ __align__(16) float ws[4][16][128];
    __shared__ __align__(16) float xs[4][16][68];

    const int tid = threadIdx.x;
    const int tx = tid & 15;
    const int ty = tid >> 4;

    const uint32_t wsb0 = s2u(ws);
    const uint32_t xsb0 = s2u(xs);
    const uint32_t wdst = wsb0 + (uint32_t)tid * 32;
    const float* wsrc_base = wt + (size_t)ot * ((size_t)NC * 2048) + tid * 8;

    uint64_t acc2[4][4];
#pragma unroll
    for (int p = 0; p < 4; p++)
#pragma unroll
        for (int i = 0; i < 4; i++) acc2[p][i] = 0ull;

    auto stage = [&](int c, int bf) {
        const float* wsrc = wsrc_base + (size_t)c * 2048;
        uint32_t wd = wdst + (uint32_t)bf * 8192;
        CP16(wd, wsrc);
        CP16(wd + 16, wsrc + 4);
#pragma unroll
        for (int i2 = 0; i2 < 4; i2++) {
            int li = tid + i2 * 256;
            int r, p;
            if (INL == 1) { r = li & 15; p = li >> 4; }
            else          { r = li >> 6; p = li & 63; }
            int rr = c * 16 + r;
            const float* src = in;
            int sz = 0;
            if (INL == 1) {
                int n = b * (Hout * Wout) + pxbase + p;
                src = in + (size_t)n * Cin + rr;
                sz = 4;
            } else {
                int ic = rr / (KK * KK);
                int kr = rr - ic * KK * KK;
                int kh = kr / KK, kw = kr - kh * KK;
                int px = pxbase + p;
                int oh = px >> woutShift;
                int ow = px & (Wout - 1);
                int ih = oh * S + kh - P;
                int iw = ow * S + kw - P;
                if ((unsigned)ih < (unsigned)Hin && (unsigned)iw < (unsigned)Win) {
                    src = in + ((size_t)(b * Cin + ic) * Hin + ih) * Win + iw;
                    sz = 4;
                }
            }
            uint32_t xd = xsb0 + (uint32_t)bf * 4352 + (uint32_t)((r * 68 + p) * 4);
            CP4Z(xd, src, sz);
        }
    };

    // prologue: 2 chunks in flight
    stage(0, 0); CP_COMMIT();
    if (NC > 1) { stage(1, 1); CP_COMMIT(); }

    for (int c = 0; c < NC; c++) {
        const int bf = c & 3;
        if (c + 2 < NC) {
            stage(c + 2, (c + 2) & 3); CP_COMMIT();
            CP_WAIT2();
        } else if (c + 1 < NC) {
            CP_WAIT1();
        } else {
            CP_WAIT0();
        }
        __syncthreads();

        const uint32_t wsb = wsb0 + (uint32_t)bf * 8192 + ty * 32;
        const float (*xsb)[68] = xs[bf];
#pragma unroll
        for (int k = 0; k < 16; k++) {
            float4 xv = *reinterpret_cast<const float4*>(&xsb[k][tx * 4]);
            uint64_t wp0, wp1, wp2, wp3;
            asm("ld.shared.v2.u64 {%0,%1}, [%2];"
                : "=l"(wp0), "=l"(wp1) : "r"(wsb + (uint32_t)(k * 512)));
            asm("ld.shared.v2.u64 {%0,%1}, [%2];"
                : "=l"(wp2), "=l"(wp3) : "r"(wsb + (uint32_t)(k * 512 + 16)));
            uint64_t xx0, xx1, xx2, xx3;
            asm("mov.b64 %0, {%1,%1};" : "=l"(xx0) : "f"(xv.x));
            asm("mov.b64 %0, {%1,%1};" : "=l"(xx1) : "f"(xv.y));
            asm("mov.b64 %0, {%1,%1};" : "=l"(xx2) : "f"(xv.z));
            asm("mov.b64 %0, {%1,%1};" : "=l"(xx3) : "f"(xv.w));
            ffma2(acc2[0][0], wp0, xx0); ffma2(acc2[0][1], wp0, xx1);
            ffma2(acc2[0][2], wp0, xx2); ffma2(acc2[0][3], wp0, xx3);
            ffma2(acc2[1][0], wp1, xx0); ffma2(acc2[1][1], wp1, xx1);
            ffma2(acc2[1][2], wp1, xx2); ffma2(acc2[1][3], wp1, xx3);
            ffma2(acc2[2][0], wp2, xx0); ffma2(acc2[2][1], wp2, xx1);
            ffma2(acc2[2][2], wp2, xx2); ffma2(acc2[2][3], wp2, xx3);
            ffma2(acc2[3][0], wp3, xx0); ffma2(acc2[3][1], wp3, xx1);
            ffma2(acc2[3][2], wp3, xx2); ffma2(acc2[3][3], wp3, xx3);
        }
        // no trailing sync: next iteration's stage targets a buffer last
        // read two iterations ago, fenced by the sync above.
    }

#pragma unroll
    for (int p = 0; p < 4; p++)
#pragma unroll
        for (int half = 0; half < 2; half++) {
            int j = 2 * p + half;
            int oc = oc0 + ty * 8 + j;
            float bv = bias[oc];
#pragma unroll
            for (int i = 0; i < 4; i++) {
                uint32_t bits = half ? (uint32_t)(acc2[p][i] >> 32)
                                     : (uint32_t)(acc2[p][i] & 0xffffffffull);
                float v = __uint_as_float(bits) + bv;
                if (RELU) v = fmaxf(v, 0.f);
                if (OUTL == 1) {
                    size_t n = (size_t)(b * (Hout * Wout) + pxbase + tx * 4 + i);
                    out[n * Cout + oc] = v;
                } else {
                    size_t addr = (size_t)(b * Cout + oc) * (Hout * Wout) + pxbase + tx * 4 + i;
                    if (OUTL == 0) {
                        out[addr] = v;
                    } else {
                        __nv_bfloat16 h = __float2bfloat16(v);
                        outh[addr] = h;
                        outl[addr] = __float2bfloat16(v - __bfloat162float(h));
                    }
                }
            }
        }
}

// =====================================================================
// Tensor-core implicit-GEMM conv, bf16 3-term split — DECODER ONLY.
// (unchanged — passing)
// =====================================================================
#define CLDA 40
#define ABUF 5120

template<int MODE, int KK, int S, int P, bool RELU, int OUTMODE>
__global__ __launch_bounds__(256)
void conv_mma(const __nv_bfloat16* __restrict__ xh, const __nv_bfloat16* __restrict__ xl,
              const __nv_bfloat16* __restrict__ wh_g, const __nv_bfloat16* __restrict__ wl_g,
              const float* __restrict__ bias,
              float* __restrict__ outf, __nv_bfloat16* __restrict__ outh,
              __nv_bfloat16* __restrict__ outl,
              int Cin, int Hin, int Win, int R)
{
    extern __shared__ __align__(16) char sm[];
    __nv_bfloat16* sA_h = (__nv_bfloat16*)(sm);
    __nv_bfloat16* sA_l = (__nv_bfloat16*)(sm + 20480);
    __nv_bfloat16* sB_h = (__nv_bfloat16*)(sm + 40960);
    __nv_bfloat16* sB_l = (__nv_bfloat16*)(sm + 61440);
    float* biasS = (float*)(sm + 81920);

    const int tid = threadIdx.x;
    const int lane = tid & 31, wid = tid >> 5;
    const int wm = wid & 3, wn = wid >> 2;
    const int lr = lane >> 2, lc = lane & 3;
    const int b = blockIdx.z;

    int pxbase = 0, j0 = 0, ohp = 0, owp = 0;
    const __nv_bfloat16* wh = wh_g;
    const __nv_bfloat16* wl = wl_g;
    if (MODE == 1) {
        j0 = blockIdx.x * 2;
        int cls = blockIdx.y;
        ohp = cls >> 1; owp = cls & 1;
        wh = wh_g + cls * (128 * 512);
        wl = wl_g + cls * (128 * 512);
    } else {
        pxbase = blockIdx.x * 128;
    }

    if (tid < 128) biasS[tid] = bias[tid];

    const int NC = R >> 5;

    const int boc = tid >> 1;
    const uint32_t sbBh = s2u(sB_h), sbBl = s2u(sB_l);
    const uint32_t bOff = (uint32_t)(boc * 80 + (tid & 1) * 32);
    const size_t bSrc = (size_t)boc * R + (tid & 1) * 16;

    const int kloc = tid & 31, pblk = tid >> 5;

    float acc[2][8][4];
#pragma unroll
    for (int mf = 0; mf < 2; mf++)
#pragma unroll
        for (int nf = 0; nf < 8; nf++)
#pragma unroll
            for (int e = 0; e < 4; e++) acc[mf][nf][e] = 0.f;

    __nv_bfloat16 pvh[16], pvl[16];

    auto cpB = [&](int r0, int bf) {
        uint32_t d = (uint32_t)bf * 10240;
        const __nv_bfloat16* sh = wh + bSrc + r0;
        const __nv_bfloat16* sl = wl + bSrc + r0;
        CP16(sbBh + d + bOff, sh);  CP16(sbBh + d + bOff + 16, sh + 8);
        CP16(sbBl + d + bOff, sl);  CP16(sbBl + d + bOff + 16, sl + 8);
    };

    auto ldgA = [&](int r0) {
        int r = r0 + kloc;
        if (MODE == 0) {
            int ic = r / (KK * KK);
            int rem = r - ic * KK * KK;
            int kh = rem / KK, kw = rem - kh * KK;
            int px = pxbase + pblk * 16;
            int oh = px >> 6, ow0 = px & 63;
            int ih = oh * S + kh - P;
            const size_t rowb = ((size_t)(b * Cin + ic) * Hin + ih) * Win;
            bool okh = (unsigned)ih < (unsigned)Hin;
#pragma unroll
            for (int i = 0; i < 16; i++) {
                int iw = (ow0 + i) * S + kw - P;
                bool ok = okh && (unsigned)iw < (unsigned)Win;
                pvh[i] = ok ? xh[rowb + iw] : __float2bfloat16(0.f);
                pvl[i] = ok ? xl[rowb + iw] : __float2bfloat16(0.f);
            }
        } else {
            int ic = r >> 2, th = (r >> 1) & 1, tw = r & 1;
            int j = j0 + (pblk >> 2);
            int i0 = (pblk & 3) * 16;
            int ih = j + (1 - ohp) - th;
            int iwb = i0 + (1 - owp) - tw;
            const size_t rowb = ((size_t)(b * Cin + ic) * 64 + ih) * 64;
            bool okh = (unsigned)ih < 64u;
#pragma unroll
            for (int i = 0; i < 16; i++) {
                int iw = iwb + i;
                bool ok = okh && (unsigned)iw < 64u;
                pvh[i] = ok ? xh[rowb + iw] : __float2bfloat16(0.f);
                pvl[i] = ok ? xl[rowb + iw] : __float2bfloat16(0.f);
            }
        }
    };

    auto stsA = [&](int bf) {
        int base = bf * ABUF + kloc;
#pragma unroll
        for (int i = 0; i < 16; i++) {
            int p = pblk * 16 + i;
            sA_h[base + p * CLDA] = pvh[i];
            sA_l[base + p * CLDA] = pvl[i];
        }
    };

    auto domma = [&](int bf) {
        const int off = bf * ABUF;
#pragma unroll
        for (int ks = 0; ks < 2; ks++) {
            const int k0 = ks * 16 + lc * 2;
            uint32_t ah[2][4], al[2][4];
#pragma unroll
            for (int mf = 0; mf < 2; mf++) {
                int r1 = wm * 32 + mf * 16 + lr;
                ah[mf][0] = *(const uint32_t*)&sA_h[off + r1 * CLDA + k0];
                ah[mf][1] = *(const uint32_t*)&sA_h[off + (r1 + 8) * CLDA + k0];
                ah[mf][2] = *(const uint32_t*)&sA_h[off + r1 * CLDA + k0 + 8];
                ah[mf][3] = *(const uint32_t*)&sA_h[off + (r1 + 8) * CLDA + k0 + 8];
                al[mf][0] = *(const uint32_t*)&sA_l[off + r1 * CLDA + k0];
                al[mf][1] = *(const uint32_t*)&sA_l[off + (r1 + 8) * CLDA + k0];
                al[mf][2] = *(const uint32_t*)&sA_l[off + r1 * CLDA + k0 + 8];
                al[mf][3] = *(const uint32_t*)&sA_l[off + (r1 + 8) * CLDA + k0 + 8];
            }
#pragma unroll
            for (int nf = 0; nf < 8; nf++) {
                int cr = wn * 64 + nf * 8 + lr;
                uint32_t bh[2], bl[2];
                bh[0] = *(const uint32_t*)&sB_h[off + cr * CLDA + k0];
                bh[1] = *(const uint32_t*)&sB_h[off + cr * CLDA + k0 + 8];
                bl[0] = *(const uint32_t*)&sB_l[off + cr * CLDA + k0];
                bl[1] = *(const uint32_t*)&sB_l[off + cr * CLDA + k0 + 8];
#pragma unroll
                for (int mf = 0; mf < 2; mf++) {
                    mma_bf16(acc[mf][nf], ah[mf], bh);
                    mma_bf16(acc[mf][nf], al[mf], bh);
                    mma_bf16(acc[mf][nf], ah[mf], bl);
                }
            }
        }
    };

    cpB(0, 0); CP_COMMIT();
    ldgA(0); stsA(0);
    for (int kc = 0; kc < NC; kc++) {
        const int bf = kc & 1;
        const bool nxt = (kc + 1 < NC);
        if (nxt) {
            cpB((kc + 1) * 32, bf ^ 1); CP_COMMIT();
            ldgA((kc + 1) * 32);
            CP_WAIT1();
        } else {
            CP_WAIT0();
        }
        __syncthreads();
        domma(bf);
        if (nxt) stsA(bf ^ 1);
        __syncthreads();
    }

#pragma unroll
    for (int mf = 0; mf < 2; mf++)
#pragma unroll
        for (int nf = 0; nf < 8; nf++)
#pragma unroll
            for (int e = 0; e < 4; e++) {
                int row = wm * 32 + mf * 16 + lr + (e >> 1) * 8;
                int oc = wn * 64 + nf * 8 + lc * 2 + (e & 1);
                float v = acc[mf][nf][e] + biasS[oc];
                if (RELU) v = fmaxf(v, 0.f);
                size_t addr;
                if (MODE == 0) {
                    int px = pxbase + row;
                    addr = ((size_t)(b * 128 + oc) * 64 + (px >> 6)) * 64 + (px & 63);
                } else {
                    int oh = (1 - ohp) + 2 * (j0 + (row >> 6));
                    int ow = (1 - owp) + 2 * (row & 63);
                    addr = ((size_t)(b * 128 + oc) * 128 + oh) * 128 + ow;
                }
                if (OUTMODE == 0) {
                    outf[addr] = v;
                } else {
                    __nv_bfloat16 h = __float2bfloat16(v);
                    outh[addr] = h;
                    outl[addr] = __float2bfloat16(v - __bfloat162float(h));
                }
            }
}

// =====================================================================
// weight split kernels (decoder only)
// =====================================================================
__global__ void wsplit(const float* __restrict__ w, __nv_bfloat16* __restrict__ wh,
                       __nv_bfloat16* __restrict__ wl, int n)
{
    int i = blockIdx.x * 256 + threadIdx.x;
    if (i >= n) return;
    float x = w[i];
    __nv_bfloat16 h = __float2bfloat16(x);
    wh[i] = h;
    wl[i] = __float2bfloat16(x - __bfloat162float(h));
}

__global__ void pack_wt2(const float* __restrict__ w, __nv_bfloat16* __restrict__ wh,
                         __nv_bfloat16* __restrict__ wl)
{
    int i = blockIdx.x * 256 + threadIdx.x;      // over 4*128*512
    int cls = i >> 16;
    int oc = (i >> 9) & 127;
    int r = i & 511;
    int ohp = cls >> 1, owp = cls & 1;
    int ic = r >> 2, th = (r >> 1) & 1, tw = r & 1;
    float x = w[((ic * 128 + oc) * 4 + ohp + 2 * th) * 4 + owp + 2 * tw];
    __nv_bfloat16 h = __float2bfloat16(x);
    wh[i] = h;
    wl[i] = __float2bfloat16(x - __bfloat162float(h));
}

// =====================================================================
// row squared-norm (exact R1 arithmetic)
// =====================================================================
__global__ void rownorm_kernel(const float* __restrict__ v, float* __restrict__ outn, int rows)
{
    int warp = threadIdx.x >> 5, lane = threadIdx.x & 31;
    int n = blockIdx.x * 8 + warp;
    if (n >= rows) return;
    const float* p = v + (size_t)n * 256;
    float s = 0.f;
#pragma unroll
    for (int k = 0; k < 8; k++) { float x = p[lane + 32 * k]; s = fmaf(x, x, s); }
#pragma unroll
    for (int off = 16; off; off >>= 1) s += __shfl_down_sync(0xffffffffu, s, off);
    if (lane == 0) outn[n] = s;
}

__global__ void zero_commit_kernel(float* c) { *c = 0.f; }

// =====================================================================
// VQ pack kernels (exact R3)
// =====================================================================
__global__ void pack_z_bf16(const float* __restrict__ z, __nv_bfloat16* __restrict__ A)
{
    int i = blockIdx.x * 256 + threadIdx.x;
    int q = i >> 8, k = i & 255;
    float x = z[i];
    __nv_bfloat16 h = __float2bfloat16(x);
    __nv_bfloat16 l = __float2bfloat16(x - __bfloat162float(h));
    size_t base = (size_t)q * KP;
    A[base + k] = h;
    A[base + 256 + k] = l;
    A[base + 512 + k] = h;
}

__global__ void pack_c_bf16(const float* __restrict__ c, __nv_bfloat16* __restrict__ B)
{
    int i = blockIdx.x * 256 + threadIdx.x;
    int q = i >> 8, k = i & 255;
    float x = c[i];
    __nv_bfloat16 h = __float2bfloat16(x);
    __nv_bfloat16 l = __float2bfloat16(x - __bfloat162float(h));
    size_t base = (size_t)q * KP;
    B[base + k] = h;
    B[base + 256 + k] = h;
    B[base + 512 + k] = l;
}

// =====================================================================
// VQ GEMM + fused argmin (exact R3/R6 — fastest passing version)
// =====================================================================
#define LDA 40
#define BUFB (128 * LDA * 2)

__global__ __launch_bounds__(256)
void vq_mma(const __nv_bfloat16* __restrict__ Apk, const __nv_bfloat16* __restrict__ Bpk,
            const float* __restrict__ znorm, const float* __restrict__ cnorm,
            float* __restrict__ bv8, int* __restrict__ bi8)
{
    __shared__ __align__(16) __nv_bfloat16 sA[2][128 * LDA];
    __shared__ __align__(16) __nv_bfloat16 sB[2][128 * LDA];
    __shared__ float znS[128], cnS[128];
    __shared__ float redV[2][128];
    __shared__ int   redI[2][128];

    const int tid = threadIdx.x;
    const int lane = tid & 31, wid = tid >> 5;
    const int wm = wid & 3, wn = wid >> 2;
    const int lr = lane >> 2, lc = lane & 3;
    const int qbase = blockIdx.x * 128;
    const int gbase = blockIdx.y * 1024;

    if (tid < 128) znS[tid] = znorm[qbase + tid];
    __syncthreads();
    float znr[4];
#pragma unroll
    for (int s = 0; s < 4; s++)
        znr[s] = znS[wm * 32 + (s >> 1) * 16 + lr + (s & 1) * 8];

    float bestv[4] = {3.4e38f, 3.4e38f, 3.4e38f, 3.4e38f};
    int   besti[4] = {0, 0, 0, 0};

    float acc[2][8][4];
#pragma unroll
    for (int mf = 0; mf < 2; mf++)
#pragma unroll
        for (int nf = 0; nf < 8; nf++)
#pragma unroll
            for (int e = 0; e < 4; e++) acc[mf][nf][e] = 0.f;

    const int srow = tid >> 1;
    const __nv_bfloat16* asrc = Apk + (size_t)(qbase + srow) * KP + (tid & 1) * 16;
    const uint32_t saA = s2u(sA) + srow * (LDA * 2) + (tid & 1) * 32;
    const uint32_t saB = s2u(sB) + srow * (LDA * 2) + (tid & 1) * 32;

    for (int nt = 0; nt < 8; nt++) {
        const __nv_bfloat16* bsrc =
            Bpk + (size_t)(gbase + nt * 128 + srow) * KP + (tid & 1) * 16;
        if (tid < 128) cnS[tid] = cnorm[gbase + nt * 128 + tid];

        CP16(saA, asrc);      CP16(saA + 16, asrc + 8);
        CP16(saB, bsrc);      CP16(saB + 16, bsrc + 8);
        CP_COMMIT();

        for (int kc = 0; kc < 24; kc++) {
            if (kc + 1 < 24) {
                const uint32_t nb = (uint32_t)((kc + 1) & 1) * BUFB;
                const __nv_bfloat16* a2 = asrc + (kc + 1) * 32;
                const __nv_bfloat16* b2 = bsrc + (kc + 1) * 32;
                CP16(saA + nb, a2);      CP16(saA + nb + 16, a2 + 8);
                CP16(saB + nb, b2);      CP16(saB + nb + 16, b2 + 8);
                CP_COMMIT();
                CP_WAIT1();
            } else {
                CP_WAIT0();
            }
            __syncthreads();

            const int buf = kc & 1;
#pragma unroll
            for (int ks = 0; ks < 2; ks++) {
                const int k0 = ks * 16 + lc * 2;
                uint32_t a[2][4], b[8][2];
#pragma unroll
                for (int mf = 0; mf < 2; mf++) {
                    int r = wm * 32 + mf * 16 + lr;
                    a[mf][0] = *(const uint32_t*)&sA[buf][r * LDA + k0];
                    a[mf][1] = *(const uint32_t*)&sA[buf][(r + 8) * LDA + k0];
                    a[mf][2] = *(const uint32_t*)&sA[buf][r * LDA + k0 + 8];
                    a[mf][3] = *(const uint32_t*)&sA[buf][(r + 8) * LDA + k0 + 8];
                }
#pragma unroll
                for (int nf = 0; nf < 8; nf++) {
                    int cr = wn * 64 + nf * 8 + lr;
                    b[nf][0] = *(const uint32_t*)&sB[buf][cr * LDA + k0];
                    b[nf][1] = *(const uint32_t*)&sB[buf][cr * LDA + k0 + 8];
                }
#pragma unroll
                for (int mf = 0; mf < 2; mf++)
#pragma unroll
                    for (int nf = 0; nf < 8; nf++)
                        mma_bf16(acc[mf][nf], a[mf], b[nf]);
            }
            __syncthreads();
        }

#pragma unroll
        for (int mf = 0; mf < 2; mf++)
#pragma unroll
            for (int nf = 0; nf < 8; nf++)
#pragma unroll
                for (int e = 0; e < 4; e++) {
                    int h = e >> 1;
                    int col = wn * 64 + nf * 8 + lc * 2 + (e & 1);
                    int slot = mf * 2 + h;
                    float t = znr[slot] + cnS[col];
                    float s = fmaf(-2.f, acc[mf][nf][e], t);
                    int code = gbase + nt * 128 + col;
                    if (s < bestv[slot]) { bestv[slot] = s; besti[slot] = code; }
                    acc[mf][nf][e] = 0.f;
                }
        __syncthreads();
    }

#pragma unroll
    for (int s = 0; s < 4; s++) {
        float v = bestv[s]; int ix = besti[s];
#pragma unroll
        for (int off = 1; off <= 2; off <<= 1) {
            float ov = __shfl_xor_sync(0xffffffffu, v, off);
            int   oi = __shfl_xor_sync(0xffffffffu, ix, off);
            if (ov < v || (ov == v && oi < ix)) { v = ov; ix = oi; }
        }
        if (lc == 0) {
            int row = wm * 32 + (s >> 1) * 16 + lr + (s & 1) * 8;
            redV[wn][row] = v; redI[wn][row] = ix;
        }
    }
    __syncthreads();
    if (tid < 128) {
        float v = redV[0][tid]; int ix = redI[0][tid];
        float v1 = redV[1][tid]; int i1 = redI[1][tid];
        if (v1 < v || (v1 == v && i1 < ix)) { v = v1; ix = i1; }
        bv8[blockIdx.y * NQ + qbase + tid] = v;
        bi8[blockIdx.y * NQ + qbase + tid] = ix;
    }
}

__global__ void vq_combine8(const float* __restrict__ bv8, const int* __restrict__ bi8,
                            int* __restrict__ idx)
{
    int q = blockIdx.x * 256 + threadIdx.x;
    if (q >= NQ) return;
    float v = bv8[q]; int ix = bi8[q];
#pragma unroll
    for (int g = 1; g < 8; g++) {
        float v2 = bv8[g * NQ + q];
        int   i2 = bi8[g * NQ + q];
        if (v2 < v || (v2 == v && i2 < ix)) { v = v2; ix = i2; }
    }
    idx[q] = ix;
}

// =====================================================================
// gather quant = codebook[idx], commit loss
// =====================================================================
__global__ __launch_bounds__(256)
void gather_commit(const float* __restrict__ cb, const float* __restrict__ z,
                   const int* __restrict__ idx, float* __restrict__ quant,
                   float* __restrict__ commit)
{
    int n = blockIdx.x;
    int t = threadIdx.x;
    int id = idx[n];
    float q = cb[(size_t)id * 256 + t];
    float zv = z[(size_t)n * 256 + t];
    quant[(size_t)n * 256 + t] = q;
    float d = q - zv; d *= d;
#pragma unroll
    for (int off = 16; off; off >>= 1) d += __shfl_down_sync(0xffffffffu, d, off);
    __shared__ float wsum[8];
    int warp = t >> 5, lane = t & 31;
    if (lane == 0) wsum[warp] = d;
    __syncthreads();
    if (t == 0) {
        float s = 0.f;
#pragma unroll
        for (int w = 0; w < 8; w++) s += wsum[w];
        atomicAdd(commit, s);
    }
}

// =====================================================================
// Final transposed conv (128 -> 3 channels) straight into d_out.
// ic loop unrolled x4 for MLP (fmaf chains keep identical order).
// =====================================================================
__global__ __launch_bounds__(256)
void convt_out3(const float* __restrict__ in, const float* __restrict__ w,
                const float* __restrict__ bias, float* __restrict__ out)
{
    __shared__ float ws[128 * 3 * 16];
    for (int i = threadIdx.x; i < 6144; i += 256) ws[i] = w[i];
    __syncthreads();

    int b = blockIdx.y, oh = blockIdx.x, ow = threadIdx.x;
    int ih0 = (oh + 1) >> 1, kh0 = (oh + 1) & 1;
    int iw0 = (ow + 1) >> 1, kw0 = (ow + 1) & 1;

    float acc0 = 0.f, acc1 = 0.f, acc2 = 0.f;
#pragma unroll 4
    for (int ic = 0; ic < 128; ic++) {
        const float* inp = in + ((size_t)(b * 128 + ic)) * 128 * 128;
        const float* wp = ws + ic * 48;
#pragma unroll
        for (int th = 0; th < 2; th++) {
            int ih = ih0 - th;
            if ((unsigned)ih < 128u) {
                int kh = kh0 + 2 * th;
#pragma unroll
                for (int tw = 0; tw < 2; tw++) {
                    int iw = iw0 - tw;
                    if ((unsigned)iw < 128u) {
                        int kw = kw0 + 2 * tw;
                        float v = inp[ih * 128 + iw];
                        int wk = kh * 4 + kw;
                        acc0 = fmaf(v, wp[wk], acc0);
                        acc1 = fmaf(v, wp[16 + wk], acc1);
                        acc2 = fmaf(v, wp[32 + wk], acc2);
                    }
                }
            }
        }
    }
    size_t ob = ((size_t)(b * 3) * 256 + oh) * 256 + ow;
    out[ob]          = acc0 + bias[0];
    out[ob + 65536]  = acc1 + bias[1];
    out[ob + 131072] = acc2 + bias[2];
}

__global__ void pack_kernel(float* __restrict__ out, const float* __restrict__ commit,
                            const int* __restrict__ idx)
{
    int i = blockIdx.x * 256 + threadIdx.x;
    if (i == 0) out[786432] = (*commit) * (1.f / 4194304.f);
    if (i < NQ) out[786433 + i] = (float)idx[i];
}

// =====================================================================
// host launcher
// =====================================================================
#define CMMA_SMEM 82432

extern "C" void kernel_launch(void* const* d_in, const int* in_sizes, int n_in,
                              void* d_out, int out_size)
{
    const float* x        = (const float*)d_in[0];
    const float* enc_w1   = (const float*)d_in[1];
    const float* enc_b1   = (const float*)d_in[2];
    const float* enc_w2   = (const float*)d_in[3];
    const float* enc_b2   = (const float*)d_in[4];
    const float* enc_w3   = (const float*)d_in[5];
    const float* enc_b3   = (const float*)d_in[6];
    const float* qconv_w  = (const float*)d_in[7];
    const float* qconv_b  = (const float*)d_in[8];
    const float* codebook = (const float*)d_in[9];
    const float* pqconv_w = (const float*)d_in[10];
    const float* pqconv_b = (const float*)d_in[11];
    const float* dec_w1   = (const float*)d_in[12];
    const float* dec_b1   = (const float*)d_in[13];
    const float* dect_w2  = (const float*)d_in[14];
    const float* dect_b2  = (const float*)d_in[15];
    const float* dect_w3  = (const float*)d_in[16];
    const float* dect_b3  = (const float*)d_in[17];
    float* out = (float*)d_out;

    float *h1, *h2, *h3, *z, *quant, *d2, *znorm, *cnorm, *commit, *bv8;
    float *w2t, *w3t, *wqt, *wpt;
    __nv_bfloat16 *qh, *ql, *d1h, *d1l, *apk, *bpk;
    __nv_bfloat16 *wd1h, *wd1l, *wt2h, *wt2l;
    int *idx, *bi8;
    cudaGetSymbolAddress((void**)&h1, g_h1);
    cudaGetSymbolAddress((void**)&h2, g_h2);
    cudaGetSymbolAddress((void**)&h3, g_h3);
    cudaGetSymbolAddress((void**)&z, g_z);
    cudaGetSymbolAddress((void**)&quant, g_quant);
    cudaGetSymbolAddress((void**)&qh, g_qh);
    cudaGetSymbolAddress((void**)&ql, g_ql);
    cudaGetSymbolAddress((void**)&d1h, g_d1h);
    cudaGetSymbolAddress((void**)&d1l, g_d1l);
    cudaGetSymbolAddress((void**)&d2, g_d2);
    cudaGetSymbolAddress((void**)&znorm, g_znorm);
    cudaGetSymbolAddress((void**)&cnorm, g_cnorm);
    cudaGetSymbolAddress((void**)&idx, g_idx);
    cudaGetSymbolAddress((void**)&commit, g_commit);
    cudaGetSymbolAddress((void**)&apk, g_apk);
    cudaGetSymbolAddress((void**)&bpk, g_bpk);
    cudaGetSymbolAddress((void**)&bv8, g_bv8);
    cudaGetSymbolAddress((void**)&bi8, g_bi8);
    cudaGetSymbolAddress((void**)&wd1h, g_wd1h); cudaGetSymbolAddress((void**)&wd1l, g_wd1l);
    cudaGetSymbolAddress((void**)&wt2h, g_wt2h); cudaGetSymbolAddress((void**)&wt2l, g_wt2l);
    cudaGetSymbolAddress((void**)&w2t, g_w2t);   cudaGetSymbolAddress((void**)&w3t, g_w3t);
    cudaGetSymbolAddress((void**)&wqt, g_wqt);   cudaGetSymbolAddress((void**)&wpt, g_wpt);

    cudaFuncSetAttribute(conv_mma<0,3,1,1,true ,1>, cudaFuncAttributeMaxDynamicSharedMemorySize, CMMA_SMEM);
    cudaFuncSetAttribute(conv_mma<1,4,2,1,true ,0>, cudaFuncAttributeMaxDynamicSharedMemorySize, CMMA_SMEM);

    // weight prep: fp32 chunk-major transposes + decoder splits + VQ codebook
    wtrans<<<1024, 256>>>(enc_w2, w2t, 2048, 128);
    wtrans<<<576, 256>>>(enc_w3, w3t, 1152, 128);
    wtrans<<<128, 256>>>(qconv_w, wqt, 128, 256);
    wtrans<<<128, 256>>>(pqconv_w, wpt, 256, 128);
    wsplit<<<576, 256>>>(dec_w1, wd1h, wd1l, 128 * 1152);
    pack_wt2<<<1024, 256>>>(dect_w2, wt2h, wt2l);
    pack_c_bf16<<<KCB, 256>>>(codebook, bpk);
    rownorm_kernel<<<1024, 256>>>(codebook, cnorm, KCB);
    zero_commit_kernel<<<1, 1>>>(commit);

    // encoder — enc1 dedicated; enc2/enc3/qconv on 4-stage async FFMA2
    conv_enc1<<<dim3(128,4),256>>>(x, enc_w1, enc_b1, h1);
    conv_async<4,2,1,true ,0,0><<<dim3(64,1,4),256>>>(h1, w2t, enc_b2, h2, nullptr, nullptr,
                                                      128,128, 128,128,  64, 64, 6);
    conv_async<3,1,1,false,0,0><<<dim3(64,1,4),256>>>(h2, w3t, enc_b3, h3, nullptr, nullptr,
                                                      128,128,  64, 64,  64, 64, 6);
    conv_async<1,1,0,false,0,1><<<dim3(64,2,4),256>>>(h3, wqt, qconv_b, z, nullptr, nullptr,
                                                      128,256,  64, 64,  64, 64, 6);

    // quantize — exact R3/R6 path
    pack_z_bf16<<<NQ, 256>>>(z, apk);
    rownorm_kernel<<<2048, 256>>>(z, znorm, NQ);
    vq_mma<<<dim3(128, 8), 256>>>(apk, bpk, znorm, cnorm, bv8, bi8);
    vq_combine8<<<64, 256>>>(bv8, bi8, idx);
    gather_commit<<<NQ, 256>>>(codebook, z, idx, quant, commit);

    // decoder — tensor-core bf16-split
    conv_async<1,1,0,false,1,2><<<dim3(64,1,4),256>>>(quant, wpt, pqconv_b, nullptr, qh, ql,
                                                      256, 128, 64,64, 64,64, 6);
    conv_mma<0,3,1,1,true ,1><<<dim3(32,1,4),256,CMMA_SMEM>>>(qh, ql, wd1h, wd1l, dec_b1,
                                                     nullptr, d1h, d1l, 128, 64, 64, 1152);
    conv_mma<1,4,2,1,true ,0><<<dim3(32,4,4),256,CMMA_SMEM>>>(d1h, d1l, wt2h, wt2l, dect_b2,
                                                     d2, nullptr, nullptr, 128, 64, 64, 512);
    convt_out3<<<dim3(256,4),256>>>(d2, dect_w3, dect_b3, out);

    pack_kernel<<<64, 256>>>(out, commit, idx);

    (void)in_sizes; (void)n_in; (void)out_size;
}

// round 14
// speedup vs baseline: 1.1581x; 1.0295x over previous
#include <cuda_runtime.h>
#include <cuda_bf16.h>
#include <cstdint>

// ---------------- problem constants ----------------
#define BATCH 4
#define NQ    16384
#define EDIM  256
#define KCB   8192
#define KP    768            // packed K' = 3 * 256 for VQ GEMM

// ---------------- scratch (static device memory; no allocation) ----------------
__device__ float g_h1[4 * 128 * 128 * 128];
__device__ float g_h2[4 * 128 * 64 * 64];
__device__ float g_h3[4 * 128 * 64 * 64];
__device__ float g_z[NQ * EDIM];
__device__ float g_quant[NQ * EDIM];
__device__ __nv_bfloat16 g_qh[4 * 128 * 64 * 64];
__device__ __nv_bfloat16 g_ql[4 * 128 * 64 * 64];
__device__ __nv_bfloat16 g_d1h[4 * 128 * 64 * 64];
__device__ __nv_bfloat16 g_d1l[4 * 128 * 64 * 64];
__device__ float g_d2[4 * 128 * 128 * 128];
__device__ float g_znorm[NQ];
__device__ float g_cnorm[KCB];
__device__ int   g_idx[NQ];
__device__ float g_commit;
// VQ packed split buffers
__device__ __nv_bfloat16 g_apk[(size_t)NQ * KP];
__device__ __nv_bfloat16 g_bpk[(size_t)KCB * KP];
__device__ float g_bv8[8 * NQ];
__device__ int   g_bi8[8 * NQ];
// pre-split decoder weights
__device__ __nv_bfloat16 g_wd1h[128 * 1152], g_wd1l[128 * 1152];
__device__ __nv_bfloat16 g_wt2h[4 * 128 * 512], g_wt2l[4 * 128 * 512];
// chunk-major transposed fp32 weights for async FFMA convs
__device__ float g_w2t[128 * 2048];
__device__ float g_w3t[128 * 1152];
__device__ float g_wqt[256 * 128];
__device__ float g_wpt[128 * 256];

__device__ __forceinline__ uint32_t s2u(const void* p)
{
    uint32_t a;
    asm("{ .reg .u64 t; cvta.to.shared.u64 t, %1; cvt.u32.u64 %0, t; }" : "=r"(a) : "l"(p));
    return a;
}

#define CP16(dst, src) \
    asm volatile("cp.async.cg.shared.global [%0], [%1], 16;" :: "r"(dst), "l"(src) : "memory")
#define CP4Z(dst, src, sz) \
    asm volatile("cp.async.ca.shared.global [%0], [%1], 4, %2;" :: "r"(dst), "l"(src), "r"(sz) : "memory")
#define CP_COMMIT() asm volatile("cp.async.commit_group;" ::: "memory")
#define CP_WAIT2()  asm volatile("cp.async.wait_group 2;" ::: "memory")
#define CP_WAIT1()  asm volatile("cp.async.wait_group 1;" ::: "memory")
#define CP_WAIT0()  asm volatile("cp.async.wait_group 0;" ::: "memory")

__device__ __forceinline__ void mma_bf16(float* c, const uint32_t* a, const uint32_t* b)
{
    asm volatile(
        "mma.sync.aligned.m16n8k16.row.col.f32.bf16.bf16.f32 "
        "{%0,%1,%2,%3}, {%4,%5,%6,%7}, {%8,%9}, {%0,%1,%2,%3};"
        : "+f"(c[0]), "+f"(c[1]), "+f"(c[2]), "+f"(c[3])
        : "r"(a[0]), "r"(a[1]), "r"(a[2]), "r"(a[3]), "r"(b[0]), "r"(b[1]));
}

__device__ __forceinline__ void ffma2(uint64_t& acc, uint64_t wp, uint64_t xx)
{
    asm("fma.rn.f32x2 %0, %1, %2, %0;" : "+l"(acc) : "l"(wp), "l"(xx));
}

// =====================================================================
// Weight transpose into chunk-major [ocTile][chunk][r(16)][ocl(128)].
// =====================================================================
__global__ void wtrans(const float* __restrict__ w, float* __restrict__ wt, int R, int Cout)
{
    int i = blockIdx.x * 256 + threadIdx.x;
    if (i >= Cout * R) return;
    int ocl = i & 127;
    int rest = i >> 7;
    int r = rest & 15;
    int chunkAll = rest >> 4;
    int NC = R >> 4;
    int ot = chunkAll / NC;
    int c = chunkAll - ot * NC;
    wt[i] = w[(size_t)(ot * 128 + ocl) * R + c * 16 + r];
}

// =====================================================================
// Dedicated enc1 kernel (R9 — passing; h1 bitwise identical)
// =====================================================================
__global__ __launch_bounds__(256)
void conv_enc1(const float* __restrict__ x, const float* __restrict__ w,
               const float* __restrict__ bias, float* __restrict__ out)
{
    __shared__ __align__(16) float ws[48][128];
    __shared__ __align__(16) float xs[48][128];

    const int tid = threadIdx.x;
    const int oh = blockIdx.x;
    const int b = blockIdx.y;

#pragma unroll
    for (int i = 0; i < 24; i++) {
        int idx = tid + i * 256;
        int r = idx >> 7, oc = idx & 127;
        ws[r][oc] = w[oc * 48 + r];
    }
#pragma unroll
    for (int i = 0; i < 24; i++) {
        int idx = tid + i * 256;
        int r = idx >> 7, p = idx & 127;
        int ic = r >> 4, kh = (r >> 2) & 3, kw = r & 3;
        int ih = oh * 2 + kh - 1;
        int iw = p * 2 + kw - 1;
        float v = 0.f;
        if ((unsigned)ih < 256u && (unsigned)iw < 256u)
            v = x[((size_t)(b * 3 + ic) * 256 + ih) * 256 + iw];
        xs[r][p] = v;
    }
    __syncthreads();

    const int tx = tid & 15;
    const int ty = tid >> 4;
    const uint32_t wsb = s2u(ws) + ty * 32;

    uint64_t acc2[4][8];
#pragma unroll
    for (int pq = 0; pq < 4; pq++)
#pragma unroll
        for (int i = 0; i < 8; i++) acc2[pq][i] = 0ull;

#pragma unroll 4
    for (int k = 0; k < 48; k++) {
        uint64_t wp0, wp1, wp2, wp3;
        asm("ld.shared.v2.u64 {%0,%1}, [%2];"
            : "=l"(wp0), "=l"(wp1) : "r"(wsb + (uint32_t)(k * 512)));
        asm("ld.shared.v2.u64 {%0,%1}, [%2];"
            : "=l"(wp2), "=l"(wp3) : "r"(wsb + (uint32_t)(k * 512 + 16)));
        float4 xv0 = *reinterpret_cast<const float4*>(&xs[k][tx * 8]);
        float4 xv1 = *reinterpret_cast<const float4*>(&xs[k][tx * 8 + 4]);
        uint64_t xx[8];
        asm("mov.b64 %0, {%1,%1};" : "=l"(xx[0]) : "f"(xv0.x));
        asm("mov.b64 %0, {%1,%1};" : "=l"(xx[1]) : "f"(xv0.y));
        asm("mov.b64 %0, {%1,%1};" : "=l"(xx[2]) : "f"(xv0.z));
        asm("mov.b64 %0, {%1,%1};" : "=l"(xx[3]) : "f"(xv0.w));
        asm("mov.b64 %0, {%1,%1};" : "=l"(xx[4]) : "f"(xv1.x));
        asm("mov.b64 %0, {%1,%1};" : "=l"(xx[5]) : "f"(xv1.y));
        asm("mov.b64 %0, {%1,%1};" : "=l"(xx[6]) : "f"(xv1.z));
        asm("mov.b64 %0, {%1,%1};" : "=l"(xx[7]) : "f"(xv1.w));
#pragma unroll
        for (int i = 0; i < 8; i++) {
            ffma2(acc2[0][i], wp0, xx[i]);
            ffma2(acc2[1][i], wp1, xx[i]);
            ffma2(acc2[2][i], wp2, xx[i]);
            ffma2(acc2[3][i], wp3, xx[i]);
        }
    }

#pragma unroll
    for (int pq = 0; pq < 4; pq++)
#pragma unroll
        for (int half = 0; half < 2; half++) {
            int oc = ty * 8 + 2 * pq + half;
            float bv = bias[oc];
            float* op = out + ((size_t)(b * 128 + oc) * 128 + oh) * 128 + tx * 8;
#pragma unroll
            for (int i = 0; i < 8; i++) {
                uint32_t bits = half ? (uint32_t)(acc2[pq][i] >> 32)
                                     : (uint32_t)(acc2[pq][i] & 0xffffffffull);
                float v = __uint_as_float(bits) + bv;
                op[i] = fmaxf(v, 0.f);
            }
        }
}

// =====================================================================
// FFMA2 implicit-GEMM conv with cp.async 4-STAGE pipeline (R13 — passing)
// =====================================================================
template<int KK, int S, int P, bool RELU, int INL, int OUTL>
__global__ __launch_bounds__(256)
void conv_async(const float* __restrict__ in, const float* __restrict__ wt,
                const float* __restrict__ bias, float* __restrict__ out,
                __nv_bfloat16* __restrict__ outh, __nv_bfloat16* __restrict__ outl,
                int Cin, int Cout, int Hin, int Win, int Hout, int Wout,
                int woutShift)
{
    const int R = Cin * KK * KK;
    const int NC = R >> 4;
    const int b = blockIdx.z;
    const int ot = blockIdx.y;
    const int oc0 = ot * 128;
    const int pxbase = blockIdx.x * 64;

    __shared__ __align__(16) float ws[4][16][128];
    __shared__ __align__(16) float xs[4][16][68];

    const int tid = threadIdx.x;
    const int tx = tid & 15;
    const int ty = tid >> 4;

    const uint32_t wsb0 = s2u(ws);
    const uint32_t xsb0 = s2u(xs);
    const uint32_t wdst = wsb0 + (uint32_t)tid * 32;
    const float* wsrc_base = wt + (size_t)ot * ((size_t)NC * 2048) + tid * 8;

    uint64_t acc2[4][4];
#pragma unroll
    for (int p = 0; p < 4; p++)
#pragma unroll
        for (int i = 0; i < 4; i++) acc2[p][i] = 0ull;

    auto stage = [&](int c, int bf) {
        const float* wsrc = wsrc_base + (size_t)c * 2048;
        uint32_t wd = wdst + (uint32_t)bf * 8192;
        CP16(wd, wsrc);
        CP16(wd + 16, wsrc + 4);
#pragma unroll
        for (int i2 = 0; i2 < 4; i2++) {
            int li = tid + i2 * 256;
            int r, p;
            if (INL == 1) { r = li & 15; p = li >> 4; }
            else          { r = li >> 6; p = li & 63; }
            int rr = c * 16 + r;
            const float* src = in;
            int sz = 0;
            if (INL == 1) {
                int n = b * (Hout * Wout) + pxbase + p;
                src = in + (size_t)n * Cin + rr;
                sz = 4;
            } else {
                int ic = rr / (KK * KK);
                int kr = rr - ic * KK * KK;
                int kh = kr / KK, kw = kr - kh * KK;
                int px = pxbase + p;
                int oh = px >> woutShift;
                int ow = px & (Wout - 1);
                int ih = oh * S + kh - P;
                int iw = ow * S + kw - P;
                if ((unsigned)ih < (unsigned)Hin && (unsigned)iw < (unsigned)Win) {
                    src = in + ((size_t)(b * Cin + ic) * Hin + ih) * Win + iw;
                    sz = 4;
                }
            }
            uint32_t xd = xsb0 + (uint32_t)bf * 4352 + (uint32_t)((r * 68 + p) * 4);
            CP4Z(xd, src, sz);
        }
    };

    stage(0, 0); CP_COMMIT();
    if (NC > 1) { stage(1, 1); CP_COMMIT(); }

    for (int c = 0; c < NC; c++) {
        const int bf = c & 3;
        if (c + 2 < NC) {
            stage(c + 2, (c + 2) & 3); CP_COMMIT();
            CP_WAIT2();
        } else if (c + 1 < NC) {
            CP_WAIT1();
        } else {
            CP_WAIT0();
        }
        __syncthreads();

        const uint32_t wsb = wsb0 + (uint32_t)bf * 8192 + ty * 32;
        const float (*xsb)[68] = xs[bf];
#pragma unroll
        for (int k = 0; k < 16; k++) {
            float4 xv = *reinterpret_cast<const float4*>(&xsb[k][tx * 4]);
            uint64_t wp0, wp1, wp2, wp3;
            asm("ld.shared.v2.u64 {%0,%1}, [%2];"
                : "=l"(wp0), "=l"(wp1) : "r"(wsb + (uint32_t)(k * 512)));
            asm("ld.shared.v2.u64 {%0,%1}, [%2];"
                : "=l"(wp2), "=l"(wp3) : "r"(wsb + (uint32_t)(k * 512 + 16)));
            uint64_t xx0, xx1, xx2, xx3;
            asm("mov.b64 %0, {%1,%1};" : "=l"(xx0) : "f"(xv.x));
            asm("mov.b64 %0, {%1,%1};" : "=l"(xx1) : "f"(xv.y));
            asm("mov.b64 %0, {%1,%1};" : "=l"(xx2) : "f"(xv.z));
            asm("mov.b64 %0, {%1,%1};" : "=l"(xx3) : "f"(xv.w));
            ffma2(acc2[0][0], wp0, xx0); ffma2(acc2[0][1], wp0, xx1);
            ffma2(acc2[0][2], wp0, xx2); ffma2(acc2[0][3], wp0, xx3);
            ffma2(acc2[1][0], wp1, xx0); ffma2(acc2[1][1], wp1, xx1);
            ffma2(acc2[1][2], wp1, xx2); ffma2(acc2[1][3], wp1, xx3);
            ffma2(acc2[2][0], wp2, xx0); ffma2(acc2[2][1], wp2, xx1);
            ffma2(acc2[2][2], wp2, xx2); ffma2(acc2[2][3], wp2, xx3);
            ffma2(acc2[3][0], wp3, xx0); ffma2(acc2[3][1], wp3, xx1);
            ffma2(acc2[3][2], wp3, xx2); ffma2(acc2[3][3], wp3, xx3);
        }
    }

#pragma unroll
    for (int p = 0; p < 4; p++)
#pragma unroll
        for (int half = 0; half < 2; half++) {
            int j = 2 * p + half;
            int oc = oc0 + ty * 8 + j;
            float bv = bias[oc];
#pragma unroll
            for (int i = 0; i < 4; i++) {
                uint32_t bits = half ? (uint32_t)(acc2[p][i] >> 32)
                                     : (uint32_t)(acc2[p][i] & 0xffffffffull);
                float v = __uint_as_float(bits) + bv;
                if (RELU) v = fmaxf(v, 0.f);
                if (OUTL == 1) {
                    size_t n = (size_t)(b * (Hout * Wout) + pxbase + tx * 4 + i);
                    out[n * Cout + oc] = v;
                } else {
                    size_t addr = (size_t)(b * Cout + oc) * (Hout * Wout) + pxbase + tx * 4 + i;
                    if (OUTL == 0) {
                        out[addr] = v;
                    } else {
                        __nv_bfloat16 h = __float2bfloat16(v);
                        outh[addr] = h;
                        outl[addr] = __float2bfloat16(v - __bfloat162float(h));
                    }
                }
            }
        }
}

// =====================================================================
// Tensor-core implicit-GEMM conv, bf16 3-term split — DECODER ONLY.
// (unchanged — passing)
// =====================================================================
#define CLDA 40
#define ABUF 5120

template<int MODE, int KK, int S, int P, bool RELU, int OUTMODE>
__global__ __launch_bounds__(256)
void conv_mma(const __nv_bfloat16* __restrict__ xh, const __nv_bfloat16* __restrict__ xl,
              const __nv_bfloat16* __restrict__ wh_g, const __nv_bfloat16* __restrict__ wl_g,
              const float* __restrict__ bias,
              float* __restrict__ outf, __nv_bfloat16* __restrict__ outh,
              __nv_bfloat16* __restrict__ outl,
              int Cin, int Hin, int Win, int R)
{
    extern __shared__ __align__(16) char sm[];
    __nv_bfloat16* sA_h = (__nv_bfloat16*)(sm);
    __nv_bfloat16* sA_l = (__nv_bfloat16*)(sm + 20480);
    __nv_bfloat16* sB_h = (__nv_bfloat16*)(sm + 40960);
    __nv_bfloat16* sB_l = (__nv_bfloat16*)(sm + 61440);
    float* biasS = (float*)(sm + 81920);

    const int tid = threadIdx.x;
    const int lane = tid & 31, wid = tid >> 5;
    const int wm = wid & 3, wn = wid >> 2;
    const int lr = lane >> 2, lc = lane & 3;
    const int b = blockIdx.z;

    int pxbase = 0, j0 = 0, ohp = 0, owp = 0;
    const __nv_bfloat16* wh = wh_g;
    const __nv_bfloat16* wl = wl_g;
    if (MODE == 1) {
        j0 = blockIdx.x * 2;
        int cls = blockIdx.y;
        ohp = cls >> 1; owp = cls & 1;
        wh = wh_g + cls * (128 * 512);
        wl = wl_g + cls * (128 * 512);
    } else {
        pxbase = blockIdx.x * 128;
    }

    if (tid < 128) biasS[tid] = bias[tid];

    const int NC = R >> 5;

    const int boc = tid >> 1;
    const uint32_t sbBh = s2u(sB_h), sbBl = s2u(sB_l);
    const uint32_t bOff = (uint32_t)(boc * 80 + (tid & 1) * 32);
    const size_t bSrc = (size_t)boc * R + (tid & 1) * 16;

    const int kloc = tid & 31, pblk = tid >> 5;

    float acc[2][8][4];
#pragma unroll
    for (int mf = 0; mf < 2; mf++)
#pragma unroll
        for (int nf = 0; nf < 8; nf++)
#pragma unroll
            for (int e = 0; e < 4; e++) acc[mf][nf][e] = 0.f;

    __nv_bfloat16 pvh[16], pvl[16];

    auto cpB = [&](int r0, int bf) {
        uint32_t d = (uint32_t)bf * 10240;
        const __nv_bfloat16* sh = wh + bSrc + r0;
        const __nv_bfloat16* sl = wl + bSrc + r0;
        CP16(sbBh + d + bOff, sh);  CP16(sbBh + d + bOff + 16, sh + 8);
        CP16(sbBl + d + bOff, sl);  CP16(sbBl + d + bOff + 16, sl + 8);
    };

    auto ldgA = [&](int r0) {
        int r = r0 + kloc;
        if (MODE == 0) {
            int ic = r / (KK * KK);
            int rem = r - ic * KK * KK;
            int kh = rem / KK, kw = rem - kh * KK;
            int px = pxbase + pblk * 16;
            int oh = px >> 6, ow0 = px & 63;
            int ih = oh * S + kh - P;
            const size_t rowb = ((size_t)(b * Cin + ic) * Hin + ih) * Win;
            bool okh = (unsigned)ih < (unsigned)Hin;
#pragma unroll
            for (int i = 0; i < 16; i++) {
                int iw = (ow0 + i) * S + kw - P;
                bool ok = okh && (unsigned)iw < (unsigned)Win;
                pvh[i] = ok ? xh[rowb + iw] : __float2bfloat16(0.f);
                pvl[i] = ok ? xl[rowb + iw] : __float2bfloat16(0.f);
            }
        } else {
            int ic = r >> 2, th = (r >> 1) & 1, tw = r & 1;
            int j = j0 + (pblk >> 2);
            int i0 = (pblk & 3) * 16;
            int ih = j + (1 - ohp) - th;
            int iwb = i0 + (1 - owp) - tw;
            const size_t rowb = ((size_t)(b * Cin + ic) * 64 + ih) * 64;
            bool okh = (unsigned)ih < 64u;
#pragma unroll
            for (int i = 0; i < 16; i++) {
                int iw = iwb + i;
                bool ok = okh && (unsigned)iw < 64u;
                pvh[i] = ok ? xh[rowb + iw] : __float2bfloat16(0.f);
                pvl[i] = ok ? xl[rowb + iw] : __float2bfloat16(0.f);
            }
        }
    };

    auto stsA = [&](int bf) {
        int base = bf * ABUF + kloc;
#pragma unroll
        for (int i = 0; i < 16; i++) {
            int p = pblk * 16 + i;
            sA_h[base + p * CLDA] = pvh[i];
            sA_l[base + p * CLDA] = pvl[i];
        }
    };

    auto domma = [&](int bf) {
        const int off = bf * ABUF;
#pragma unroll
        for (int ks = 0; ks < 2; ks++) {
            const int k0 = ks * 16 + lc * 2;
            uint32_t ah[2][4], al[2][4];
#pragma unroll
            for (int mf = 0; mf < 2; mf++) {
                int r1 = wm * 32 + mf * 16 + lr;
                ah[mf][0] = *(const uint32_t*)&sA_h[off + r1 * CLDA + k0];
                ah[mf][1] = *(const uint32_t*)&sA_h[off + (r1 + 8) * CLDA + k0];
                ah[mf][2] = *(const uint32_t*)&sA_h[off + r1 * CLDA + k0 + 8];
                ah[mf][3] = *(const uint32_t*)&sA_h[off + (r1 + 8) * CLDA + k0 + 8];
                al[mf][0] = *(const uint32_t*)&sA_l[off + r1 * CLDA + k0];
                al[mf][1] = *(const uint32_t*)&sA_l[off + (r1 + 8) * CLDA + k0];
                al[mf][2] = *(const uint32_t*)&sA_l[off + r1 * CLDA + k0 + 8];
                al[mf][3] = *(const uint32_t*)&sA_l[off + (r1 + 8) * CLDA + k0 + 8];
            }
#pragma unroll
            for (int nf = 0; nf < 8; nf++) {
                int cr = wn * 64 + nf * 8 + lr;
                uint32_t bh[2], bl[2];
                bh[0] = *(const uint32_t*)&sB_h[off + cr * CLDA + k0];
                bh[1] = *(const uint32_t*)&sB_h[off + cr * CLDA + k0 + 8];
                bl[0] = *(const uint32_t*)&sB_l[off + cr * CLDA + k0];
                bl[1] = *(const uint32_t*)&sB_l[off + cr * CLDA + k0 + 8];
#pragma unroll
                for (int mf = 0; mf < 2; mf++) {
                    mma_bf16(acc[mf][nf], ah[mf], bh);
                    mma_bf16(acc[mf][nf], al[mf], bh);
                    mma_bf16(acc[mf][nf], ah[mf], bl);
                }
            }
        }
    };

    cpB(0, 0); CP_COMMIT();
    ldgA(0); stsA(0);
    for (int kc = 0; kc < NC; kc++) {
        const int bf = kc & 1;
        const bool nxt = (kc + 1 < NC);
        if (nxt) {
            cpB((kc + 1) * 32, bf ^ 1); CP_COMMIT();
            ldgA((kc + 1) * 32);
            CP_WAIT1();
        } else {
            CP_WAIT0();
        }
        __syncthreads();
        domma(bf);
        if (nxt) stsA(bf ^ 1);
        __syncthreads();
    }

#pragma unroll
    for (int mf = 0; mf < 2; mf++)
#pragma unroll
        for (int nf = 0; nf < 8; nf++)
#pragma unroll
            for (int e = 0; e < 4; e++) {
                int row = wm * 32 + mf * 16 + lr + (e >> 1) * 8;
                int oc = wn * 64 + nf * 8 + lc * 2 + (e & 1);
                float v = acc[mf][nf][e] + biasS[oc];
                if (RELU) v = fmaxf(v, 0.f);
                size_t addr;
                if (MODE == 0) {
                    int px = pxbase + row;
                    addr = ((size_t)(b * 128 + oc) * 64 + (px >> 6)) * 64 + (px & 63);
                } else {
                    int oh = (1 - ohp) + 2 * (j0 + (row >> 6));
                    int ow = (1 - owp) + 2 * (row & 63);
                    addr = ((size_t)(b * 128 + oc) * 128 + oh) * 128 + ow;
                }
                if (OUTMODE == 0) {
                    outf[addr] = v;
                } else {
                    __nv_bfloat16 h = __float2bfloat16(v);
                    outh[addr] = h;
                    outl[addr] = __float2bfloat16(v - __bfloat162float(h));
                }
            }
}

// =====================================================================
// weight split kernels (decoder only)
// =====================================================================
__global__ void wsplit(const float* __restrict__ w, __nv_bfloat16* __restrict__ wh,
                       __nv_bfloat16* __restrict__ wl, int n)
{
    int i = blockIdx.x * 256 + threadIdx.x;
    if (i >= n) return;
    float x = w[i];
    __nv_bfloat16 h = __float2bfloat16(x);
    wh[i] = h;
    wl[i] = __float2bfloat16(x - __bfloat162float(h));
}

__global__ void pack_wt2(const float* __restrict__ w, __nv_bfloat16* __restrict__ wh,
                         __nv_bfloat16* __restrict__ wl)
{
    int i = blockIdx.x * 256 + threadIdx.x;      // over 4*128*512
    int cls = i >> 16;
    int oc = (i >> 9) & 127;
    int r = i & 511;
    int ohp = cls >> 1, owp = cls & 1;
    int ic = r >> 2, th = (r >> 1) & 1, tw = r & 1;
    float x = w[((ic * 128 + oc) * 4 + ohp + 2 * th) * 4 + owp + 2 * tw];
    __nv_bfloat16 h = __float2bfloat16(x);
    wh[i] = h;
    wl[i] = __float2bfloat16(x - __bfloat162float(h));
}

// =====================================================================
// row squared-norm (exact R1 arithmetic)
// =====================================================================
__global__ void rownorm_kernel(const float* __restrict__ v, float* __restrict__ outn, int rows)
{
    int warp = threadIdx.x >> 5, lane = threadIdx.x & 31;
    int n = blockIdx.x * 8 + warp;
    if (n >= rows) return;
    const float* p = v + (size_t)n * 256;
    float s = 0.f;
#pragma unroll
    for (int k = 0; k < 8; k++) { float x = p[lane + 32 * k]; s = fmaf(x, x, s); }
#pragma unroll
    for (int off = 16; off; off >>= 1) s += __shfl_down_sync(0xffffffffu, s, off);
    if (lane == 0) outn[n] = s;
}

__global__ void zero_commit_kernel(float* c) { *c = 0.f; }

// =====================================================================
// VQ pack kernels (exact R3)
// =====================================================================
__global__ void pack_z_bf16(const float* __restrict__ z, __nv_bfloat16* __restrict__ A)
{
    int i = blockIdx.x * 256 + threadIdx.x;
    int q = i >> 8, k = i & 255;
    float x = z[i];
    __nv_bfloat16 h = __float2bfloat16(x);
    __nv_bfloat16 l = __float2bfloat16(x - __bfloat162float(h));
    size_t base = (size_t)q * KP;
    A[base + k] = h;
    A[base + 256 + k] = l;
    A[base + 512 + k] = h;
}

__global__ void pack_c_bf16(const float* __restrict__ c, __nv_bfloat16* __restrict__ B)
{
    int i = blockIdx.x * 256 + threadIdx.x;
    int q = i >> 8, k = i & 255;
    float x = c[i];
    __nv_bfloat16 h = __float2bfloat16(x);
    __nv_bfloat16 l = __float2bfloat16(x - __bfloat162float(h));
    size_t base = (size_t)q * KP;
    B[base + k] = h;
    B[base + 256 + k] = h;
    B[base + 512 + k] = l;
}

// =====================================================================
// VQ GEMM + fused argmin — CONTINUOUS 4-STAGE pipeline.
// Flat chunk stream g = 0..191 (tile nt = g/24, kc = g%24); one sync per
// chunk; cnorm double-buffered per tile. Per-dot arithmetic (24 ascending
// chunks, same MMA order, same epilogue) identical to R3 => same indices.
// Dynamic smem layout:
//   [0)      sA  4 x 10240 B
//   [40960)  sB  4 x 10240 B
//   [81920)  znS 128 f32
//   [82432)  cnS 2 x 128 f32
//   [83456)  redV 2 x 128 f32
//   [84480)  redI 2 x 128 int
// =====================================================================
#define LDA 40
#define VQ_SMEM 85504

__global__ __launch_bounds__(256)
void vq_mma(const __nv_bfloat16* __restrict__ Apk, const __nv_bfloat16* __restrict__ Bpk,
            const float* __restrict__ znorm, const float* __restrict__ cnorm,
            float* __restrict__ bv8, int* __restrict__ bi8)
{
    extern __shared__ __align__(16) char sm[];
    __nv_bfloat16* sA = (__nv_bfloat16*)(sm);
    __nv_bfloat16* sB = (__nv_bfloat16*)(sm + 40960);
    float* znS = (float*)(sm + 81920);
    float* cnS = (float*)(sm + 82432);
    float* redV = (float*)(sm + 83456);
    int*   redI = (int*)(sm + 84480);

    const int tid = threadIdx.x;
    const int lane = tid & 31, wid = tid >> 5;
    const int wm = wid & 3, wn = wid >> 2;
    const int lr = lane >> 2, lc = lane & 3;
    const int qbase = blockIdx.x * 128;
    const int gbase = blockIdx.y * 1024;

    if (tid < 128) znS[tid] = znorm[qbase + tid];

    const int srow = tid >> 1;
    const __nv_bfloat16* asrc = Apk + (size_t)(qbase + srow) * KP + (tid & 1) * 16;
    const uint32_t saA = s2u(sA) + srow * (LDA * 2) + (tid & 1) * 32;
    const uint32_t saB = s2u(sB) + srow * (LDA * 2) + (tid & 1) * 32;

    auto stage = [&](int g) {
        const int nt = g / 24, kc = g - nt * 24;
        const uint32_t d = (uint32_t)(g & 3) * 10240;
        const __nv_bfloat16* a2 = asrc + kc * 32;
        const __nv_bfloat16* b2 = Bpk + (size_t)(gbase + nt * 128 + srow) * KP
                                  + kc * 32 + (tid & 1) * 16;
        CP16(saA + d, a2);       CP16(saA + d + 16, a2 + 8);
        CP16(saB + d, b2);       CP16(saB + d + 16, b2 + 8);
        CP_COMMIT();
    };

    stage(0);
    stage(1);
    __syncthreads();            // znS visible
    float znr[4];
#pragma unroll
    for (int s = 0; s < 4; s++)
        znr[s] = znS[wm * 32 + (s >> 1) * 16 + lr + (s & 1) * 8];

    float bestv[4] = {3.4e38f, 3.4e38f, 3.4e38f, 3.4e38f};
    int   besti[4] = {0, 0, 0, 0};

    float acc[2][8][4];
#pragma unroll
    for (int mf = 0; mf < 2; mf++)
#pragma unroll
        for (int nf = 0; nf < 8; nf++)
#pragma unroll
            for (int e = 0; e < 4; e++) acc[mf][nf][e] = 0.f;

    for (int g = 0; g < 192; g++) {
        const int nt = g / 24, kc = g - nt * 24;

        if (kc == 0 && tid < 128)     // stage this tile's cnorm (double-buffered)
            cnS[(nt & 1) * 128 + tid] = cnorm[gbase + nt * 128 + tid];

        if (g + 2 < 192) {
            stage(g + 2);
            CP_WAIT2();
        } else if (g + 1 < 192) {
            CP_WAIT1();
        } else {
            CP_WAIT0();
        }
        __syncthreads();

        const int buf = g & 3;
        const uint32_t aoff = (uint32_t)buf * 5120;   // elements
#pragma unroll
        for (int ks = 0; ks < 2; ks++) {
            const int k0 = ks * 16 + lc * 2;
            uint32_t a[2][4], b[8][2];
#pragma unroll
            for (int mf = 0; mf < 2; mf++) {
                int r = wm * 32 + mf * 16 + lr;
                a[mf][0] = *(const uint32_t*)&sA[aoff + r * LDA + k0];
                a[mf][1] = *(const uint32_t*)&sA[aoff + (r + 8) * LDA + k0];
                a[mf][2] = *(const uint32_t*)&sA[aoff + r * LDA + k0 + 8];
                a[mf][3] = *(const uint32_t*)&sA[aoff + (r + 8) * LDA + k0 + 8];
            }
#pragma unroll
            for (int nf = 0; nf < 8; nf++) {
                int cr = wn * 64 + nf * 8 + lr;
                b[nf][0] = *(const uint32_t*)&sB[aoff + cr * LDA + k0];
                b[nf][1] = *(const uint32_t*)&sB[aoff + cr * LDA + k0 + 8];
            }
#pragma unroll
            for (int mf = 0; mf < 2; mf++)
#pragma unroll
                for (int nf = 0; nf < 8; nf++)
                    mma_bf16(acc[mf][nf], a[mf], b[nf]);
        }

        if (kc == 23) {
            // epilogue: score + per-thread argmin, reset acc (registers only)
            const float* cns = cnS + (nt & 1) * 128;
#pragma unroll
            for (int mf = 0; mf < 2; mf++)
#pragma unroll
                for (int nf = 0; nf < 8; nf++)
#pragma unroll
                    for (int e = 0; e < 4; e++) {
                        int h = e >> 1;
                        int col = wn * 64 + nf * 8 + lc * 2 + (e & 1);
                        int slot = mf * 2 + h;
                        float t = znr[slot] + cns[col];
                        float s = fmaf(-2.f, acc[mf][nf][e], t);
                        int code = gbase + nt * 128 + col;
                        if (s < bestv[slot]) { bestv[slot] = s; besti[slot] = code; }
                        acc[mf][nf][e] = 0.f;
                    }
        }
    }

#pragma unroll
    for (int s = 0; s < 4; s++) {
        float v = bestv[s]; int ix = besti[s];
#pragma unroll
        for (int off = 1; off <= 2; off <<= 1) {
            float ov = __shfl_xor_sync(0xffffffffu, v, off);
            int   oi = __shfl_xor_sync(0xffffffffu, ix, off);
            if (ov < v || (ov == v && oi < ix)) { v = ov; ix = oi; }
        }
        if (lc == 0) {
            int row = wm * 32 + (s >> 1) * 16 + lr + (s & 1) * 8;
            redV[wn * 128 + row] = v; redI[wn * 128 + row] = ix;
        }
    }
    __syncthreads();
    if (tid < 128) {
        float v = redV[tid]; int ix = redI[tid];
        float v1 = redV[128 + tid]; int i1 = redI[128 + tid];
        if (v1 < v || (v1 == v && i1 < ix)) { v = v1; ix = i1; }
        bv8[blockIdx.y * NQ + qbase + tid] = v;
        bi8[blockIdx.y * NQ + qbase + tid] = ix;
    }
}

__global__ void vq_combine8(const float* __restrict__ bv8, const int* __restrict__ bi8,
                            int* __restrict__ idx)
{
    int q = blockIdx.x * 256 + threadIdx.x;
    if (q >= NQ) return;
    float v = bv8[q]; int ix = bi8[q];
#pragma unroll
    for (int g = 1; g < 8; g++) {
        float v2 = bv8[g * NQ + q];
        int   i2 = bi8[g * NQ + q];
        if (v2 < v || (v2 == v && i2 < ix)) { v = v2; ix = i2; }
    }
    idx[q] = ix;
}

// =====================================================================
// gather quant = codebook[idx], commit loss
// =====================================================================
__global__ __launch_bounds__(256)
void gather_commit(const float* __restrict__ cb, const float* __restrict__ z,
                   const int* __restrict__ idx, float* __restrict__ quant,
                   float* __restrict__ commit)
{
    int n = blockIdx.x;
    int t = threadIdx.x;
    int id = idx[n];
    float q = cb[(size_t)id * 256 + t];
    float zv = z[(size_t)n * 256 + t];
    quant[(size_t)n * 256 + t] = q;
    float d = q - zv; d *= d;
#pragma unroll
    for (int off = 16; off; off >>= 1) d += __shfl_down_sync(0xffffffffu, d, off);
    __shared__ float wsum[8];
    int warp = t >> 5, lane = t & 31;
    if (lane == 0) wsum[warp] = d;
    __syncthreads();
    if (t == 0) {
        float s = 0.f;
#pragma unroll
        for (int w = 0; w < 8; w++) s += wsum[w];
        atomicAdd(commit, s);
    }
}

// =====================================================================
// Final transposed conv (128 -> 3 channels) straight into d_out.
// =====================================================================
__global__ __launch_bounds__(256)
void convt_out3(const float* __restrict__ in, const float* __restrict__ w,
                const float* __restrict__ bias, float* __restrict__ out)
{
    __shared__ float ws[128 * 3 * 16];
    for (int i = threadIdx.x; i < 6144; i += 256) ws[i] = w[i];
    __syncthreads();

    int b = blockIdx.y, oh = blockIdx.x, ow = threadIdx.x;
    int ih0 = (oh + 1) >> 1, kh0 = (oh + 1) & 1;
    int iw0 = (ow + 1) >> 1, kw0 = (ow + 1) & 1;

    float acc0 = 0.f, acc1 = 0.f, acc2 = 0.f;
#pragma unroll 4
    for (int ic = 0; ic < 128; ic++) {
        const float* inp = in + ((size_t)(b * 128 + ic)) * 128 * 128;
        const float* wp = ws + ic * 48;
#pragma unroll
        for (int th = 0; th < 2; th++) {
            int ih = ih0 - th;
            if ((unsigned)ih < 128u) {
                int kh = kh0 + 2 * th;
#pragma unroll
                for (int tw = 0; tw < 2; tw++) {
                    int iw = iw0 - tw;
                    if ((unsigned)iw < 128u) {
                        int kw = kw0 + 2 * tw;
                        float v = inp[ih * 128 + iw];
                        int wk = kh * 4 + kw;
                        acc0 = fmaf(v, wp[wk], acc0);
                        acc1 = fmaf(v, wp[16 + wk], acc1);
                        acc2 = fmaf(v, wp[32 + wk], acc2);
                    }
                }
            }
        }
    }
    size_t ob = ((size_t)(b * 3) * 256 + oh) * 256 + ow;
    out[ob]          = acc0 + bias[0];
    out[ob + 65536]  = acc1 + bias[1];
    out[ob + 131072] = acc2 + bias[2];
}

__global__ void pack_kernel(float* __restrict__ out, const float* __restrict__ commit,
                            const int* __restrict__ idx)
{
    int i = blockIdx.x * 256 + threadIdx.x;
    if (i == 0) out[786432] = (*commit) * (1.f / 4194304.f);
    if (i < NQ) out[786433 + i] = (float)idx[i];
}

// =====================================================================
// host launcher
// =====================================================================
#define CMMA_SMEM 82432

extern "C" void kernel_launch(void* const* d_in, const int* in_sizes, int n_in,
                              void* d_out, int out_size)
{
    const float* x        = (const float*)d_in[0];
    const float* enc_w1   = (const float*)d_in[1];
    const float* enc_b1   = (const float*)d_in[2];
    const float* enc_w2   = (const float*)d_in[3];
    const float* enc_b2   = (const float*)d_in[4];
    const float* enc_w3   = (const float*)d_in[5];
    const float* enc_b3   = (const float*)d_in[6];
    const float* qconv_w  = (const float*)d_in[7];
    const float* qconv_b  = (const float*)d_in[8];
    const float* codebook = (const float*)d_in[9];
    const float* pqconv_w = (const float*)d_in[10];
    const float* pqconv_b = (const float*)d_in[11];
    const float* dec_w1   = (const float*)d_in[12];
    const float* dec_b1   = (const float*)d_in[13];
    const float* dect_w2  = (const float*)d_in[14];
    const float* dect_b2  = (const float*)d_in[15];
    const float* dect_w3  = (const float*)d_in[16];
    const float* dect_b3  = (const float*)d_in[17];
    float* out = (float*)d_out;

    float *h1, *h2, *h3, *z, *quant, *d2, *znorm, *cnorm, *commit, *bv8;
    float *w2t, *w3t, *wqt, *wpt;
    __nv_bfloat16 *qh, *ql, *d1h, *d1l, *apk, *bpk;
    __nv_bfloat16 *wd1h, *wd1l, *wt2h, *wt2l;
    int *idx, *bi8;
    cudaGetSymbolAddress((void**)&h1, g_h1);
    cudaGetSymbolAddress((void**)&h2, g_h2);
    cudaGetSymbolAddress((void**)&h3, g_h3);
    cudaGetSymbolAddress((void**)&z, g_z);
    cudaGetSymbolAddress((void**)&quant, g_quant);
    cudaGetSymbolAddress((void**)&qh, g_qh);
    cudaGetSymbolAddress((void**)&ql, g_ql);
    cudaGetSymbolAddress((void**)&d1h, g_d1h);
    cudaGetSymbolAddress((void**)&d1l, g_d1l);
    cudaGetSymbolAddress((void**)&d2, g_d2);
    cudaGetSymbolAddress((void**)&znorm, g_znorm);
    cudaGetSymbolAddress((void**)&cnorm, g_cnorm);
    cudaGetSymbolAddress((void**)&idx, g_idx);
    cudaGetSymbolAddress((void**)&commit, g_commit);
    cudaGetSymbolAddress((void**)&apk, g_apk);
    cudaGetSymbolAddress((void**)&bpk, g_bpk);
    cudaGetSymbolAddress((void**)&bv8, g_bv8);
    cudaGetSymbolAddress((void**)&bi8, g_bi8);
    cudaGetSymbolAddress((void**)&wd1h, g_wd1h); cudaGetSymbolAddress((void**)&wd1l, g_wd1l);
    cudaGetSymbolAddress((void**)&wt2h, g_wt2h); cudaGetSymbolAddress((void**)&wt2l, g_wt2l);
    cudaGetSymbolAddress((void**)&w2t, g_w2t);   cudaGetSymbolAddress((void**)&w3t, g_w3t);
    cudaGetSymbolAddress((void**)&wqt, g_wqt);   cudaGetSymbolAddress((void**)&wpt, g_wpt);

    cudaFuncSetAttribute(conv_mma<0,3,1,1,true ,1>, cudaFuncAttributeMaxDynamicSharedMemorySize, CMMA_SMEM);
    cudaFuncSetAttribute(conv_mma<1,4,2,1,true ,0>, cudaFuncAttributeMaxDynamicSharedMemorySize, CMMA_SMEM);
    cudaFuncSetAttribute(vq_mma, cudaFuncAttributeMaxDynamicSharedMemorySize, VQ_SMEM);

    // weight prep: fp32 chunk-major transposes + decoder splits + VQ codebook
    wtrans<<<1024, 256>>>(enc_w2, w2t, 2048, 128);
    wtrans<<<576, 256>>>(enc_w3, w3t, 1152, 128);
    wtrans<<<128, 256>>>(qconv_w, wqt, 128, 256);
    wtrans<<<128, 256>>>(pqconv_w, wpt, 256, 128);
    wsplit<<<576, 256>>>(dec_w1, wd1h, wd1l, 128 * 1152);
    pack_wt2<<<1024, 256>>>(dect_w2, wt2h, wt2l);
    pack_c_bf16<<<KCB, 256>>>(codebook, bpk);
    rownorm_kernel<<<1024, 256>>>(codebook, cnorm, KCB);
    zero_commit_kernel<<<1, 1>>>(commit);

    // encoder — enc1 dedicated; enc2/enc3/qconv on 4-stage async FFMA2
    conv_enc1<<<dim3(128,4),256>>>(x, enc_w1, enc_b1, h1);
    conv_async<4,2,1,true ,0,0><<<dim3(64,1,4),256>>>(h1, w2t, enc_b2, h2, nullptr, nullptr,
                                                      128,128, 128,128,  64, 64, 6);
    conv_async<3,1,1,false,0,0><<<dim3(64,1,4),256>>>(h2, w3t, enc_b3, h3, nullptr, nullptr,
                                                      128,128,  64, 64,  64, 64, 6);
    conv_async<1,1,0,false,0,1><<<dim3(64,2,4),256>>>(h3, wqt, qconv_b, z, nullptr, nullptr,
                                                      128,256,  64, 64,  64, 64, 6);

    // quantize — continuous-pipeline VQ (same arithmetic as R3)
    pack_z_bf16<<<NQ, 256>>>(z, apk);
    rownorm_kernel<<<2048, 256>>>(z, znorm, NQ);
    vq_mma<<<dim3(128, 8), 256, VQ_SMEM>>>(apk, bpk, znorm, cnorm, bv8, bi8);
    vq_combine8<<<64, 256>>>(bv8, bi8, idx);
    gather_commit<<<NQ, 256>>>(codebook, z, idx, quant, commit);

    // decoder — tensor-core bf16-split
    conv_async<1,1,0,false,1,2><<<dim3(64,1,4),256>>>(quant, wpt, pqconv_b, nullptr, qh, ql,
                                                      256, 128, 64,64, 64,64, 6);
    conv_mma<0,3,1,1,true ,1><<<dim3(32,1,4),256,CMMA_SMEM>>>(qh, ql, wd1h, wd1l, dec_b1,
                                                     nullptr, d1h, d1l, 128, 64, 64, 1152);
    conv_mma<1,4,2,1,true ,0><<<dim3(32,4,4),256,CMMA_SMEM>>>(d1h, d1l, wt2h, wt2l, dect_b2,
                                                     d2, nullptr, nullptr, 128, 64, 64, 512);
    convt_out3<<<dim3(256,4),256>>>(d2, dect_w3, dect_b3, out);

    pack_kernel<<<64, 256>>>(out, commit, idx);

    (void)in_sizes; (void)n_in; (void)out_size;
}

// round 15
// speedup vs baseline: 1.2595x; 1.0876x over previous
#include <cuda_runtime.h>
#include <cuda_bf16.h>
#include <cstdint>

// ---------------- problem constants ----------------
#define BATCH 4
#define NQ    16384
#define EDIM  256
#define KCB   8192

// ---------------- scratch (static device memory; no allocation) ----------------
__device__ float g_h1[4 * 128 * 128 * 128];
__device__ float g_h2[4 * 128 * 64 * 64];
__device__ float g_h3[4 * 128 * 64 * 64];
__device__ float g_z[NQ * EDIM];
__device__ float g_quant[NQ * EDIM];
__device__ __nv_bfloat16 g_qh[4 * 128 * 64 * 64];
__device__ __nv_bfloat16 g_ql[4 * 128 * 64 * 64];
__device__ __nv_bfloat16 g_d1h[4 * 128 * 64 * 64];
__device__ __nv_bfloat16 g_d1l[4 * 128 * 64 * 64];
__device__ float g_d2[4 * 128 * 128 * 128];
__device__ float g_znorm[NQ];
__device__ float g_cnorm[KCB];
__device__ int   g_idx[NQ];
__device__ float g_commit;
// VQ split planes (deduplicated: zh,zl,ch,cl)
__device__ __nv_bfloat16 g_zh[(size_t)NQ * EDIM],  g_zl[(size_t)NQ * EDIM];
__device__ __nv_bfloat16 g_ch[(size_t)KCB * EDIM], g_cl[(size_t)KCB * EDIM];
__device__ float g_bv8[8 * NQ];
__device__ int   g_bi8[8 * NQ];
// pre-split decoder weights
__device__ __nv_bfloat16 g_wd1h[128 * 1152], g_wd1l[128 * 1152];
__device__ __nv_bfloat16 g_wt2h[4 * 128 * 512], g_wt2l[4 * 128 * 512];
// chunk-major transposed fp32 weights for async FFMA convs
__device__ float g_w2t[128 * 2048];
__device__ float g_w3t[128 * 1152];
__device__ float g_wqt[256 * 128];
__device__ float g_wpt[128 * 256];

__device__ __forceinline__ uint32_t s2u(const void* p)
{
    uint32_t a;
    asm("{ .reg .u64 t; cvta.to.shared.u64 t, %1; cvt.u32.u64 %0, t; }" : "=r"(a) : "l"(p));
    return a;
}

#define CP16(dst, src) \
    asm volatile("cp.async.cg.shared.global [%0], [%1], 16;" :: "r"(dst), "l"(src) : "memory")
#define CP4Z(dst, src, sz) \
    asm volatile("cp.async.ca.shared.global [%0], [%1], 4, %2;" :: "r"(dst), "l"(src), "r"(sz) : "memory")
#define CP_COMMIT() asm volatile("cp.async.commit_group;" ::: "memory")
#define CP_WAIT2()  asm volatile("cp.async.wait_group 2;" ::: "memory")
#define CP_WAIT1()  asm volatile("cp.async.wait_group 1;" ::: "memory")
#define CP_WAIT0()  asm volatile("cp.async.wait_group 0;" ::: "memory")

__device__ __forceinline__ void mma_bf16(float* c, const uint32_t* a, const uint32_t* b)
{
    asm volatile(
        "mma.sync.aligned.m16n8k16.row.col.f32.bf16.bf16.f32 "
        "{%0,%1,%2,%3}, {%4,%5,%6,%7}, {%8,%9}, {%0,%1,%2,%3};"
        : "+f"(c[0]), "+f"(c[1]), "+f"(c[2]), "+f"(c[3])
        : "r"(a[0]), "r"(a[1]), "r"(a[2]), "r"(a[3]), "r"(b[0]), "r"(b[1]));
}

__device__ __forceinline__ void ffma2(uint64_t& acc, uint64_t wp, uint64_t xx)
{
    asm("fma.rn.f32x2 %0, %1, %2, %0;" : "+l"(acc) : "l"(wp), "l"(xx));
}

// =====================================================================
// Weight transpose into chunk-major [ocTile][chunk][r(16)][ocl(128)].
// =====================================================================
__global__ void wtrans(const float* __restrict__ w, float* __restrict__ wt, int R, int Cout)
{
    int i = blockIdx.x * 256 + threadIdx.x;
    if (i >= Cout * R) return;
    int ocl = i & 127;
    int rest = i >> 7;
    int r = rest & 15;
    int chunkAll = rest >> 4;
    int NC = R >> 4;
    int ot = chunkAll / NC;
    int c = chunkAll - ot * NC;
    wt[i] = w[(size_t)(ot * 128 + ocl) * R + c * 16 + r];
}

// =====================================================================
// Dedicated enc1 kernel (R9 — passing; h1 bitwise identical)
// =====================================================================
__global__ __launch_bounds__(256)
void conv_enc1(const float* __restrict__ x, const float* __restrict__ w,
               const float* __restrict__ bias, float* __restrict__ out)
{
    __shared__ __align__(16) float ws[48][128];
    __shared__ __align__(16) float xs[48][128];

    const int tid = threadIdx.x;
    const int oh = blockIdx.x;
    const int b = blockIdx.y;

#pragma unroll
    for (int i = 0; i < 24; i++) {
        int idx = tid + i * 256;
        int r = idx >> 7, oc = idx & 127;
        ws[r][oc] = w[oc * 48 + r];
    }
#pragma unroll
    for (int i = 0; i < 24; i++) {
        int idx = tid + i * 256;
        int r = idx >> 7, p = idx & 127;
        int ic = r >> 4, kh = (r >> 2) & 3, kw = r & 3;
        int ih = oh * 2 + kh - 1;
        int iw = p * 2 + kw - 1;
        float v = 0.f;
        if ((unsigned)ih < 256u && (unsigned)iw < 256u)
            v = x[((size_t)(b * 3 + ic) * 256 + ih) * 256 + iw];
        xs[r][p] = v;
    }
    __syncthreads();

    const int tx = tid & 15;
    const int ty = tid >> 4;
    const uint32_t wsb = s2u(ws) + ty * 32;

    uint64_t acc2[4][8];
#pragma unroll
    for (int pq = 0; pq < 4; pq++)
#pragma unroll
        for (int i = 0; i < 8; i++) acc2[pq][i] = 0ull;

#pragma unroll 4
    for (int k = 0; k < 48; k++) {
        uint64_t wp0, wp1, wp2, wp3;
        asm("ld.shared.v2.u64 {%0,%1}, [%2];"
            : "=l"(wp0), "=l"(wp1) : "r"(wsb + (uint32_t)(k * 512)));
        asm("ld.shared.v2.u64 {%0,%1}, [%2];"
            : "=l"(wp2), "=l"(wp3) : "r"(wsb + (uint32_t)(k * 512 + 16)));
        float4 xv0 = *reinterpret_cast<const float4*>(&xs[k][tx * 8]);
        float4 xv1 = *reinterpret_cast<const float4*>(&xs[k][tx * 8 + 4]);
        uint64_t xx[8];
        asm("mov.b64 %0, {%1,%1};" : "=l"(xx[0]) : "f"(xv0.x));
        asm("mov.b64 %0, {%1,%1};" : "=l"(xx[1]) : "f"(xv0.y));
        asm("mov.b64 %0, {%1,%1};" : "=l"(xx[2]) : "f"(xv0.z));
        asm("mov.b64 %0, {%1,%1};" : "=l"(xx[3]) : "f"(xv0.w));
        asm("mov.b64 %0, {%1,%1};" : "=l"(xx[4]) : "f"(xv1.x));
        asm("mov.b64 %0, {%1,%1};" : "=l"(xx[5]) : "f"(xv1.y));
        asm("mov.b64 %0, {%1,%1};" : "=l"(xx[6]) : "f"(xv1.z));
        asm("mov.b64 %0, {%1,%1};" : "=l"(xx[7]) : "f"(xv1.w));
#pragma unroll
        for (int i = 0; i < 8; i++) {
            ffma2(acc2[0][i], wp0, xx[i]);
            ffma2(acc2[1][i], wp1, xx[i]);
            ffma2(acc2[2][i], wp2, xx[i]);
            ffma2(acc2[3][i], wp3, xx[i]);
        }
    }

#pragma unroll
    for (int pq = 0; pq < 4; pq++)
#pragma unroll
        for (int half = 0; half < 2; half++) {
            int oc = ty * 8 + 2 * pq + half;
            float bv = bias[oc];
            float* op = out + ((size_t)(b * 128 + oc) * 128 + oh) * 128 + tx * 8;
#pragma unroll
            for (int i = 0; i < 8; i++) {
                uint32_t bits = half ? (uint32_t)(acc2[pq][i] >> 32)
                                     : (uint32_t)(acc2[pq][i] & 0xffffffffull);
                float v = __uint_as_float(bits) + bv;
                op[i] = fmaxf(v, 0.f);
            }
        }
}

// =====================================================================
// FFMA2 implicit-GEMM conv with cp.async 4-STAGE pipeline (R13/R14 — passing)
// =====================================================================
template<int KK, int S, int P, bool RELU, int INL, int OUTL>
__global__ __launch_bounds__(256)
void conv_async(const float* __restrict__ in, const float* __restrict__ wt,
                const float* __restrict__ bias, float* __restrict__ out,
                __nv_bfloat16* __restrict__ outh, __nv_bfloat16* __restrict__ outl,
                int Cin, int Cout, int Hin, int Win, int Hout, int Wout,
                int woutShift)
{
    const int R = Cin * KK * KK;
    const int NC = R >> 4;
    const int b = blockIdx.z;
    const int ot = blockIdx.y;
    const int oc0 = ot * 128;
    const int pxbase = blockIdx.x * 64;

    __shared__ __align__(16) float ws[4][16][128];
    __shared__ __align__(16) float xs[4][16][68];

    const int tid = threadIdx.x;
    const int tx = tid & 15;
    const int ty = tid >> 4;

    const uint32_t wsb0 = s2u(ws);
    const uint32_t xsb0 = s2u(xs);
    const uint32_t wdst = wsb0 + (uint32_t)tid * 32;
    const float* wsrc_base = wt + (size_t)ot * ((size_t)NC * 2048) + tid * 8;

    uint64_t acc2[4][4];
#pragma unroll
    for (int p = 0; p < 4; p++)
#pragma unroll
        for (int i = 0; i < 4; i++) acc2[p][i] = 0ull;

    auto stage = [&](int c, int bf) {
        const float* wsrc = wsrc_base + (size_t)c * 2048;
        uint32_t wd = wdst + (uint32_t)bf * 8192;
        CP16(wd, wsrc);
        CP16(wd + 16, wsrc + 4);
#pragma unroll
        for (int i2 = 0; i2 < 4; i2++) {
            int li = tid + i2 * 256;
            int r, p;
            if (INL == 1) { r = li & 15; p = li >> 4; }
            else          { r = li >> 6; p = li & 63; }
            int rr = c * 16 + r;
            const float* src = in;
            int sz = 0;
            if (INL == 1) {
                int n = b * (Hout * Wout) + pxbase + p;
                src = in + (size_t)n * Cin + rr;
                sz = 4;
            } else {
                int ic = rr / (KK * KK);
                int kr = rr - ic * KK * KK;
                int kh = kr / KK, kw = kr - kh * KK;
                int px = pxbase + p;
                int oh = px >> woutShift;
                int ow = px & (Wout - 1);
                int ih = oh * S + kh - P;
                int iw = ow * S + kw - P;
                if ((unsigned)ih < (unsigned)Hin && (unsigned)iw < (unsigned)Win) {
                    src = in + ((size_t)(b * Cin + ic) * Hin + ih) * Win + iw;
                    sz = 4;
                }
            }
            uint32_t xd = xsb0 + (uint32_t)bf * 4352 + (uint32_t)((r * 68 + p) * 4);
            CP4Z(xd, src, sz);
        }
    };

    stage(0, 0); CP_COMMIT();
    if (NC > 1) { stage(1, 1); CP_COMMIT(); }

    for (int c = 0; c < NC; c++) {
        const int bf = c & 3;
        if (c + 2 < NC) {
            stage(c + 2, (c + 2) & 3); CP_COMMIT();
            CP_WAIT2();
        } else if (c + 1 < NC) {
            CP_WAIT1();
        } else {
            CP_WAIT0();
        }
        __syncthreads();

        const uint32_t wsb = wsb0 + (uint32_t)bf * 8192 + ty * 32;
        const float (*xsb)[68] = xs[bf];
#pragma unroll
        for (int k = 0; k < 16; k++) {
            float4 xv = *reinterpret_cast<const float4*>(&xsb[k][tx * 4]);
            uint64_t wp0, wp1, wp2, wp3;
            asm("ld.shared.v2.u64 {%0,%1}, [%2];"
                : "=l"(wp0), "=l"(wp1) : "r"(wsb + (uint32_t)(k * 512)));
            asm("ld.shared.v2.u64 {%0,%1}, [%2];"
                : "=l"(wp2), "=l"(wp3) : "r"(wsb + (uint32_t)(k * 512 + 16)));
            uint64_t xx0, xx1, xx2, xx3;
            asm("mov.b64 %0, {%1,%1};" : "=l"(xx0) : "f"(xv.x));
            asm("mov.b64 %0, {%1,%1};" : "=l"(xx1) : "f"(xv.y));
            asm("mov.b64 %0, {%1,%1};" : "=l"(xx2) : "f"(xv.z));
            asm("mov.b64 %0, {%1,%1};" : "=l"(xx3) : "f"(xv.w));
            ffma2(acc2[0][0], wp0, xx0); ffma2(acc2[0][1], wp0, xx1);
            ffma2(acc2[0][2], wp0, xx2); ffma2(acc2[0][3], wp0, xx3);
            ffma2(acc2[1][0], wp1, xx0); ffma2(acc2[1][1], wp1, xx1);
            ffma2(acc2[1][2], wp1, xx2); ffma2(acc2[1][3], wp1, xx3);
            ffma2(acc2[2][0], wp2, xx0); ffma2(acc2[2][1], wp2, xx1);
            ffma2(acc2[2][2], wp2, xx2); ffma2(acc2[2][3], wp2, xx3);
            ffma2(acc2[3][0], wp3, xx0); ffma2(acc2[3][1], wp3, xx1);
            ffma2(acc2[3][2], wp3, xx2); ffma2(acc2[3][3], wp3, xx3);
        }
    }

#pragma unroll
    for (int p = 0; p < 4; p++)
#pragma unroll
        for (int half = 0; half < 2; half++) {
            int j = 2 * p + half;
            int oc = oc0 + ty * 8 + j;
            float bv = bias[oc];
#pragma unroll
            for (int i = 0; i < 4; i++) {
                uint32_t bits = half ? (uint32_t)(acc2[p][i] >> 32)
                                     : (uint32_t)(acc2[p][i] & 0xffffffffull);
                float v = __uint_as_float(bits) + bv;
                if (RELU) v = fmaxf(v, 0.f);
                if (OUTL == 1) {
                    size_t n = (size_t)(b * (Hout * Wout) + pxbase + tx * 4 + i);
                    out[n * Cout + oc] = v;
                } else {
                    size_t addr = (size_t)(b * Cout + oc) * (Hout * Wout) + pxbase + tx * 4 + i;
                    if (OUTL == 0) {
                        out[addr] = v;
                    } else {
                        __nv_bfloat16 h = __float2bfloat16(v);
                        outh[addr] = h;
                        outl[addr] = __float2bfloat16(v - __bfloat162float(h));
                    }
                }
            }
        }
}

// =====================================================================
// Tensor-core implicit-GEMM conv, bf16 3-term split — DECODER ONLY.
// (unchanged — passing)
// =====================================================================
#define CLDA 40
#define ABUF 5120

template<int MODE, int KK, int S, int P, bool RELU, int OUTMODE>
__global__ __launch_bounds__(256)
void conv_mma(const __nv_bfloat16* __restrict__ xh, const __nv_bfloat16* __restrict__ xl,
              const __nv_bfloat16* __restrict__ wh_g, const __nv_bfloat16* __restrict__ wl_g,
              const float* __restrict__ bias,
              float* __restrict__ outf, __nv_bfloat16* __restrict__ outh,
              __nv_bfloat16* __restrict__ outl,
              int Cin, int Hin, int Win, int R)
{
    extern __shared__ __align__(16) char sm[];
    __nv_bfloat16* sA_h = (__nv_bfloat16*)(sm);
    __nv_bfloat16* sA_l = (__nv_bfloat16*)(sm + 20480);
    __nv_bfloat16* sB_h = (__nv_bfloat16*)(sm + 40960);
    __nv_bfloat16* sB_l = (__nv_bfloat16*)(sm + 61440);
    float* biasS = (float*)(sm + 81920);

    const int tid = threadIdx.x;
    const int lane = tid & 31, wid = tid >> 5;
    const int wm = wid & 3, wn = wid >> 2;
    const int lr = lane >> 2, lc = lane & 3;
    const int b = blockIdx.z;

    int pxbase = 0, j0 = 0, ohp = 0, owp = 0;
    const __nv_bfloat16* wh = wh_g;
    const __nv_bfloat16* wl = wl_g;
    if (MODE == 1) {
        j0 = blockIdx.x * 2;
        int cls = blockIdx.y;
        ohp = cls >> 1; owp = cls & 1;
        wh = wh_g + cls * (128 * 512);
        wl = wl_g + cls * (128 * 512);
    } else {
        pxbase = blockIdx.x * 128;
    }

    if (tid < 128) biasS[tid] = bias[tid];

    const int NC = R >> 5;

    const int boc = tid >> 1;
    const uint32_t sbBh = s2u(sB_h), sbBl = s2u(sB_l);
    const uint32_t bOff = (uint32_t)(boc * 80 + (tid & 1) * 32);
    const size_t bSrc = (size_t)boc * R + (tid & 1) * 16;

    const int kloc = tid & 31, pblk = tid >> 5;

    float acc[2][8][4];
#pragma unroll
    for (int mf = 0; mf < 2; mf++)
#pragma unroll
        for (int nf = 0; nf < 8; nf++)
#pragma unroll
            for (int e = 0; e < 4; e++) acc[mf][nf][e] = 0.f;

    __nv_bfloat16 pvh[16], pvl[16];

    auto cpB = [&](int r0, int bf) {
        uint32_t d = (uint32_t)bf * 10240;
        const __nv_bfloat16* sh = wh + bSrc + r0;
        const __nv_bfloat16* sl = wl + bSrc + r0;
        CP16(sbBh + d + bOff, sh);  CP16(sbBh + d + bOff + 16, sh + 8);
        CP16(sbBl + d + bOff, sl);  CP16(sbBl + d + bOff + 16, sl + 8);
    };

    auto ldgA = [&](int r0) {
        int r = r0 + kloc;
        if (MODE == 0) {
            int ic = r / (KK * KK);
            int rem = r - ic * KK * KK;
            int kh = rem / KK, kw = rem - kh * KK;
            int px = pxbase + pblk * 16;
            int oh = px >> 6, ow0 = px & 63;
            int ih = oh * S + kh - P;
            const size_t rowb = ((size_t)(b * Cin + ic) * Hin + ih) * Win;
            bool okh = (unsigned)ih < (unsigned)Hin;
#pragma unroll
            for (int i = 0; i < 16; i++) {
                int iw = (ow0 + i) * S + kw - P;
                bool ok = okh && (unsigned)iw < (unsigned)Win;
                pvh[i] = ok ? xh[rowb + iw] : __float2bfloat16(0.f);
                pvl[i] = ok ? xl[rowb + iw] : __float2bfloat16(0.f);
            }
        } else {
            int ic = r >> 2, th = (r >> 1) & 1, tw = r & 1;
            int j = j0 + (pblk >> 2);
            int i0 = (pblk & 3) * 16;
            int ih = j + (1 - ohp) - th;
            int iwb = i0 + (1 - owp) - tw;
            const size_t rowb = ((size_t)(b * Cin + ic) * 64 + ih) * 64;
            bool okh = (unsigned)ih < 64u;
#pragma unroll
            for (int i = 0; i < 16; i++) {
                int iw = iwb + i;
                bool ok = okh && (unsigned)iw < 64u;
                pvh[i] = ok ? xh[rowb + iw] : __float2bfloat16(0.f);
                pvl[i] = ok ? xl[rowb + iw] : __float2bfloat16(0.f);
            }
        }
    };

    auto stsA = [&](int bf) {
        int base = bf * ABUF + kloc;
#pragma unroll
        for (int i = 0; i < 16; i++) {
            int p = pblk * 16 + i;
            sA_h[base + p * CLDA] = pvh[i];
            sA_l[base + p * CLDA] = pvl[i];
        }
    };

    auto domma = [&](int bf) {
        const int off = bf * ABUF;
#pragma unroll
        for (int ks = 0; ks < 2; ks++) {
            const int k0 = ks * 16 + lc * 2;
            uint32_t ah[2][4], al[2][4];
#pragma unroll
            for (int mf = 0; mf < 2; mf++) {
                int r1 = wm * 32 + mf * 16 + lr;
                ah[mf][0] = *(const uint32_t*)&sA_h[off + r1 * CLDA + k0];
                ah[mf][1] = *(const uint32_t*)&sA_h[off + (r1 + 8) * CLDA + k0];
                ah[mf][2] = *(const uint32_t*)&sA_h[off + r1 * CLDA + k0 + 8];
                ah[mf][3] = *(const uint32_t*)&sA_h[off + (r1 + 8) * CLDA + k0 + 8];
                al[mf][0] = *(const uint32_t*)&sA_l[off + r1 * CLDA + k0];
                al[mf][1] = *(const uint32_t*)&sA_l[off + (r1 + 8) * CLDA + k0];
                al[mf][2] = *(const uint32_t*)&sA_l[off + r1 * CLDA + k0 + 8];
                al[mf][3] = *(const uint32_t*)&sA_l[off + (r1 + 8) * CLDA + k0 + 8];
            }
#pragma unroll
            for (int nf = 0; nf < 8; nf++) {
                int cr = wn * 64 + nf * 8 + lr;
                uint32_t bh[2], bl[2];
                bh[0] = *(const uint32_t*)&sB_h[off + cr * CLDA + k0];
                bh[1] = *(const uint32_t*)&sB_h[off + cr * CLDA + k0 + 8];
                bl[0] = *(const uint32_t*)&sB_l[off + cr * CLDA + k0];
                bl[1] = *(const uint32_t*)&sB_l[off + cr * CLDA + k0 + 8];
#pragma unroll
                for (int mf = 0; mf < 2; mf++) {
                    mma_bf16(acc[mf][nf], ah[mf], bh);
                    mma_bf16(acc[mf][nf], al[mf], bh);
                    mma_bf16(acc[mf][nf], ah[mf], bl);
                }
            }
        }
    };

    cpB(0, 0); CP_COMMIT();
    ldgA(0); stsA(0);
    for (int kc = 0; kc < NC; kc++) {
        const int bf = kc & 1;
        const bool nxt = (kc + 1 < NC);
        if (nxt) {
            cpB((kc + 1) * 32, bf ^ 1); CP_COMMIT();
            ldgA((kc + 1) * 32);
            CP_WAIT1();
        } else {
            CP_WAIT0();
        }
        __syncthreads();
        domma(bf);
        if (nxt) stsA(bf ^ 1);
        __syncthreads();
    }

#pragma unroll
    for (int mf = 0; mf < 2; mf++)
#pragma unroll
        for (int nf = 0; nf < 8; nf++)
#pragma unroll
            for (int e = 0; e < 4; e++) {
                int row = wm * 32 + mf * 16 + lr + (e >> 1) * 8;
                int oc = wn * 64 + nf * 8 + lc * 2 + (e & 1);
                float v = acc[mf][nf][e] + biasS[oc];
                if (RELU) v = fmaxf(v, 0.f);
                size_t addr;
                if (MODE == 0) {
                    int px = pxbase + row;
                    addr = ((size_t)(b * 128 + oc) * 64 + (px >> 6)) * 64 + (px & 63);
                } else {
                    int oh = (1 - ohp) + 2 * (j0 + (row >> 6));
                    int ow = (1 - owp) + 2 * (row & 63);
                    addr = ((size_t)(b * 128 + oc) * 128 + oh) * 128 + ow;
                }
                if (OUTMODE == 0) {
                    outf[addr] = v;
                } else {
                    __nv_bfloat16 h = __float2bfloat16(v);
                    outh[addr] = h;
                    outl[addr] = __float2bfloat16(v - __bfloat162float(h));
                }
            }
}

// =====================================================================
// generic h/l split (weights, z, codebook)
// =====================================================================
__global__ void wsplit(const float* __restrict__ w, __nv_bfloat16* __restrict__ wh,
                       __nv_bfloat16* __restrict__ wl, int n)
{
    int i = blockIdx.x * 256 + threadIdx.x;
    if (i >= n) return;
    float x = w[i];
    __nv_bfloat16 h = __float2bfloat16(x);
    wh[i] = h;
    wl[i] = __float2bfloat16(x - __bfloat162float(h));
}

__global__ void pack_wt2(const float* __restrict__ w, __nv_bfloat16* __restrict__ wh,
                         __nv_bfloat16* __restrict__ wl)
{
    int i = blockIdx.x * 256 + threadIdx.x;      // over 4*128*512
    int cls = i >> 16;
    int oc = (i >> 9) & 127;
    int r = i & 511;
    int ohp = cls >> 1, owp = cls & 1;
    int ic = r >> 2, th = (r >> 1) & 1, tw = r & 1;
    float x = w[((ic * 128 + oc) * 4 + ohp + 2 * th) * 4 + owp + 2 * tw];
    __nv_bfloat16 h = __float2bfloat16(x);
    wh[i] = h;
    wl[i] = __float2bfloat16(x - __bfloat162float(h));
}

// =====================================================================
// row squared-norm (exact R1 arithmetic)
// =====================================================================
__global__ void rownorm_kernel(const float* __restrict__ v, float* __restrict__ outn, int rows)
{
    int warp = threadIdx.x >> 5, lane = threadIdx.x & 31;
    int n = blockIdx.x * 8 + warp;
    if (n >= rows) return;
    const float* p = v + (size_t)n * 256;
    float s = 0.f;
#pragma unroll
    for (int k = 0; k < 8; k++) { float x = p[lane + 32 * k]; s = fmaf(x, x, s); }
#pragma unroll
    for (int off = 16; off; off >>= 1) s += __shfl_down_sync(0xffffffffu, s, off);
    if (lane == 0) outn[n] = s;
}

__global__ void zero_commit_kernel(float* c) { *c = 0.f; }

// =====================================================================
// VQ GEMM + fused argmin — DEDUPED 4-plane continuous pipeline.
// K chunks of 16; per chunk: 3 MMA terms (zh*ch, zl*ch, zh*cl) from the
// same staged planes (33% less L2 traffic than packed K'=768). One sync
// per chunk, 4-stage cp.async, cnorm double-buffered.
// Accumulation order differs from R3 (interleaved per 16-K chunk) —
// ~1e-8 dot perturbation; R1->R3 evidence says index margins tolerate it.
// smem (dynamic, 101888 B):
//   [0)      sAh 4 x 6144   [24576) sAl 4 x 6144
//   [49152)  sBh 4 x 6144   [73728) sBl 4 x 6144
//   [98304)  znS 128 f32    [98816) cnS 2 x 128 f32
//   [99840)  redV 2x128 f32 [100864) redI 2x128 int
// =====================================================================
#define VLDA 24
#define VQ_SMEM 101888

__global__ __launch_bounds__(256, 2)
void vq_mma4(const __nv_bfloat16* __restrict__ zh, const __nv_bfloat16* __restrict__ zl,
             const __nv_bfloat16* __restrict__ ch, const __nv_bfloat16* __restrict__ cl,
             const float* __restrict__ znorm, const float* __restrict__ cnorm,
             float* __restrict__ bv8, int* __restrict__ bi8)
{
    extern __shared__ __align__(16) char sm[];
    __nv_bfloat16* sAh = (__nv_bfloat16*)(sm);
    __nv_bfloat16* sAl = (__nv_bfloat16*)(sm + 24576);
    __nv_bfloat16* sBh = (__nv_bfloat16*)(sm + 49152);
    __nv_bfloat16* sBl = (__nv_bfloat16*)(sm + 73728);
    float* znS = (float*)(sm + 98304);
    float* cnS = (float*)(sm + 98816);
    float* redV = (float*)(sm + 99840);
    int*   redI = (int*)(sm + 100864);

    const int tid = threadIdx.x;
    const int lane = tid & 31, wid = tid >> 5;
    const int wm = wid & 3, wn = wid >> 2;
    const int lr = lane >> 2, lc = lane & 3;
    const int qbase = blockIdx.x * 128;
    const int gbase = blockIdx.y * 1024;

    if (tid < 128) znS[tid] = znorm[qbase + tid];

    const int srow = tid >> 1, shalf = tid & 1;
    const uint32_t dstRow = (uint32_t)(srow * (VLDA * 2) + shalf * 16);
    const size_t aRow = (size_t)(qbase + srow) * 256 + shalf * 8;

    const uint32_t sah = s2u(sAh), sal = s2u(sAl);
    const uint32_t sbh = s2u(sBh), sbl = s2u(sBl);

    auto stage = [&](int g) {
        const int nt = g >> 4, kc = g & 15;
        const uint32_t d = (uint32_t)(g & 3) * 6144 + dstRow;
        const size_t ao = aRow + kc * 16;
        const size_t bo = (size_t)(gbase + nt * 128 + srow) * 256 + kc * 16 + shalf * 8;
        CP16(sah + d, zh + ao);
        CP16(sal + d, zl + ao);
        CP16(sbh + d, ch + bo);
        CP16(sbl + d, cl + bo);
        CP_COMMIT();
    };

    stage(0);
    stage(1);
    __syncthreads();            // znS visible
    float znr[4];
#pragma unroll
    for (int s = 0; s < 4; s++)
        znr[s] = znS[wm * 32 + (s >> 1) * 16 + lr + (s & 1) * 8];

    float bestv[4] = {3.4e38f, 3.4e38f, 3.4e38f, 3.4e38f};
    int   besti[4] = {0, 0, 0, 0};

    float acc[2][8][4];
#pragma unroll
    for (int mf = 0; mf < 2; mf++)
#pragma unroll
        for (int nf = 0; nf < 8; nf++)
#pragma unroll
            for (int e = 0; e < 4; e++) acc[mf][nf][e] = 0.f;

    for (int g = 0; g < 128; g++) {
        const int nt = g >> 4, kc = g & 15;

        if (kc == 0 && tid < 128)
            cnS[(nt & 1) * 128 + tid] = cnorm[gbase + nt * 128 + tid];

        if (g + 2 < 128) {
            stage(g + 2);
            CP_WAIT2();
        } else if (g + 1 < 128) {
            CP_WAIT1();
        } else {
            CP_WAIT0();
        }
        __syncthreads();

        const uint32_t off = (uint32_t)(g & 3) * 3072;   // elements
        const int k0 = lc * 2;
        uint32_t ah[2][4], al[2][4], bh[8][2], bl[8][2];
#pragma unroll
        for (int mf = 0; mf < 2; mf++) {
            int r = wm * 32 + mf * 16 + lr;
            ah[mf][0] = *(const uint32_t*)&sAh[off + r * VLDA + k0];
            ah[mf][1] = *(const uint32_t*)&sAh[off + (r + 8) * VLDA + k0];
            ah[mf][2] = *(const uint32_t*)&sAh[off + r * VLDA + k0 + 8];
            ah[mf][3] = *(const uint32_t*)&sAh[off + (r + 8) * VLDA + k0 + 8];
            al[mf][0] = *(const uint32_t*)&sAl[off + r * VLDA + k0];
            al[mf][1] = *(const uint32_t*)&sAl[off + (r + 8) * VLDA + k0];
            al[mf][2] = *(const uint32_t*)&sAl[off + r * VLDA + k0 + 8];
            al[mf][3] = *(const uint32_t*)&sAl[off + (r + 8) * VLDA + k0 + 8];
        }
#pragma unroll
        for (int nf = 0; nf < 8; nf++) {
            int cr = wn * 64 + nf * 8 + lr;
            bh[nf][0] = *(const uint32_t*)&sBh[off + cr * VLDA + k0];
            bh[nf][1] = *(const uint32_t*)&sBh[off + cr * VLDA + k0 + 8];
            bl[nf][0] = *(const uint32_t*)&sBl[off + cr * VLDA + k0];
            bl[nf][1] = *(const uint32_t*)&sBl[off + cr * VLDA + k0 + 8];
        }
        // term order per chunk: hh, lh, hl (deterministic chain)
#pragma unroll
        for (int mf = 0; mf < 2; mf++)
#pragma unroll
            for (int nf = 0; nf < 8; nf++)
                mma_bf16(acc[mf][nf], ah[mf], bh[nf]);
#pragma unroll
        for (int mf = 0; mf < 2; mf++)
#pragma unroll
            for (int nf = 0; nf < 8; nf++)
                mma_bf16(acc[mf][nf], al[mf], bh[nf]);
#pragma unroll
        for (int mf = 0; mf < 2; mf++)
#pragma unroll
            for (int nf = 0; nf < 8; nf++)
                mma_bf16(acc[mf][nf], ah[mf], bl[nf]);

        if (kc == 15) {
            const float* cns = cnS + (nt & 1) * 128;
#pragma unroll
            for (int mf = 0; mf < 2; mf++)
#pragma unroll
                for (int nf = 0; nf < 8; nf++)
#pragma unroll
                    for (int e = 0; e < 4; e++) {
                        int h = e >> 1;
                        int col = wn * 64 + nf * 8 + lc * 2 + (e & 1);
                        int slot = mf * 2 + h;
                        float t = znr[slot] + cns[col];
                        float s = fmaf(-2.f, acc[mf][nf][e], t);
                        int code = gbase + nt * 128 + col;
                        if (s < bestv[slot]) { bestv[slot] = s; besti[slot] = code; }
                        acc[mf][nf][e] = 0.f;
                    }
        }
    }

#pragma unroll
    for (int s = 0; s < 4; s++) {
        float v = bestv[s]; int ix = besti[s];
#pragma unroll
        for (int off2 = 1; off2 <= 2; off2 <<= 1) {
            float ov = __shfl_xor_sync(0xffffffffu, v, off2);
            int   oi = __shfl_xor_sync(0xffffffffu, ix, off2);
            if (ov < v || (ov == v && oi < ix)) { v = ov; ix = oi; }
        }
        if (lc == 0) {
            int row = wm * 32 + (s >> 1) * 16 + lr + (s & 1) * 8;
            redV[wn * 128 + row] = v; redI[wn * 128 + row] = ix;
        }
    }
    __syncthreads();
    if (tid < 128) {
        float v = redV[tid]; int ix = redI[tid];
        float v1 = redV[128 + tid]; int i1 = redI[128 + tid];
        if (v1 < v || (v1 == v && i1 < ix)) { v = v1; ix = i1; }
        bv8[blockIdx.y * NQ + qbase + tid] = v;
        bi8[blockIdx.y * NQ + qbase + tid] = ix;
    }
}

__global__ void vq_combine8(const float* __restrict__ bv8, const int* __restrict__ bi8,
                            int* __restrict__ idx)
{
    int q = blockIdx.x * 256 + threadIdx.x;
    if (q >= NQ) return;
    float v = bv8[q]; int ix = bi8[q];
#pragma unroll
    for (int g = 1; g < 8; g++) {
        float v2 = bv8[g * NQ + q];
        int   i2 = bi8[g * NQ + q];
        if (v2 < v || (v2 == v && i2 < ix)) { v = v2; ix = i2; }
    }
    idx[q] = ix;
}

// =====================================================================
// gather quant = codebook[idx], commit loss
// =====================================================================
__global__ __launch_bounds__(256)
void gather_commit(const float* __restrict__ cb, const float* __restrict__ z,
                   const int* __restrict__ idx, float* __restrict__ quant,
                   float* __restrict__ commit)
{
    int n = blockIdx.x;
    int t = threadIdx.x;
    int id = idx[n];
    float q = cb[(size_t)id * 256 + t];
    float zv = z[(size_t)n * 256 + t];
    quant[(size_t)n * 256 + t] = q;
    float d = q - zv; d *= d;
#pragma unroll
    for (int off = 16; off; off >>= 1) d += __shfl_down_sync(0xffffffffu, d, off);
    __shared__ float wsum[8];
    int warp = t >> 5, lane = t & 31;
    if (lane == 0) wsum[warp] = d;
    __syncthreads();
    if (t == 0) {
        float s = 0.f;
#pragma unroll
        for (int w = 0; w < 8; w++) s += wsum[w];
        atomicAdd(commit, s);
    }
}

// =====================================================================
// Final transposed conv (128 -> 3 channels) straight into d_out.
// =====================================================================
__global__ __launch_bounds__(256)
void convt_out3(const float* __restrict__ in, const float* __restrict__ w,
                const float* __restrict__ bias, float* __restrict__ out)
{
    __shared__ float ws[128 * 3 * 16];
    for (int i = threadIdx.x; i < 6144; i += 256) ws[i] = w[i];
    __syncthreads();

    int b = blockIdx.y, oh = blockIdx.x, ow = threadIdx.x;
    int ih0 = (oh + 1) >> 1, kh0 = (oh + 1) & 1;
    int iw0 = (ow + 1) >> 1, kw0 = (ow + 1) & 1;

    float acc0 = 0.f, acc1 = 0.f, acc2 = 0.f;
#pragma unroll 4
    for (int ic = 0; ic < 128; ic++) {
        const float* inp = in + ((size_t)(b * 128 + ic)) * 128 * 128;
        const float* wp = ws + ic * 48;
#pragma unroll
        for (int th = 0; th < 2; th++) {
            int ih = ih0 - th;
            if ((unsigned)ih < 128u) {
                int kh = kh0 + 2 * th;
#pragma unroll
                for (int tw = 0; tw < 2; tw++) {
                    int iw = iw0 - tw;
                    if ((unsigned)iw < 128u) {
                        int kw = kw0 + 2 * tw;
                        float v = inp[ih * 128 + iw];
                        int wk = kh * 4 + kw;
                        acc0 = fmaf(v, wp[wk], acc0);
                        acc1 = fmaf(v, wp[16 + wk], acc1);
                        acc2 = fmaf(v, wp[32 + wk], acc2);
                    }
                }
            }
        }
    }
    size_t ob = ((size_t)(b * 3) * 256 + oh) * 256 + ow;
    out[ob]          = acc0 + bias[0];
    out[ob + 65536]  = acc1 + bias[1];
    out[ob + 131072] = acc2 + bias[2];
}

__global__ void pack_kernel(float* __restrict__ out, const float* __restrict__ commit,
                            const int* __restrict__ idx)
{
    int i = blockIdx.x * 256 + threadIdx.x;
    if (i == 0) out[786432] = (*commit) * (1.f / 4194304.f);
    if (i < NQ) out[786433 + i] = (float)idx[i];
}

// =====================================================================
// host launcher
// =====================================================================
#define CMMA_SMEM 82432

extern "C" void kernel_launch(void* const* d_in, const int* in_sizes, int n_in,
                              void* d_out, int out_size)
{
    const float* x        = (const float*)d_in[0];
    const float* enc_w1   = (const float*)d_in[1];
    const float* enc_b1   = (const float*)d_in[2];
    const float* enc_w2   = (const float*)d_in[3];
    const float* enc_b2   = (const float*)d_in[4];
    const float* enc_w3   = (const float*)d_in[5];
    const float* enc_b3   = (const float*)d_in[6];
    const float* qconv_w  = (const float*)d_in[7];
    const float* qconv_b  = (const float*)d_in[8];
    const float* codebook = (const float*)d_in[9];
    const float* pqconv_w = (const float*)d_in[10];
    const float* pqconv_b = (const float*)d_in[11];
    const float* dec_w1   = (const float*)d_in[12];
    const float* dec_b1   = (const float*)d_in[13];
    const float* dect_w2  = (const float*)d_in[14];
    const float* dect_b2  = (const float*)d_in[15];
    const float* dect_w3  = (const float*)d_in[16];
    const float* dect_b3  = (const float*)d_in[17];
    float* out = (float*)d_out;

    float *h1, *h2, *h3, *z, *quant, *d2, *znorm, *cnorm, *commit, *bv8;
    float *w2t, *w3t, *wqt, *wpt;
    __nv_bfloat16 *qh, *ql, *d1h, *d1l;
    __nv_bfloat16 *zh, *zl, *chp, *clp;
    __nv_bfloat16 *wd1h, *wd1l, *wt2h, *wt2l;
    int *idx, *bi8;
    cudaGetSymbolAddress((void**)&h1, g_h1);
    cudaGetSymbolAddress((void**)&h2, g_h2);
    cudaGetSymbolAddress((void**)&h3, g_h3);
    cudaGetSymbolAddress((void**)&z, g_z);
    cudaGetSymbolAddress((void**)&quant, g_quant);
    cudaGetSymbolAddress((void**)&qh, g_qh);
    cudaGetSymbolAddress((void**)&ql, g_ql);
    cudaGetSymbolAddress((void**)&d1h, g_d1h);
    cudaGetSymbolAddress((void**)&d1l, g_d1l);
    cudaGetSymbolAddress((void**)&d2, g_d2);
    cudaGetSymbolAddress((void**)&znorm, g_znorm);
    cudaGetSymbolAddress((void**)&cnorm, g_cnorm);
    cudaGetSymbolAddress((void**)&idx, g_idx);
    cudaGetSymbolAddress((void**)&commit, g_commit);
    cudaGetSymbolAddress((void**)&zh, g_zh);   cudaGetSymbolAddress((void**)&zl, g_zl);
    cudaGetSymbolAddress((void**)&chp, g_ch);  cudaGetSymbolAddress((void**)&clp, g_cl);
    cudaGetSymbolAddress((void**)&bv8, g_bv8);
    cudaGetSymbolAddress((void**)&bi8, g_bi8);
    cudaGetSymbolAddress((void**)&wd1h, g_wd1h); cudaGetSymbolAddress((void**)&wd1l, g_wd1l);
    cudaGetSymbolAddress((void**)&wt2h, g_wt2h); cudaGetSymbolAddress((void**)&wt2l, g_wt2l);
    cudaGetSymbolAddress((void**)&w2t, g_w2t);   cudaGetSymbolAddress((void**)&w3t, g_w3t);
    cudaGetSymbolAddress((void**)&wqt, g_wqt);   cudaGetSymbolAddress((void**)&wpt, g_wpt);

    cudaFuncSetAttribute(conv_mma<0,3,1,1,true ,1>, cudaFuncAttributeMaxDynamicSharedMemorySize, CMMA_SMEM);
    cudaFuncSetAttribute(conv_mma<1,4,2,1,true ,0>, cudaFuncAttributeMaxDynamicSharedMemorySize, CMMA_SMEM);
    cudaFuncSetAttribute(vq_mma4, cudaFuncAttributeMaxDynamicSharedMemorySize, VQ_SMEM);

    // weight prep: fp32 chunk-major transposes + decoder splits + VQ codebook planes
    wtrans<<<1024, 256>>>(enc_w2, w2t, 2048, 128);
    wtrans<<<576, 256>>>(enc_w3, w3t, 1152, 128);
    wtrans<<<128, 256>>>(qconv_w, wqt, 128, 256);
    wtrans<<<128, 256>>>(pqconv_w, wpt, 256, 128);
    wsplit<<<576, 256>>>(dec_w1, wd1h, wd1l, 128 * 1152);
    pack_wt2<<<1024, 256>>>(dect_w2, wt2h, wt2l);
    wsplit<<<8192, 256>>>(codebook, chp, clp, KCB * EDIM);
    rownorm_kernel<<<1024, 256>>>(codebook, cnorm, KCB);
    zero_commit_kernel<<<1, 1>>>(commit);

    // encoder — enc1 dedicated; enc2/enc3/qconv on 4-stage async FFMA2
    conv_enc1<<<dim3(128,4),256>>>(x, enc_w1, enc_b1, h1);
    conv_async<4,2,1,true ,0,0><<<dim3(64,1,4),256>>>(h1, w2t, enc_b2, h2, nullptr, nullptr,
                                                      128,128, 128,128,  64, 64, 6);
    conv_async<3,1,1,false,0,0><<<dim3(64,1,4),256>>>(h2, w3t, enc_b3, h3, nullptr, nullptr,
                                                      128,128,  64, 64,  64, 64, 6);
    conv_async<1,1,0,false,0,1><<<dim3(64,2,4),256>>>(h3, wqt, qconv_b, z, nullptr, nullptr,
                                                      128,256,  64, 64,  64, 64, 6);

    // quantize — deduped 4-plane continuous-pipeline VQ
    wsplit<<<16384, 256>>>(z, zh, zl, NQ * EDIM);
    rownorm_kernel<<<2048, 256>>>(z, znorm, NQ);
    vq_mma4<<<dim3(128, 8), 256, VQ_SMEM>>>(zh, zl, chp, clp, znorm, cnorm, bv8, bi8);
    vq_combine8<<<64, 256>>>(bv8, bi8, idx);
    gather_commit<<<NQ, 256>>>(codebook, z, idx, quant, commit);

    // decoder — tensor-core bf16-split
    conv_async<1,1,0,false,1,2><<<dim3(64,1,4),256>>>(quant, wpt, pqconv_b, nullptr, qh, ql,
                                                      256, 128, 64,64, 64,64, 6);
    conv_mma<0,3,1,1,true ,1><<<dim3(32,1,4),256,CMMA_SMEM>>>(qh, ql, wd1h, wd1l, dec_b1,
                                                     nullptr, d1h, d1l, 128, 64, 64, 1152);
    conv_mma<1,4,2,1,true ,0><<<dim3(32,4,4),256,CMMA_SMEM>>>(d1h, d1l, wt2h, wt2l, dect_b2,
                                                     d2, nullptr, nullptr, 128, 64, 64, 512);
    convt_out3<<<dim3(256,4),256>>>(d2, dect_w3, dect_b3, out);

    pack_kernel<<<64, 256>>>(out, commit, idx);

    (void)in_sizes; (void)n_in; (void)out_size;
}

// round 17
// speedup vs baseline: 1.2777x; 1.0144x over previous
#include <cuda_runtime.h>
#include <cuda_bf16.h>
#include <cstdint>

// ---------------- problem constants ----------------
#define BATCH 4
#define NQ    16384
#define EDIM  256
#define KCB   8192

// ---------------- scratch (static device memory; no allocation) ----------------
__device__ float g_h1[4 * 128 * 128 * 128];
__device__ float g_h2[4 * 128 * 64 * 64];
__device__ float g_h3[4 * 128 * 64 * 64];
__device__ float g_z[NQ * EDIM];
__device__ __nv_bfloat16 g_qh[4 * 128 * 64 * 64];
__device__ __nv_bfloat16 g_ql[4 * 128 * 64 * 64];
__device__ __nv_bfloat16 g_d1h[4 * 128 * 64 * 64];
__device__ __nv_bfloat16 g_d1l[4 * 128 * 64 * 64];
__device__ float g_d2[4 * 128 * 128 * 128];
__device__ float g_znorm[NQ];
__device__ float g_cnorm[KCB];
__device__ int   g_idx[NQ];
__device__ float g_commit;
// VQ split planes (deduplicated: zh,zl,ch,cl)
__device__ __nv_bfloat16 g_zh[(size_t)NQ * EDIM],  g_zl[(size_t)NQ * EDIM];
__device__ __nv_bfloat16 g_ch[(size_t)KCB * EDIM], g_cl[(size_t)KCB * EDIM];
__device__ float g_bv8[8 * NQ];
__device__ int   g_bi8[8 * NQ];
// pre-split decoder weights
__device__ __nv_bfloat16 g_wd1h[128 * 1152], g_wd1l[128 * 1152];
__device__ __nv_bfloat16 g_wt2h[4 * 128 * 512], g_wt2l[4 * 128 * 512];
// chunk-major transposed fp32 weights for async FFMA convs
__device__ float g_w2t[128 * 2048];
__device__ float g_w3t[128 * 1152];
__device__ float g_wqt[256 * 128];
__device__ float g_wpt[128 * 256];

__device__ __forceinline__ uint32_t s2u(const void* p)
{
    uint32_t a;
    asm("{ .reg .u64 t; cvta.to.shared.u64 t, %1; cvt.u32.u64 %0, t; }" : "=r"(a) : "l"(p));
    return a;
}

#define CP16(dst, src) \
    asm volatile("cp.async.cg.shared.global [%0], [%1], 16;" :: "r"(dst), "l"(src) : "memory")
#define CP4Z(dst, src, sz) \
    asm volatile("cp.async.ca.shared.global [%0], [%1], 4, %2;" :: "r"(dst), "l"(src), "r"(sz) : "memory")
#define CP_COMMIT() asm volatile("cp.async.commit_group;" ::: "memory")
#define CP_WAIT2()  asm volatile("cp.async.wait_group 2;" ::: "memory")
#define CP_WAIT1()  asm volatile("cp.async.wait_group 1;" ::: "memory")
#define CP_WAIT0()  asm volatile("cp.async.wait_group 0;" ::: "memory")

__device__ __forceinline__ void mma_bf16(float* c, const uint32_t* a, const uint32_t* b)
{
    asm volatile(
        "mma.sync.aligned.m16n8k16.row.col.f32.bf16.bf16.f32 "
        "{%0,%1,%2,%3}, {%4,%5,%6,%7}, {%8,%9}, {%0,%1,%2,%3};"
        : "+f"(c[0]), "+f"(c[1]), "+f"(c[2]), "+f"(c[3])
        : "r"(a[0]), "r"(a[1]), "r"(a[2]), "r"(a[3]), "r"(b[0]), "r"(b[1]));
}

__device__ __forceinline__ void ffma2(uint64_t& acc, uint64_t wp, uint64_t xx)
{
    asm("fma.rn.f32x2 %0, %1, %2, %0;" : "+l"(acc) : "l"(wp), "l"(xx));
}

// =====================================================================
// megaprep: all weight/codebook prep fused into one kernel (R16 piece — values
// identical to R15 standalone kernels).
// =====================================================================
__device__ __forceinline__ void wtrans_body(const float* __restrict__ w,
                                            float* __restrict__ wt, int R, int Cout,
                                            int lb, int tid)
{
    int i = lb * 256 + tid;
    if (i >= Cout * R) return;
    int ocl = i & 127;
    int rest = i >> 7;
    int r = rest & 15;
    int chunkAll = rest >> 4;
    int NC = R >> 4;
    int ot = chunkAll / NC;
    int c = chunkAll - ot * NC;
    wt[i] = w[(size_t)(ot * 128 + ocl) * R + c * 16 + r];
}

__device__ __forceinline__ void wsplit_body(const float* __restrict__ w,
                                            __nv_bfloat16* __restrict__ wh,
                                            __nv_bfloat16* __restrict__ wl, int n,
                                            int lb, int tid)
{
    int i = lb * 256 + tid;
    if (i >= n) return;
    float x = w[i];
    __nv_bfloat16 h = __float2bfloat16(x);
    wh[i] = h;
    wl[i] = __float2bfloat16(x - __bfloat162float(h));
}

__global__ void megaprep(const float* __restrict__ enc_w2, const float* __restrict__ enc_w3,
                         const float* __restrict__ qconv_w, const float* __restrict__ pqconv_w,
                         const float* __restrict__ dec_w1, const float* __restrict__ dect_w2,
                         const float* __restrict__ codebook,
                         float* __restrict__ w2t, float* __restrict__ w3t,
                         float* __restrict__ wqt, float* __restrict__ wpt,
                         __nv_bfloat16* __restrict__ wd1h, __nv_bfloat16* __restrict__ wd1l,
                         __nv_bfloat16* __restrict__ wt2h, __nv_bfloat16* __restrict__ wt2l,
                         __nv_bfloat16* __restrict__ chp, __nv_bfloat16* __restrict__ clp,
                         float* __restrict__ cnorm, float* __restrict__ commit)
{
    int bx = blockIdx.x;
    int tid = threadIdx.x;
    if (bx < 1024) { wtrans_body(enc_w2, w2t, 2048, 128, bx, tid); return; }
    bx -= 1024;
    if (bx < 576) { wtrans_body(enc_w3, w3t, 1152, 128, bx, tid); return; }
    bx -= 576;
    if (bx < 128) { wtrans_body(qconv_w, wqt, 128, 256, bx, tid); return; }
    bx -= 128;
    if (bx < 128) { wtrans_body(pqconv_w, wpt, 256, 128, bx, tid); return; }
    bx -= 128;
    if (bx < 576) { wsplit_body(dec_w1, wd1h, wd1l, 128 * 1152, bx, tid); return; }
    bx -= 576;
    if (bx < 1024) {
        int i = bx * 256 + tid;      // over 4*128*512
        int cls = i >> 16;
        int oc = (i >> 9) & 127;
        int r = i & 511;
        int ohp = cls >> 1, owp = cls & 1;
        int ic = r >> 2, th = (r >> 1) & 1, tw = r & 1;
        float x = dect_w2[((ic * 128 + oc) * 4 + ohp + 2 * th) * 4 + owp + 2 * tw];
        __nv_bfloat16 h = __float2bfloat16(x);
        wt2h[i] = h;
        wt2l[i] = __float2bfloat16(x - __bfloat162float(h));
        return;
    }
    bx -= 1024;
    if (bx < 8192) { wsplit_body(codebook, chp, clp, KCB * EDIM, bx, tid); return; }
    bx -= 8192;
    if (bx < 1024) {
        int warp = tid >> 5, lane = tid & 31;
        int n = bx * 8 + warp;
        const float* p = codebook + (size_t)n * 256;
        float s = 0.f;
#pragma unroll
        for (int k = 0; k < 8; k++) { float x = p[lane + 32 * k]; s = fmaf(x, x, s); }
#pragma unroll
        for (int off = 16; off; off >>= 1) s += __shfl_down_sync(0xffffffffu, s, off);
        if (lane == 0) cnorm[n] = s;
        return;
    }
    bx -= 1024;
    if (bx == 0 && tid == 0) *commit = 0.f;
}
#define MEGAPREP_BLOCKS (1024 + 576 + 128 + 128 + 576 + 1024 + 8192 + 1024 + 1)

// =====================================================================
// fused z split + rownorm (values & norm chains identical to R15 pair)
// =====================================================================
__global__ void zsplit_norm(const float* __restrict__ z, __nv_bfloat16* __restrict__ zh,
                            __nv_bfloat16* __restrict__ zl, float* __restrict__ outn)
{
    int warp = threadIdx.x >> 5, lane = threadIdx.x & 31;
    int n = blockIdx.x * 8 + warp;
    const float* p = z + (size_t)n * 256;
    float s = 0.f;
#pragma unroll
    for (int k = 0; k < 8; k++) {
        float x = p[lane + 32 * k];
        __nv_bfloat16 h = __float2bfloat16(x);
        zh[(size_t)n * 256 + lane + 32 * k] = h;
        zl[(size_t)n * 256 + lane + 32 * k] = __float2bfloat16(x - __bfloat162float(h));
        s = fmaf(x, x, s);
    }
#pragma unroll
    for (int off = 16; off; off >>= 1) s += __shfl_down_sync(0xffffffffu, s, off);
    if (lane == 0) outn[n] = s;
}

// =====================================================================
// Dedicated enc1 kernel (R9 — passing; h1 bitwise identical)
// =====================================================================
__global__ __launch_bounds__(256)
void conv_enc1(const float* __restrict__ x, const float* __restrict__ w,
               const float* __restrict__ bias, float* __restrict__ out)
{
    __shared__ __align__(16) float ws[48][128];
    __shared__ __align__(16) float xs[48][128];

    const int tid = threadIdx.x;
    const int oh = blockIdx.x;
    const int b = blockIdx.y;

#pragma unroll
    for (int i = 0; i < 24; i++) {
        int idx = tid + i * 256;
        int r = idx >> 7, oc = idx & 127;
        ws[r][oc] = w[oc * 48 + r];
    }
#pragma unroll
    for (int i = 0; i < 24; i++) {
        int idx = tid + i * 256;
        int r = idx >> 7, p = idx & 127;
        int ic = r >> 4, kh = (r >> 2) & 3, kw = r & 3;
        int ih = oh * 2 + kh - 1;
        int iw = p * 2 + kw - 1;
        float v = 0.f;
        if ((unsigned)ih < 256u && (unsigned)iw < 256u)
            v = x[((size_t)(b * 3 + ic) * 256 + ih) * 256 + iw];
        xs[r][p] = v;
    }
    __syncthreads();

    const int tx = tid & 15;
    const int ty = tid >> 4;
    const uint32_t wsb = s2u(ws) + ty * 32;

    uint64_t acc2[4][8];
#pragma unroll
    for (int pq = 0; pq < 4; pq++)
#pragma unroll
        for (int i = 0; i < 8; i++) acc2[pq][i] = 0ull;

#pragma unroll 4
    for (int k = 0; k < 48; k++) {
        uint64_t wp0, wp1, wp2, wp3;
        asm("ld.shared.v2.u64 {%0,%1}, [%2];"
            : "=l"(wp0), "=l"(wp1) : "r"(wsb + (uint32_t)(k * 512)));
        asm("ld.shared.v2.u64 {%0,%1}, [%2];"
            : "=l"(wp2), "=l"(wp3) : "r"(wsb + (uint32_t)(k * 512 + 16)));
        float4 xv0 = *reinterpret_cast<const float4*>(&xs[k][tx * 8]);
        float4 xv1 = *reinterpret_cast<const float4*>(&xs[k][tx * 8 + 4]);
        uint64_t xx[8];
        asm("mov.b64 %0, {%1,%1};" : "=l"(xx[0]) : "f"(xv0.x));
        asm("mov.b64 %0, {%1,%1};" : "=l"(xx[1]) : "f"(xv0.y));
        asm("mov.b64 %0, {%1,%1};" : "=l"(xx[2]) : "f"(xv0.z));
        asm("mov.b64 %0, {%1,%1};" : "=l"(xx[3]) : "f"(xv0.w));
        asm("mov.b64 %0, {%1,%1};" : "=l"(xx[4]) : "f"(xv1.x));
        asm("mov.b64 %0, {%1,%1};" : "=l"(xx[5]) : "f"(xv1.y));
        asm("mov.b64 %0, {%1,%1};" : "=l"(xx[6]) : "f"(xv1.z));
        asm("mov.b64 %0, {%1,%1};" : "=l"(xx[7]) : "f"(xv1.w));
#pragma unroll
        for (int i = 0; i < 8; i++) {
            ffma2(acc2[0][i], wp0, xx[i]);
            ffma2(acc2[1][i], wp1, xx[i]);
            ffma2(acc2[2][i], wp2, xx[i]);
            ffma2(acc2[3][i], wp3, xx[i]);
        }
    }

#pragma unroll
    for (int pq = 0; pq < 4; pq++)
#pragma unroll
        for (int half = 0; half < 2; half++) {
            int oc = ty * 8 + 2 * pq + half;
            float bv = bias[oc];
            float* op = out + ((size_t)(b * 128 + oc) * 128 + oh) * 128 + tx * 8;
#pragma unroll
            for (int i = 0; i < 8; i++) {
                uint32_t bits = half ? (uint32_t)(acc2[pq][i] >> 32)
                                     : (uint32_t)(acc2[pq][i] & 0xffffffffull);
                float v = __uint_as_float(bits) + bv;
                op[i] = fmaxf(v, 0.f);
            }
        }
}

// =====================================================================
// FFMA2 implicit-GEMM conv with cp.async 4-STAGE pipeline.
// INL: 0 = NCHW f32, 1 = [n][Cin] f32, 2 = codebook gather via idx
// (identical staged values to reading quant). OUTL: 0/1/2 as before.
// =====================================================================
template<int KK, int S, int P, bool RELU, int INL, int OUTL>
__global__ __launch_bounds__(256)
void conv_async(const float* __restrict__ in, const float* __restrict__ wt,
                const float* __restrict__ bias, float* __restrict__ out,
                __nv_bfloat16* __restrict__ outh, __nv_bfloat16* __restrict__ outl,
                int Cin, int Cout, int Hin, int Win, int Hout, int Wout,
                int woutShift, const int* __restrict__ idxp)
{
    const int R = Cin * KK * KK;
    const int NC = R >> 4;
    const int b = blockIdx.z;
    const int ot = blockIdx.y;
    const int oc0 = ot * 128;
    const int pxbase = blockIdx.x * 64;

    __shared__ __align__(16) float ws[4][16][128];
    __shared__ __align__(16) float xs[4][16][68];

    const int tid = threadIdx.x;
    const int tx = tid & 15;
    const int ty = tid >> 4;

    const uint32_t wsb0 = s2u(ws);
    const uint32_t xsb0 = s2u(xs);
    const uint32_t wdst = wsb0 + (uint32_t)tid * 32;
    const float* wsrc_base = wt + (size_t)ot * ((size_t)NC * 2048) + tid * 8;

    uint64_t acc2[4][4];
#pragma unroll
    for (int p = 0; p < 4; p++)
#pragma unroll
        for (int i = 0; i < 4; i++) acc2[p][i] = 0ull;

    auto stage = [&](int c, int bf) {
        const float* wsrc = wsrc_base + (size_t)c * 2048;
        uint32_t wd = wdst + (uint32_t)bf * 8192;
        CP16(wd, wsrc);
        CP16(wd + 16, wsrc + 4);
#pragma unroll
        for (int i2 = 0; i2 < 4; i2++) {
            int li = tid + i2 * 256;
            int r, p;
            if (INL >= 1) { r = li & 15; p = li >> 4; }
            else          { r = li >> 6; p = li & 63; }
            int rr = c * 16 + r;
            const float* src = in;
            int sz = 0;
            if (INL == 1) {
                int n = b * (Hout * Wout) + pxbase + p;
                src = in + (size_t)n * Cin + rr;
                sz = 4;
            } else if (INL == 2) {
                int n = b * (Hout * Wout) + pxbase + p;
                src = in + (size_t)idxp[n] * Cin + rr;
                sz = 4;
            } else {
                int ic = rr / (KK * KK);
                int kr = rr - ic * KK * KK;
                int kh = kr / KK, kw = kr - kh * KK;
                int px = pxbase + p;
                int oh = px >> woutShift;
                int ow = px & (Wout - 1);
                int ih = oh * S + kh - P;
                int iw = ow * S + kw - P;
                if ((unsigned)ih < (unsigned)Hin && (unsigned)iw < (unsigned)Win) {
                    src = in + ((size_t)(b * Cin + ic) * Hin + ih) * Win + iw;
                    sz = 4;
                }
            }
            uint32_t xd = xsb0 + (uint32_t)bf * 4352 + (uint32_t)((r * 68 + p) * 4);
            CP4Z(xd, src, sz);
        }
    };

    stage(0, 0); CP_COMMIT();
    if (NC > 1) { stage(1, 1); CP_COMMIT(); }

    for (int c = 0; c < NC; c++) {
        const int bf = c & 3;
        if (c + 2 < NC) {
            stage(c + 2, (c + 2) & 3); CP_COMMIT();
            CP_WAIT2();
        } else if (c + 1 < NC) {
            CP_WAIT1();
        } else {
            CP_WAIT0();
        }
        __syncthreads();

        const uint32_t wsb = wsb0 + (uint32_t)bf * 8192 + ty * 32;
        const float (*xsb)[68] = xs[bf];
#pragma unroll
        for (int k = 0; k < 16; k++) {
            float4 xv = *reinterpret_cast<const float4*>(&xsb[k][tx * 4]);
            uint64_t wp0, wp1, wp2, wp3;
            asm("ld.shared.v2.u64 {%0,%1}, [%2];"
                : "=l"(wp0), "=l"(wp1) : "r"(wsb + (uint32_t)(k * 512)));
            asm("ld.shared.v2.u64 {%0,%1}, [%2];"
                : "=l"(wp2), "=l"(wp3) : "r"(wsb + (uint32_t)(k * 512 + 16)));
            uint64_t xx0, xx1, xx2, xx3;
            asm("mov.b64 %0, {%1,%1};" : "=l"(xx0) : "f"(xv.x));
            asm("mov.b64 %0, {%1,%1};" : "=l"(xx1) : "f"(xv.y));
            asm("mov.b64 %0, {%1,%1};" : "=l"(xx2) : "f"(xv.z));
            asm("mov.b64 %0, {%1,%1};" : "=l"(xx3) : "f"(xv.w));
            ffma2(acc2[0][0], wp0, xx0); ffma2(acc2[0][1], wp0, xx1);
            ffma2(acc2[0][2], wp0, xx2); ffma2(acc2[0][3], wp0, xx3);
            ffma2(acc2[1][0], wp1, xx0); ffma2(acc2[1][1], wp1, xx1);
            ffma2(acc2[1][2], wp1, xx2); ffma2(acc2[1][3], wp1, xx3);
            ffma2(acc2[2][0], wp2, xx0); ffma2(acc2[2][1], wp2, xx1);
            ffma2(acc2[2][2], wp2, xx2); ffma2(acc2[2][3], wp2, xx3);
            ffma2(acc2[3][0], wp3, xx0); ffma2(acc2[3][1], wp3, xx1);
            ffma2(acc2[3][2], wp3, xx2); ffma2(acc2[3][3], wp3, xx3);
        }
    }

#pragma unroll
    for (int p = 0; p < 4; p++)
#pragma unroll
        for (int half = 0; half < 2; half++) {
            int j = 2 * p + half;
            int oc = oc0 + ty * 8 + j;
            float bv = bias[oc];
#pragma unroll
            for (int i = 0; i < 4; i++) {
                uint32_t bits = half ? (uint32_t)(acc2[p][i] >> 32)
                                     : (uint32_t)(acc2[p][i] & 0xffffffffull);
                float v = __uint_as_float(bits) + bv;
                if (RELU) v = fmaxf(v, 0.f);
                if (OUTL == 1) {
                    size_t n = (size_t)(b * (Hout * Wout) + pxbase + tx * 4 + i);
                    out[n * Cout + oc] = v;
                } else {
                    size_t addr = (size_t)(b * Cout + oc) * (Hout * Wout) + pxbase + tx * 4 + i;
                    if (OUTL == 0) {
                        out[addr] = v;
                    } else {
                        __nv_bfloat16 h = __float2bfloat16(v);
                        outh[addr] = h;
                        outl[addr] = __float2bfloat16(v - __bfloat162float(h));
                    }
                }
            }
        }
}

// =====================================================================
// Tensor-core implicit-GEMM conv, bf16 3-term split — DECODER ONLY.
// (unchanged — passing)
// =====================================================================
#define CLDA 40
#define ABUF 5120

template<int MODE, int KK, int S, int P, bool RELU, int OUTMODE>
__global__ __launch_bounds__(256)
void conv_mma(const __nv_bfloat16* __restrict__ xh, const __nv_bfloat16* __restrict__ xl,
              const __nv_bfloat16* __restrict__ wh_g, const __nv_bfloat16* __restrict__ wl_g,
              const float* __restrict__ bias,
              float* __restrict__ outf, __nv_bfloat16* __restrict__ outh,
              __nv_bfloat16* __restrict__ outl,
              int Cin, int Hin, int Win, int R)
{
    extern __shared__ __align__(16) char sm[];
    __nv_bfloat16* sA_h = (__nv_bfloat16*)(sm);
    __nv_bfloat16* sA_l = (__nv_bfloat16*)(sm + 20480);
    __nv_bfloat16* sB_h = (__nv_bfloat16*)(sm + 40960);
    __nv_bfloat16* sB_l = (__nv_bfloat16*)(sm + 61440);
    float* biasS = (float*)(sm + 81920);

    const int tid = threadIdx.x;
    const int lane = tid & 31, wid = tid >> 5;
    const int wm = wid & 3, wn = wid >> 2;
    const int lr = lane >> 2, lc = lane & 3;
    const int b = blockIdx.z;

    int pxbase = 0, j0 = 0, ohp = 0, owp = 0;
    const __nv_bfloat16* wh = wh_g;
    const __nv_bfloat16* wl = wl_g;
    if (MODE == 1) {
        j0 = blockIdx.x * 2;
        int cls = blockIdx.y;
        ohp = cls >> 1; owp = cls & 1;
        wh = wh_g + cls * (128 * 512);
        wl = wl_g + cls * (128 * 512);
    } else {
        pxbase = blockIdx.x * 128;
    }

    if (tid < 128) biasS[tid] = bias[tid];

    const int NC = R >> 5;

    const int boc = tid >> 1;
    const uint32_t sbBh = s2u(sB_h), sbBl = s2u(sB_l);
    const uint32_t bOff = (uint32_t)(boc * 80 + (tid & 1) * 32);
    const size_t bSrc = (size_t)boc * R + (tid & 1) * 16;

    const int kloc = tid & 31, pblk = tid >> 5;

    float acc[2][8][4];
#pragma unroll
    for (int mf = 0; mf < 2; mf++)
#pragma unroll
        for (int nf = 0; nf < 8; nf++)
#pragma unroll
            for (int e = 0; e < 4; e++) acc[mf][nf][e] = 0.f;

    __nv_bfloat16 pvh[16], pvl[16];

    auto cpB = [&](int r0, int bf) {
        uint32_t d = (uint32_t)bf * 10240;
        const __nv_bfloat16* sh = wh + bSrc + r0;
        const __nv_bfloat16* sl = wl + bSrc + r0;
        CP16(sbBh + d + bOff, sh);  CP16(sbBh + d + bOff + 16, sh + 8);
        CP16(sbBl + d + bOff, sl);  CP16(sbBl + d + bOff + 16, sl + 8);
    };

    auto ldgA = [&](int r0) {
        int r = r0 + kloc;
        if (MODE == 0) {
            int ic = r / (KK * KK);
            int rem = r - ic * KK * KK;
            int kh = rem / KK, kw = rem - kh * KK;
            int px = pxbase + pblk * 16;
            int oh = px >> 6, ow0 = px & 63;
            int ih = oh * S + kh - P;
            const size_t rowb = ((size_t)(b * Cin + ic) * Hin + ih) * Win;
            bool okh = (unsigned)ih < (unsigned)Hin;
#pragma unroll
            for (int i = 0; i < 16; i++) {
                int iw = (ow0 + i) * S + kw - P;
                bool ok = okh && (unsigned)iw < (unsigned)Win;
                pvh[i] = ok ? xh[rowb + iw] : __float2bfloat16(0.f);
                pvl[i] = ok ? xl[rowb + iw] : __float2bfloat16(0.f);
            }
        } else {
            int ic = r >> 2, th = (r >> 1) & 1, tw = r & 1;
            int j = j0 + (pblk >> 2);
            int i0 = (pblk & 3) * 16;
            int ih = j + (1 - ohp) - th;
            int iwb = i0 + (1 - owp) - tw;
            const size_t rowb = ((size_t)(b * Cin + ic) * 64 + ih) * 64;
            bool okh = (unsigned)ih < 64u;
#pragma unroll
            for (int i = 0; i < 16; i++) {
                int iw = iwb + i;
                bool ok = okh && (unsigned)iw < 64u;
                pvh[i] = ok ? xh[rowb + iw] : __float2bfloat16(0.f);
                pvl[i] = ok ? xl[rowb + iw] : __float2bfloat16(0.f);
            }
        }
    };

    auto stsA = [&](int bf) {
        int base = bf * ABUF + kloc;
#pragma unroll
        for (int i = 0; i < 16; i++) {
            int p = pblk * 16 + i;
            sA_h[base + p * CLDA] = pvh[i];
            sA_l[base + p * CLDA] = pvl[i];
        }
    };

    auto domma = [&](int bf) {
        const int off = bf * ABUF;
#pragma unroll
        for (int ks = 0; ks < 2; ks++) {
            const int k0 = ks * 16 + lc * 2;
            uint32_t ah[2][4], al[2][4];
#pragma unroll
            for (int mf = 0; mf < 2; mf++) {
                int r1 = wm * 32 + mf * 16 + lr;
                ah[mf][0] = *(const uint32_t*)&sA_h[off + r1 * CLDA + k0];
                ah[mf][1] = *(const uint32_t*)&sA_h[off + (r1 + 8) * CLDA + k0];
                ah[mf][2] = *(const uint32_t*)&sA_h[off + r1 * CLDA + k0 + 8];
                ah[mf][3] = *(const uint32_t*)&sA_h[off + (r1 + 8) * CLDA + k0 + 8];
                al[mf][0] = *(const uint32_t*)&sA_l[off + r1 * CLDA + k0];
                al[mf][1] = *(const uint32_t*)&sA_l[off + (r1 + 8) * CLDA + k0];
                al[mf][2] = *(const uint32_t*)&sA_l[off + r1 * CLDA + k0 + 8];
                al[mf][3] = *(const uint32_t*)&sA_l[off + (r1 + 8) * CLDA + k0 + 8];
            }
#pragma unroll
            for (int nf = 0; nf < 8; nf++) {
                int cr = wn * 64 + nf * 8 + lr;
                uint32_t bh[2], bl[2];
                bh[0] = *(const uint32_t*)&sB_h[off + cr * CLDA + k0];
                bh[1] = *(const uint32_t*)&sB_h[off + cr * CLDA + k0 + 8];
                bl[0] = *(const uint32_t*)&sB_l[off + cr * CLDA + k0];
                bl[1] = *(const uint32_t*)&sB_l[off + cr * CLDA + k0 + 8];
#pragma unroll
                for (int mf = 0; mf < 2; mf++) {
                    mma_bf16(acc[mf][nf], ah[mf], bh);
                    mma_bf16(acc[mf][nf], al[mf], bh);
                    mma_bf16(acc[mf][nf], ah[mf], bl);
                }
            }
        }
    };

    cpB(0, 0); CP_COMMIT();
    ldgA(0); stsA(0);
    for (int kc = 0; kc < NC; kc++) {
        const int bf = kc & 1;
        const bool nxt = (kc + 1 < NC);
        if (nxt) {
            cpB((kc + 1) * 32, bf ^ 1); CP_COMMIT();
            ldgA((kc + 1) * 32);
            CP_WAIT1();
        } else {
            CP_WAIT0();
        }
        __syncthreads();
        domma(bf);
        if (nxt) stsA(bf ^ 1);
        __syncthreads();
    }

#pragma unroll
    for (int mf = 0; mf < 2; mf++)
#pragma unroll
        for (int nf = 0; nf < 8; nf++)
#pragma unroll
            for (int e = 0; e < 4; e++) {
                int row = wm * 32 + mf * 16 + lr + (e >> 1) * 8;
                int oc = wn * 64 + nf * 8 + lc * 2 + (e & 1);
                float v = acc[mf][nf][e] + biasS[oc];
                if (RELU) v = fmaxf(v, 0.f);
                size_t addr;
                if (MODE == 0) {
                    int px = pxbase + row;
                    addr = ((size_t)(b * 128 + oc) * 64 + (px >> 6)) * 64 + (px & 63);
                } else {
                    int oh = (1 - ohp) + 2 * (j0 + (row >> 6));
                    int ow = (1 - owp) + 2 * (row & 63);
                    addr = ((size_t)(b * 128 + oc) * 128 + oh) * 128 + ow;
                }
                if (OUTMODE == 0) {
                    outf[addr] = v;
                } else {
                    __nv_bfloat16 h = __float2bfloat16(v);
                    outh[addr] = h;
                    outl[addr] = __float2bfloat16(v - __bfloat162float(h));
                }
            }
}

// =====================================================================
// VQ GEMM + fused argmin — R15-EXACT deduped 4-plane continuous pipeline
// (one chunk per sync, 2-chunk prefetch distance — the safe rotation).
// =====================================================================
#define VLDA 24
#define VQ_SMEM 101888

__global__ __launch_bounds__(256, 2)
void vq_mma4(const __nv_bfloat16* __restrict__ zh, const __nv_bfloat16* __restrict__ zl,
             const __nv_bfloat16* __restrict__ ch, const __nv_bfloat16* __restrict__ cl,
             const float* __restrict__ znorm, const float* __restrict__ cnorm,
             float* __restrict__ bv8, int* __restrict__ bi8)
{
    extern __shared__ __align__(16) char sm[];
    __nv_bfloat16* sAh = (__nv_bfloat16*)(sm);
    __nv_bfloat16* sAl = (__nv_bfloat16*)(sm + 24576);
    __nv_bfloat16* sBh = (__nv_bfloat16*)(sm + 49152);
    __nv_bfloat16* sBl = (__nv_bfloat16*)(sm + 73728);
    float* znS = (float*)(sm + 98304);
    float* cnS = (float*)(sm + 98816);
    float* redV = (float*)(sm + 99840);
    int*   redI = (int*)(sm + 100864);

    const int tid = threadIdx.x;
    const int lane = tid & 31, wid = tid >> 5;
    const int wm = wid & 3, wn = wid >> 2;
    const int lr = lane >> 2, lc = lane & 3;
    const int qbase = blockIdx.x * 128;
    const int gbase = blockIdx.y * 1024;

    if (tid < 128) znS[tid] = znorm[qbase + tid];

    const int srow = tid >> 1, shalf = tid & 1;
    const uint32_t dstRow = (uint32_t)(srow * (VLDA * 2) + shalf * 16);
    const size_t aRow = (size_t)(qbase + srow) * 256 + shalf * 8;

    const uint32_t sah = s2u(sAh), sal = s2u(sAl);
    const uint32_t sbh = s2u(sBh), sbl = s2u(sBl);

    auto stage = [&](int g) {
        const int nt = g >> 4, kc = g & 15;
        const uint32_t d = (uint32_t)(g & 3) * 6144 + dstRow;
        const size_t ao = aRow + kc * 16;
        const size_t bo = (size_t)(gbase + nt * 128 + srow) * 256 + kc * 16 + shalf * 8;
        CP16(sah + d, zh + ao);
        CP16(sal + d, zl + ao);
        CP16(sbh + d, ch + bo);
        CP16(sbl + d, cl + bo);
        CP_COMMIT();
    };

    stage(0);
    stage(1);
    __syncthreads();            // znS visible
    float znr[4];
#pragma unroll
    for (int s = 0; s < 4; s++)
        znr[s] = znS[wm * 32 + (s >> 1) * 16 + lr + (s & 1) * 8];

    float bestv[4] = {3.4e38f, 3.4e38f, 3.4e38f, 3.4e38f};
    int   besti[4] = {0, 0, 0, 0};

    float acc[2][8][4];
#pragma unroll
    for (int mf = 0; mf < 2; mf++)
#pragma unroll
        for (int nf = 0; nf < 8; nf++)
#pragma unroll
            for (int e = 0; e < 4; e++) acc[mf][nf][e] = 0.f;

    for (int g = 0; g < 128; g++) {
        const int nt = g >> 4, kc = g & 15;

        if (kc == 0 && tid < 128)
            cnS[(nt & 1) * 128 + tid] = cnorm[gbase + nt * 128 + tid];

        if (g + 2 < 128) {
            stage(g + 2);
            CP_WAIT2();
        } else if (g + 1 < 128) {
            CP_WAIT1();
        } else {
            CP_WAIT0();
        }
        __syncthreads();

        const uint32_t off = (uint32_t)(g & 3) * 3072;   // elements
        const int k0 = lc * 2;
        uint32_t a_h[2][4], a_l[2][4], b_h[8][2], b_l[8][2];
#pragma unroll
        for (int mf = 0; mf < 2; mf++) {
            int r = wm * 32 + mf * 16 + lr;
            a_h[mf][0] = *(const uint32_t*)&sAh[off + r * VLDA + k0];
            a_h[mf][1] = *(const uint32_t*)&sAh[off + (r + 8) * VLDA + k0];
            a_h[mf][2] = *(const uint32_t*)&sAh[off + r * VLDA + k0 + 8];
            a_h[mf][3] = *(const uint32_t*)&sAh[off + (r + 8) * VLDA + k0 + 8];
            a_l[mf][0] = *(const uint32_t*)&sAl[off + r * VLDA + k0];
            a_l[mf][1] = *(const uint32_t*)&sAl[off + (r + 8) * VLDA + k0];
            a_l[mf][2] = *(const uint32_t*)&sAl[off + r * VLDA + k0 + 8];
            a_l[mf][3] = *(const uint32_t*)&sAl[off + (r + 8) * VLDA + k0 + 8];
        }
#pragma unroll
        for (int nf = 0; nf < 8; nf++) {
            int cr = wn * 64 + nf * 8 + lr;
            b_h[nf][0] = *(const uint32_t*)&sBh[off + cr * VLDA + k0];
            b_h[nf][1] = *(const uint32_t*)&sBh[off + cr * VLDA + k0 + 8];
            b_l[nf][0] = *(const uint32_t*)&sBl[off + cr * VLDA + k0];
            b_l[nf][1] = *(const uint32_t*)&sBl[off + cr * VLDA + k0 + 8];
        }
        // term order per chunk: hh, lh, hl (deterministic chain)
#pragma unroll
        for (int mf = 0; mf < 2; mf++)
#pragma unroll
            for (int nf = 0; nf < 8; nf++)
                mma_bf16(acc[mf][nf], a_h[mf], b_h[nf]);
#pragma unroll
        for (int mf = 0; mf < 2; mf++)
#pragma unroll
            for (int nf = 0; nf < 8; nf++)
                mma_bf16(acc[mf][nf], a_l[mf], b_h[nf]);
#pragma unroll
        for (int mf = 0; mf < 2; mf++)
#pragma unroll
            for (int nf = 0; nf < 8; nf++)
                mma_bf16(acc[mf][nf], a_h[mf], b_l[nf]);

        if (kc == 15) {
            const float* cns = cnS + (nt & 1) * 128;
#pragma unroll
            for (int mf = 0; mf < 2; mf++)
#pragma unroll
                for (int nf = 0; nf < 8; nf++)
#pragma unroll
                    for (int e = 0; e < 4; e++) {
                        int h = e >> 1;
                        int col = wn * 64 + nf * 8 + lc * 2 + (e & 1);
                        int slot = mf * 2 + h;
                        float t = znr[slot] + cns[col];
                        float s = fmaf(-2.f, acc[mf][nf][e], t);
                        int code = gbase + nt * 128 + col;
                        if (s < bestv[slot]) { bestv[slot] = s; besti[slot] = code; }
                        acc[mf][nf][e] = 0.f;
                    }
        }
    }

#pragma unroll
    for (int s = 0; s < 4; s++) {
        float v = bestv[s]; int ix = besti[s];
#pragma unroll
        for (int off2 = 1; off2 <= 2; off2 <<= 1) {
            float ov = __shfl_xor_sync(0xffffffffu, v, off2);
            int   oi = __shfl_xor_sync(0xffffffffu, ix, off2);
            if (ov < v || (ov == v && oi < ix)) { v = ov; ix = oi; }
        }
        if (lc == 0) {
            int row = wm * 32 + (s >> 1) * 16 + lr + (s & 1) * 8;
            redV[wn * 128 + row] = v; redI[wn * 128 + row] = ix;
        }
    }
    __syncthreads();
    if (tid < 128) {
        float v = redV[tid]; int ix = redI[tid];
        float v1 = redV[128 + tid]; int i1 = redI[128 + tid];
        if (v1 < v || (v1 == v && i1 < ix)) { v = v1; ix = i1; }
        bv8[blockIdx.y * NQ + qbase + tid] = v;
        bi8[blockIdx.y * NQ + qbase + tid] = ix;
    }
}

__global__ void vq_combine8(const float* __restrict__ bv8, const int* __restrict__ bi8,
                            int* __restrict__ idx)
{
    int q = blockIdx.x * 256 + threadIdx.x;
    if (q >= NQ) return;
    float v = bv8[q]; int ix = bi8[q];
#pragma unroll
    for (int g = 1; g < 8; g++) {
        float v2 = bv8[g * NQ + q];
        int   i2 = bi8[g * NQ + q];
        if (v2 < v || (v2 == v && i2 < ix)) { v = v2; ix = i2; }
    }
    idx[q] = ix;
}

// =====================================================================
// commit loss only (quant buffer eliminated; pqconv gathers directly)
// =====================================================================
__global__ __launch_bounds__(256)
void commit_only(const float* __restrict__ cb, const float* __restrict__ z,
                 const int* __restrict__ idx, float* __restrict__ commit)
{
    int n = blockIdx.x;
    int t = threadIdx.x;
    int id = idx[n];
    float q = cb[(size_t)id * 256 + t];
    float zv = z[(size_t)n * 256 + t];
    float d = q - zv; d *= d;
#pragma unroll
    for (int off = 16; off; off >>= 1) d += __shfl_down_sync(0xffffffffu, d, off);
    __shared__ float wsum[8];
    int warp = t >> 5, lane = t & 31;
    if (lane == 0) wsum[warp] = d;
    __syncthreads();
    if (t == 0) {
        float s = 0.f;
#pragma unroll
        for (int w = 0; w < 8; w++) s += wsum[w];
        atomicAdd(commit, s);
    }
}

// =====================================================================
// Final transposed conv (128 -> 3 channels) straight into d_out.
// =====================================================================
__global__ __launch_bounds__(256)
void convt_out3(const float* __restrict__ in, const float* __restrict__ w,
                const float* __restrict__ bias, float* __restrict__ out)
{
    __shared__ float ws[128 * 3 * 16];
    for (int i = threadIdx.x; i < 6144; i += 256) ws[i] = w[i];
    __syncthreads();

    int b = blockIdx.y, oh = blockIdx.x, ow = threadIdx.x;
    int ih0 = (oh + 1) >> 1, kh0 = (oh + 1) & 1;
    int iw0 = (ow + 1) >> 1, kw0 = (ow + 1) & 1;

    float acc0 = 0.f, acc1 = 0.f, acc2 = 0.f;
#pragma unroll 4
    for (int ic = 0; ic < 128; ic++) {
        const float* inp = in + ((size_t)(b * 128 + ic)) * 128 * 128;
        const float* wp = ws + ic * 48;
#pragma unroll
        for (int th = 0; th < 2; th++) {
            int ih = ih0 - th;
            if ((unsigned)ih < 128u) {
                int kh = kh0 + 2 * th;
#pragma unroll
                for (int tw = 0; tw < 2; tw++) {
                    int iw = iw0 - tw;
                    if ((unsigned)iw < 128u) {
                        int kw = kw0 + 2 * tw;
                        float v = inp[ih * 128 + iw];
                        int wk = kh * 4 + kw;
                        acc0 = fmaf(v, wp[wk], acc0);
                        acc1 = fmaf(v, wp[16 + wk], acc1);
                        acc2 = fmaf(v, wp[32 + wk], acc2);
                    }
                }
            }
        }
    }
    size_t ob = ((size_t)(b * 3) * 256 + oh) * 256 + ow;
    out[ob]          = acc0 + bias[0];
    out[ob + 65536]  = acc1 + bias[1];
    out[ob + 131072] = acc2 + bias[2];
}

__global__ void pack_kernel(float* __restrict__ out, const float* __restrict__ commit,
                            const int* __restrict__ idx)
{
    int i = blockIdx.x * 256 + threadIdx.x;
    if (i == 0) out[786432] = (*commit) * (1.f / 4194304.f);
    if (i < NQ) out[786433 + i] = (float)idx[i];
}

// =====================================================================
// host launcher
// =====================================================================
#define CMMA_SMEM 82432

extern "C" void kernel_launch(void* const* d_in, const int* in_sizes, int n_in,
                              void* d_out, int out_size)
{
    const float* x        = (const float*)d_in[0];
    const float* enc_w1   = (const float*)d_in[1];
    const float* enc_b1   = (const float*)d_in[2];
    const float* enc_w2   = (const float*)d_in[3];
    const float* enc_b2   = (const float*)d_in[4];
    const float* enc_w3   = (const float*)d_in[5];
    const float* enc_b3   = (const float*)d_in[6];
    const float* qconv_w  = (const float*)d_in[7];
    const float* qconv_b  = (const float*)d_in[8];
    const float* codebook = (const float*)d_in[9];
    const float* pqconv_w = (const float*)d_in[10];
    const float* pqconv_b = (const float*)d_in[11];
    const float* dec_w1   = (const float*)d_in[12];
    const float* dec_b1   = (const float*)d_in[13];
    const float* dect_w2  = (const float*)d_in[14];
    const float* dect_b2  = (const float*)d_in[15];
    const float* dect_w3  = (const float*)d_in[16];
    const float* dect_b3  = (const float*)d_in[17];
    float* out = (float*)d_out;

    float *h1, *h2, *h3, *z, *d2, *znorm, *cnorm, *commit, *bv8;
    float *w2t, *w3t, *wqt, *wpt;
    __nv_bfloat16 *qh, *ql, *d1h, *d1l;
    __nv_bfloat16 *zh, *zl, *chp, *clp;
    __nv_bfloat16 *wd1h, *wd1l, *wt2h, *wt2l;
    int *idx, *bi8;
    cudaGetSymbolAddress((void**)&h1, g_h1);
    cudaGetSymbolAddress((void**)&h2, g_h2);
    cudaGetSymbolAddress((void**)&h3, g_h3);
    cudaGetSymbolAddress((void**)&z, g_z);
    cudaGetSymbolAddress((void**)&qh, g_qh);
    cudaGetSymbolAddress((void**)&ql, g_ql);
    cudaGetSymbolAddress((void**)&d1h, g_d1h);
    cudaGetSymbolAddress((void**)&d1l, g_d1l);
    cudaGetSymbolAddress((void**)&d2, g_d2);
    cudaGetSymbolAddress((void**)&znorm, g_znorm);
    cudaGetSymbolAddress((void**)&cnorm, g_cnorm);
    cudaGetSymbolAddress((void**)&idx, g_idx);
    cudaGetSymbolAddress((void**)&commit, g_commit);
    cudaGetSymbolAddress((void**)&zh, g_zh);   cudaGetSymbolAddress((void**)&zl, g_zl);
    cudaGetSymbolAddress((void**)&chp, g_ch);  cudaGetSymbolAddress((void**)&clp, g_cl);
    cudaGetSymbolAddress((void**)&bv8, g_bv8);
    cudaGetSymbolAddress((void**)&bi8, g_bi8);
    cudaGetSymbolAddress((void**)&wd1h, g_wd1h); cudaGetSymbolAddress((void**)&wd1l, g_wd1l);
    cudaGetSymbolAddress((void**)&wt2h, g_wt2h); cudaGetSymbolAddress((void**)&wt2l, g_wt2l);
    cudaGetSymbolAddress((void**)&w2t, g_w2t);   cudaGetSymbolAddress((void**)&w3t, g_w3t);
    cudaGetSymbolAddress((void**)&wqt, g_wqt);   cudaGetSymbolAddress((void**)&wpt, g_wpt);

    cudaFuncSetAttribute(conv_mma<0,3,1,1,true ,1>, cudaFuncAttributeMaxDynamicSharedMemorySize, CMMA_SMEM);
    cudaFuncSetAttribute(conv_mma<1,4,2,1,true ,0>, cudaFuncAttributeMaxDynamicSharedMemorySize, CMMA_SMEM);
    cudaFuncSetAttribute(vq_mma4, cudaFuncAttributeMaxDynamicSharedMemorySize, VQ_SMEM);

    // fused prep (weights, codebook planes, cnorm, commit zero)
    megaprep<<<MEGAPREP_BLOCKS, 256>>>(enc_w2, enc_w3, qconv_w, pqconv_w, dec_w1, dect_w2,
                                       codebook, w2t, w3t, wqt, wpt, wd1h, wd1l,
                                       wt2h, wt2l, chp, clp, cnorm, commit);

    // encoder — enc1 dedicated; enc2/enc3/qconv on 4-stage async FFMA2
    conv_enc1<<<dim3(128,4),256>>>(x, enc_w1, enc_b1, h1);
    conv_async<4,2,1,true ,0,0><<<dim3(64,1,4),256>>>(h1, w2t, enc_b2, h2, nullptr, nullptr,
                                                      128,128, 128,128,  64, 64, 6, nullptr);
    conv_async<3,1,1,false,0,0><<<dim3(64,1,4),256>>>(h2, w3t, enc_b3, h3, nullptr, nullptr,
                                                      128,128,  64, 64,  64, 64, 6, nullptr);
    conv_async<1,1,0,false,0,1><<<dim3(64,2,4),256>>>(h3, wqt, qconv_b, z, nullptr, nullptr,
                                                      128,256,  64, 64,  64, 64, 6, nullptr);

    // quantize — fused z split+norm, R15-exact VQ pipeline
    zsplit_norm<<<2048, 256>>>(z, zh, zl, znorm);
    vq_mma4<<<dim3(128, 8), 256, VQ_SMEM>>>(zh, zl, chp, clp, znorm, cnorm, bv8, bi8);
    vq_combine8<<<64, 256>>>(bv8, bi8, idx);
    commit_only<<<NQ, 256>>>(codebook, z, idx, commit);

    // decoder — pqconv gathers codebook rows via idx (values == quant)
    conv_async<1,1,0,false,2,2><<<dim3(64,1,4),256>>>(codebook, wpt, pqconv_b, nullptr, qh, ql,
                                                      256, 128, 64,64, 64,64, 6, idx);
    conv_mma<0,3,1,1,true ,1><<<dim3(32,1,4),256,CMMA_SMEM>>>(qh, ql, wd1h, wd1l, dec_b1,
                                                     nullptr, d1h, d1l, 128, 64, 64, 1152);
    conv_mma<1,4,2,1,true ,0><<<dim3(32,4,4),256,CMMA_SMEM>>>(d1h, d1l, wt2h, wt2l, dect_b2,
                                                     d2, nullptr, nullptr, 128, 64, 64, 512);
    convt_out3<<<dim3(256,4),256>>>(d2, dect_w3, dect_b3, out);

    pack_kernel<<<64, 256>>>(out, commit, idx);

    (void)in_sizes; (void)n_in; (void)out_size;
}